// round 1
// baseline (speedup 1.0000x reference)
#include <cuda_runtime.h>
#include <math.h>

// Problem constants
#define N_NODES 60000
#define N_EDGES 600000
#define N_GRAPH 512
#define DIM 128
#define N_LAYERS 3
#define GRID_G 8192   // distance-table resolution over [0, 10]

// ---------------- device scratch (static globals; no allocation) ----------------
__device__ float g_H[(long long)N_NODES * 512];      // hs levels 0..3 concatenated per row
__device__ float g_Hn[(long long)N_NODES * DIM];     // h_new (+1 baked into bias)
__device__ float g_Node[(long long)N_NODES * DIM];   // scatter accumulator
__device__ float g_T1[(long long)N_NODES * DIM];     // softplus intermediate / readout t
__device__ float g_Wf[N_LAYERS * DIM * DIM];         // folded W_c2 @ W_c3
__device__ float g_bf[N_LAYERS * DIM];               // folded bias
__device__ float g_Tab[(long long)N_LAYERS * GRID_G * DIM]; // e(d) lookup tables

// ---------------- helpers ----------------
__device__ __forceinline__ float sp_half(float x) {   // softplus(beta=0.5, thr=14)
    float bx = 0.5f * x;
    return bx > 14.0f ? x : 2.0f * log1pf(expf(bx));
}
__device__ __forceinline__ float sp_one(float x) {    // softplus(beta=1, thr=20)
    return x > 20.0f ? x : log1pf(expf(x));
}

__device__ __forceinline__ unsigned long long ffma2(unsigned long long a,
                                                    unsigned long long b,
                                                    unsigned long long c) {
    unsigned long long d;
    asm("fma.rn.f32x2 %0, %1, %2, %3;" : "=l"(d) : "l"(a), "l"(b), "l"(c));
    return d;
}
__device__ __forceinline__ unsigned long long pack2(float x, float y) {
    unsigned long long r;
    asm("mov.b64 %0, {%1, %2};" : "=l"(r) : "f"(x), "f"(y));
    return r;
}
__device__ __forceinline__ float2 unpack2(unsigned long long v) {
    float2 r;
    asm("mov.b64 {%0, %1}, %2;" : "=f"(r.x), "=f"(r.y) : "l"(v));
    return r;
}

// ---------------- precompute: fold W_c2 @ W_c3 ----------------
__global__ void fold_kernel(const float* __restrict__ Wc2, const float* __restrict__ bc2,
                            const float* __restrict__ Wc3, const float* __restrict__ bc3) {
    int k = blockIdx.x;      // 0..127 (row of Wc2)
    int l = blockIdx.y;      // layer
    int j = threadIdx.x;     // 0..127 (output col)
    __shared__ float row[DIM];
    row[j] = Wc2[((long long)l * DIM + k) * DIM + j];
    __syncthreads();
    float acc = 0.0f;
    #pragma unroll 4
    for (int m = 0; m < DIM; m++)
        acc += row[m] * Wc3[((long long)l * DIM + m) * DIM + j];
    g_Wf[((long long)l * DIM + k) * DIM + j] = acc;
    if (k == 0) {
        float bacc = bc3[l * DIM + j];
        #pragma unroll 4
        for (int m = 0; m < DIM; m++)
            bacc += bc2[l * DIM + m] * Wc3[((long long)l * DIM + m) * DIM + j];
        g_bf[l * DIM + j] = bacc;
    }
}

// ---------------- precompute: e(d) tables ----------------
__global__ void table_kernel(const float* __restrict__ Wc1, const float* __restrict__ bc1) {
    int g = blockIdx.x;      // grid point
    int l = blockIdx.y;      // layer
    int j = threadIdx.x;     // 0..127
    __shared__ float rbf[32];
    __shared__ float spu[DIM];
    float dg = (float)g * (10.0f / (float)(GRID_G - 1));
    if (j < 30) {
        float c = (float)j * (10.0f / 29.0f);
        float dd = dg - c;
        rbf[j] = expf(-dd * dd * 2.9f);   // gap = 10/29, 1/gap = 2.9
    }
    __syncthreads();
    float u = bc1[l * DIM + j];
    #pragma unroll
    for (int r = 0; r < 30; r++)
        u += rbf[r] * Wc1[(l * 30 + r) * DIM + j];
    spu[j] = sp_half(u);
    __syncthreads();
    float acc = g_bf[l * DIM + j];
    #pragma unroll 4
    for (int m = 0; m < DIM; m++)
        acc += spu[m] * g_Wf[((long long)l * DIM + m) * DIM + j];
    g_Tab[((long long)l * GRID_G + g) * DIM + j] = acc;
}

// ---------------- embedding gather ----------------
__global__ void embed_kernel(const int* __restrict__ at, const float* __restrict__ emb) {
    int i = blockIdx.x * blockDim.x + threadIdx.x;   // over N*32 float4
    if (i >= N_NODES * 32) return;
    int n = i >> 5, q = i & 31;
    float4 v = __ldg((const float4*)(emb + (long long)at[n] * DIM) + q);
    *(float4*)(g_H + (long long)n * 512 + q * 4) = v;
}

__global__ void zero_node_kernel() {
    int i = blockIdx.x * blockDim.x + threadIdx.x;
    if (i < N_NODES * 32) ((float4*)g_Node)[i] = make_float4(0.f, 0.f, 0.f, 0.f);
}

__global__ void zero_out_kernel(float* out) { out[threadIdx.x] = 0.0f; }

// ---------------- GEMM: Y = act(X @ W + b [+extra]) [+ Res] ----------------
// BM=128 rows/block, 256 threads, thread tile 8 rows x (NO/16) cols via FFMA2.
template<int K, int NO, int ACT, bool RES>
__global__ __launch_bounds__(256) void gemm_kernel(
    const float* __restrict__ X, int sx,
    const float* __restrict__ W,            // [K][NO] row-major
    const float* __restrict__ bias, float bias_extra,
    const float* __restrict__ Res, int sr,
    float* __restrict__ Y, int sy, int M)
{
    constexpr int BM = 128, BK = 32;
    constexpr int NP = NO / 32;             // float2 col-pairs per thread
    __shared__ float Xs[BK][BM];            // transposed X tile
    __shared__ float Ws[BK][NO];

    const int tid = threadIdx.x;
    const int tx = tid & 15, ty = tid >> 4;
    const int r0 = blockIdx.x * BM;
    const int row_t = ty * 8;
    const int colp = tx * 2;                // thread cols: colp + 32*j (conflict-free)

    unsigned long long acc[8][NP];
    #pragma unroll
    for (int i = 0; i < 8; i++)
        #pragma unroll
        for (int j = 0; j < NP; j++) acc[i][j] = 0ULL;  // bits of (0.f, 0.f)

    for (int k0 = 0; k0 < K; k0 += BK) {
        #pragma unroll
        for (int t = 0; t < 4; t++) {               // X tile: 128x32 floats
            int idx = tid + t * 256;
            int row = idx >> 3;
            int kq = idx & 7;
            float4 v = make_float4(0.f, 0.f, 0.f, 0.f);
            int grow = r0 + row;
            if (grow < M) v = *(const float4*)(X + (long long)grow * sx + k0 + kq * 4);
            Xs[kq * 4 + 0][row] = v.x;
            Xs[kq * 4 + 1][row] = v.y;
            Xs[kq * 4 + 2][row] = v.z;
            Xs[kq * 4 + 3][row] = v.w;
        }
        #pragma unroll
        for (int t = 0; t < (BK * NO) / 1024; t++) {  // W tile: 32xNO
            int idx = tid + t * 256;
            int kk = idx / (NO / 4);
            int cq = idx % (NO / 4);
            *(float4*)&Ws[kk][cq * 4] =
                *(const float4*)(W + (long long)(k0 + kk) * NO + cq * 4);
        }
        __syncthreads();
        #pragma unroll
        for (int k = 0; k < BK; k++) {
            float4 xa = *(const float4*)&Xs[k][row_t];
            float4 xb = *(const float4*)&Xs[k][row_t + 4];
            unsigned long long xp[8];
            xp[0] = pack2(xa.x, xa.x); xp[1] = pack2(xa.y, xa.y);
            xp[2] = pack2(xa.z, xa.z); xp[3] = pack2(xa.w, xa.w);
            xp[4] = pack2(xb.x, xb.x); xp[5] = pack2(xb.y, xb.y);
            xp[6] = pack2(xb.z, xb.z); xp[7] = pack2(xb.w, xb.w);
            unsigned long long wp[NP];
            #pragma unroll
            for (int j = 0; j < NP; j++)
                wp[j] = *(const unsigned long long*)&Ws[k][colp + 32 * j];
            #pragma unroll
            for (int i = 0; i < 8; i++)
                #pragma unroll
                for (int j = 0; j < NP; j++)
                    acc[i][j] = ffma2(xp[i], wp[j], acc[i][j]);
        }
        __syncthreads();
    }
    #pragma unroll
    for (int i = 0; i < 8; i++) {
        int grow = r0 + row_t + i;
        if (grow < M) {
            #pragma unroll
            for (int j = 0; j < NP; j++) {
                int c = colp + 32 * j;
                float2 v = unpack2(acc[i][j]);
                v.x += bias[c] + bias_extra;
                v.y += bias[c + 1] + bias_extra;
                if (ACT == 1) { v.x = sp_half(v.x); v.y = sp_half(v.y); }
                else if (ACT == 2) { v.x = sp_one(v.x); v.y = sp_one(v.y); }
                if (RES) {
                    v.x += Res[(long long)grow * sr + c];
                    v.y += Res[(long long)grow * sr + c + 1];
                }
                *(float2*)(Y + (long long)grow * sy + c) = v;
            }
        }
    }
}

// ---------------- edge pass: msg=(h_new[src])*(lerp table), scatter-add ----------------
__global__ __launch_bounds__(256) void edge_kernel(
    const int* __restrict__ src, const int* __restrict__ dst,
    const float* __restrict__ dist,
    const float* __restrict__ tab,   // this layer's [GRID_G][128]
    const float* __restrict__ hn,    // [N][128], +1 baked in
    float* __restrict__ node)
{
    int gt = blockIdx.x * blockDim.x + threadIdx.x;
    int e = gt >> 5;
    int lane = gt & 31;
    if (e >= N_EDGES) return;
    int s = __ldg(src + e);
    int d = __ldg(dst + e);
    float di = __ldg(dist + e);
    float t = di * ((float)(GRID_G - 1) / 10.0f);
    int g = (int)t;
    g = g < GRID_G - 2 ? g : GRID_G - 2;
    float f = t - (float)g;
    const float4* p0 = (const float4*)(tab + (long long)g * DIM) + lane;
    float4 a = __ldg(p0);
    float4 b = __ldg(p0 + 32);     // next grid row = +128 floats = +32 float4
    float4 h = __ldg((const float4*)(hn + (long long)s * DIM) + lane);
    float4 m;
    m.x = fmaf(f, b.x - a.x, a.x) * h.x;
    m.y = fmaf(f, b.y - a.y, a.y) * h.y;
    m.z = fmaf(f, b.z - a.z, a.z) * h.z;
    m.w = fmaf(f, b.w - a.w, a.w) * h.w;
    float* p = node + (long long)d * DIM + lane * 4;
    asm volatile("red.global.add.v4.f32 [%0], {%1,%2,%3,%4};"
                 :: "l"(p), "f"(m.x), "f"(m.y), "f"(m.z), "f"(m.w) : "memory");
}

// ---------------- readout 2nd linear + graph scatter ----------------
__global__ void readout2_kernel(const float* __restrict__ W_r2, const float* __restrict__ b_r2,
                                const int* __restrict__ gid, float* __restrict__ out) {
    int n = blockIdx.x * blockDim.x + threadIdx.x;
    if (n >= N_NODES) return;
    float acc = b_r2[0];
    const float4* t = (const float4*)(g_T1 + (long long)n * 64);
    #pragma unroll
    for (int q = 0; q < 16; q++) {
        float4 v = t[q];
        acc += v.x * __ldg(W_r2 + q * 4 + 0) + v.y * __ldg(W_r2 + q * 4 + 1)
             + v.z * __ldg(W_r2 + q * 4 + 2) + v.w * __ldg(W_r2 + q * 4 + 3);
    }
    atomicAdd(&out[gid[n]], acc);
}

// ---------------- launch ----------------
extern "C" void kernel_launch(void* const* d_in, const int* in_sizes, int n_in,
                              void* d_out, int out_size) {
    const int*   atom_type = (const int*)d_in[0];
    const int*   src  = (const int*)d_in[1];
    const int*   dst  = (const int*)d_in[2];
    const int*   gid  = (const int*)d_in[3];
    const float* dist = (const float*)d_in[4];
    const float* emb  = (const float*)d_in[5];
    const float* W_n1 = (const float*)d_in[6];  const float* b_n1 = (const float*)d_in[7];
    const float* W_c1 = (const float*)d_in[8];  const float* b_c1 = (const float*)d_in[9];
    const float* W_c2 = (const float*)d_in[10]; const float* b_c2 = (const float*)d_in[11];
    const float* W_c3 = (const float*)d_in[12]; const float* b_c3 = (const float*)d_in[13];
    const float* W_n2 = (const float*)d_in[14]; const float* b_n2 = (const float*)d_in[15];
    const float* W_n3 = (const float*)d_in[16]; const float* b_n3 = (const float*)d_in[17];
    const float* W_r1 = (const float*)d_in[18]; const float* b_r1 = (const float*)d_in[19];
    const float* W_r2 = (const float*)d_in[20]; const float* b_r2 = (const float*)d_in[21];
    float* out = (float*)d_out;

    float *H, *Hn, *Node, *T1, *Tab;
    cudaGetSymbolAddress((void**)&H,    g_H);
    cudaGetSymbolAddress((void**)&Hn,   g_Hn);
    cudaGetSymbolAddress((void**)&Node, g_Node);
    cudaGetSymbolAddress((void**)&T1,   g_T1);
    cudaGetSymbolAddress((void**)&Tab,  g_Tab);

    const int M = N_NODES;
    const int GB = (M + 127) / 128;           // 469 GEMM blocks

    fold_kernel<<<dim3(DIM, N_LAYERS), DIM>>>(W_c2, b_c2, W_c3, b_c3);
    table_kernel<<<dim3(GRID_G, N_LAYERS), DIM>>>(W_c1, b_c1);
    embed_kernel<<<(N_NODES * 32 + 255) / 256, 256>>>(atom_type, emb);

    for (int l = 0; l < N_LAYERS; l++) {
        // h_new = H_l @ W_n1 + (b_n1 + 1)
        gemm_kernel<128, 128, 0, false><<<GB, 256>>>(
            H + l * 128, 512, W_n1 + (long long)l * 128 * 128, b_n1 + l * 128, 1.0f,
            nullptr, 0, Hn, 128, M);
        zero_node_kernel<<<(N_NODES * 32 + 255) / 256, 256>>>();
        edge_kernel<<<(N_EDGES * 32) / 256, 256>>>(
            src, dst, dist, Tab + (long long)l * GRID_G * DIM, Hn, Node);
        // t = sp0.5(Node @ W_n2 + b_n2)
        gemm_kernel<128, 128, 1, false><<<GB, 256>>>(
            Node, 128, W_n2 + (long long)l * 128 * 128, b_n2 + l * 128, 0.0f,
            nullptr, 0, T1, 128, M);
        // H_{l+1} = H_l + (t @ W_n3 + b_n3)
        gemm_kernel<128, 128, 0, true><<<GB, 256>>>(
            T1, 128, W_n3 + (long long)l * 128 * 128, b_n3 + l * 128, 0.0f,
            H + l * 128, 512, H + (l + 1) * 128, 512, M);
    }

    // readout: t = sp1(hcat @ W_r1 + b_r1), K=512 -> 64
    gemm_kernel<512, 64, 2, false><<<GB, 256>>>(
        H, 512, W_r1, b_r1, 0.0f, nullptr, 0, T1, 64, M);
    zero_out_kernel<<<1, N_GRAPH>>>(out);
    readout2_kernel<<<(N_NODES + 255) / 256, 256>>>(W_r2, b_r2, gid, out);
}

// round 3
// speedup vs baseline: 1.3192x; 1.3192x over previous
#include <cuda_runtime.h>
#include <cuda_bf16.h>
#include <math.h>
#include <stdint.h>

// Problem constants
#define N_NODES 60000
#define N_EDGES 600000
#define N_GRAPH 512
#define DIM 128
#define N_LAYERS 3
#define GRID_G 8192

// ---------------- device scratch ----------------
__device__ float g_H[(long long)N_NODES * 512];
__device__ float g_Hn[(long long)N_NODES * DIM];
__device__ float g_Node[(long long)N_NODES * DIM];
__device__ float g_T1[(long long)N_NODES * DIM];
__device__ float g_Wf[N_LAYERS * DIM * DIM];
__device__ float g_bf[N_LAYERS * DIM];
__device__ float g_Tab[(long long)N_LAYERS * GRID_G * DIM];
// bf16 hi/lo weights as B-operand layout [N][K] packed, 9 matrices (n1,n2,n3 x 3 layers)
__device__ __align__(256) __nv_bfloat16 g_WbHi[9 * DIM * DIM];
__device__ __align__(256) __nv_bfloat16 g_WbLo[9 * DIM * DIM];

// ---------------- scalar helpers ----------------
__device__ __forceinline__ float sp_half(float x) {
    float bx = 0.5f * x;
    return bx > 14.0f ? x : 2.0f * log1pf(expf(bx));
}
__device__ __forceinline__ float sp_one(float x) {
    return x > 20.0f ? x : log1pf(expf(x));
}
__device__ __forceinline__ unsigned long long ffma2(unsigned long long a,
                                                    unsigned long long b,
                                                    unsigned long long c) {
    unsigned long long d;
    asm("fma.rn.f32x2 %0, %1, %2, %3;" : "=l"(d) : "l"(a), "l"(b), "l"(c));
    return d;
}
__device__ __forceinline__ unsigned long long pack2(float x, float y) {
    unsigned long long r;
    asm("mov.b64 %0, {%1, %2};" : "=l"(r) : "f"(x), "f"(y));
    return r;
}
__device__ __forceinline__ float2 unpack2(unsigned long long v) {
    float2 r;
    asm("mov.b64 {%0, %1}, %2;" : "=f"(r.x), "=f"(r.y) : "l"(v));
    return r;
}

// ---------------- HMMA mma.sync bf16 helpers ----------------
__device__ __forceinline__ void mma16816(float* d, const uint32_t* a,
                                         uint32_t b0, uint32_t b1) {
    asm volatile(
        "mma.sync.aligned.m16n8k16.row.col.f32.bf16.bf16.f32 "
        "{%0,%1,%2,%3}, {%4,%5,%6,%7}, {%8,%9}, {%0,%1,%2,%3};"
        : "+f"(d[0]), "+f"(d[1]), "+f"(d[2]), "+f"(d[3])
        : "r"(a[0]), "r"(a[1]), "r"(a[2]), "r"(a[3]), "r"(b0), "r"(b1));
}

// smem layout (uint32 words): padded row stride 68 words (136 bf16) -> conflict-free frags
#define ASTR 68
#define A_WORDS (64 * ASTR)            // 4352
#define B_WORDS (128 * ASTR)           // 8704
#define OFF_AHI 0
#define OFF_ALO A_WORDS
#define OFF_BHI (2 * A_WORDS)
#define OFF_BLO (2 * A_WORDS + B_WORDS)
#define TSMEM_M ((2 * A_WORDS + 2 * B_WORDS) * 4)   // 104448 bytes

// split fp32 pair -> (hi bf16x2, lo bf16x2)
__device__ __forceinline__ void split2(float x, float y, uint32_t& h, uint32_t& l) {
    __nv_bfloat162 hb = __floats2bfloat162_rn(x, y);
    float2 hf = __bfloat1622float2(hb);
    __nv_bfloat162 lb = __floats2bfloat162_rn(x - hf.x, y - hf.y);
    h = *(uint32_t*)&hb;
    l = *(uint32_t*)&lb;
}

// core: acc[8][4] += (A @ B) over K=128, 3-product precision split.
// warp covers rows mw*16..+15, cols nw*64..+63 of the 64x128 tile.
__device__ __forceinline__ void mma_core(const uint32_t* __restrict__ sm,
                                         int mw, int nw, int g, int tg,
                                         float acc[8][4]) {
    const uint32_t* Ahi = sm + OFF_AHI;
    const uint32_t* Alo = sm + OFF_ALO;
    const uint32_t* Bhi = sm + OFF_BHI;
    const uint32_t* Blo = sm + OFF_BLO;
    int ra0 = (mw * 16 + g) * ASTR;
    int ra1 = ra0 + 8 * ASTR;
    #pragma unroll
    for (int ks = 0; ks < 8; ks++) {
        int c = ks * 8 + tg;
        uint32_t ah[4], al[4];
        ah[0] = Ahi[ra0 + c];     ah[1] = Ahi[ra1 + c];
        ah[2] = Ahi[ra0 + c + 4]; ah[3] = Ahi[ra1 + c + 4];
        al[0] = Alo[ra0 + c];     al[1] = Alo[ra1 + c];
        al[2] = Alo[ra0 + c + 4]; al[3] = Alo[ra1 + c + 4];
        #pragma unroll
        for (int t = 0; t < 8; t++) {
            int rb = (nw * 64 + t * 8 + g) * ASTR;
            uint32_t bh0 = Bhi[rb + c], bh1 = Bhi[rb + c + 4];
            uint32_t bl0 = Blo[rb + c], bl1 = Blo[rb + c + 4];
            mma16816(acc[t], ah, bh0, bh1);
            mma16816(acc[t], ah, bl0, bl1);
            mma16816(acc[t], al, bh0, bh1);
        }
    }
}

// load X tile (64 rows x 128 f32) -> A smem hi/lo
__device__ __forceinline__ void load_A(uint32_t* sm, const float* __restrict__ X,
                                       int sx, int r0, int M, int tid) {
    uint32_t* Ahi = sm + OFF_AHI;
    uint32_t* Alo = sm + OFF_ALO;
    #pragma unroll
    for (int j = 0; j < 8; j++) {
        int f = tid + j * 256;
        int row = f >> 5, q = f & 31;
        float4 v = make_float4(0.f, 0.f, 0.f, 0.f);
        int gr = r0 + row;
        if (gr < M) v = *(const float4*)(X + (long long)gr * sx + q * 4);
        uint32_t h0, l0, h1, l1;
        split2(v.x, v.y, h0, l0);
        split2(v.z, v.w, h1, l1);
        int w = row * ASTR + q * 2;
        *(uint2*)(Ahi + w) = make_uint2(h0, h1);
        *(uint2*)(Alo + w) = make_uint2(l0, l1);
    }
}

// copy packed W [128][64 words] -> B smem (padded)
__device__ __forceinline__ void load_B(uint32_t* sm, const __nv_bfloat16* __restrict__ Whi,
                                       const __nv_bfloat16* __restrict__ Wlo, int tid) {
    uint32_t* Bhi = sm + OFF_BHI;
    uint32_t* Blo = sm + OFF_BLO;
    const uint4* s1 = (const uint4*)Whi;
    const uint4* s2 = (const uint4*)Wlo;
    #pragma unroll
    for (int j = 0; j < 8; j++) {
        int i = tid + j * 256;
        int row = i >> 4, cq = (i & 15) * 4;
        *(uint4*)(Bhi + row * ASTR + cq) = s1[i];
        *(uint4*)(Blo + row * ASTR + cq) = s2[i];
    }
}

// ---------------- weight prep: fp32 [K][N] -> bf16 hi/lo packed [N][K] ----------------
__global__ void prep_w(const float* __restrict__ Wn1, const float* __restrict__ Wn2,
                       const float* __restrict__ Wn3,
                       __nv_bfloat16* __restrict__ Hi, __nv_bfloat16* __restrict__ Lo) {
    int m = blockIdx.x;  // 0..8
    const float* src = (m < 3 ? Wn1 : (m < 6 ? Wn2 : Wn3)) + (long long)(m % 3) * DIM * DIM;
    __nv_bfloat16* dh = Hi + (long long)m * DIM * DIM;
    __nv_bfloat16* dl = Lo + (long long)m * DIM * DIM;
    int idx0 = blockIdx.y * 1024;
    for (int i = 0; i < 8; i++) {
        int idx = idx0 + i * 128 + threadIdx.x;
        int k = idx >> 7, n = idx & 127;
        float v = src[idx];  // W[k][n]
        __nv_bfloat16 h = __float2bfloat16(v);
        __nv_bfloat16 l = __float2bfloat16(v - __bfloat162float(h));
        dh[n * DIM + k] = h;   // B as [N][K]
        dl[n * DIM + k] = l;
    }
}

// ---------------- HMMA GEMM: Y = X @ W + bias + bextra ----------------
__global__ __launch_bounds__(256) void gemm_m1(
    const float* __restrict__ X, int sx,
    const __nv_bfloat16* __restrict__ Whi, const __nv_bfloat16* __restrict__ Wlo,
    const float* __restrict__ bias, float bextra,
    float* __restrict__ Y, int sy, int M)
{
    extern __shared__ uint32_t sm[];
    int tid = threadIdx.x, wid = tid >> 5, lane = tid & 31;
    int mw = wid & 3, nw = wid >> 2;
    int g = lane >> 2, tg = lane & 3;
    int r0 = blockIdx.x * 64;

    load_A(sm, X, sx, r0, M, tid);
    load_B(sm, Whi, Wlo, tid);
    __syncthreads();

    float acc[8][4];
    #pragma unroll
    for (int t = 0; t < 8; t++)
        #pragma unroll
        for (int i = 0; i < 4; i++) acc[t][i] = 0.0f;
    mma_core(sm, mw, nw, g, tg, acc);

    int row0 = r0 + mw * 16 + g, row1 = row0 + 8;
    #pragma unroll
    for (int t = 0; t < 8; t++) {
        int col = nw * 64 + t * 8 + tg * 2;
        float b0 = __ldg(bias + col) + bextra;
        float b1 = __ldg(bias + col + 1) + bextra;
        if (row0 < M)
            *(float2*)(Y + (long long)row0 * sy + col) =
                make_float2(acc[t][0] + b0, acc[t][1] + b1);
        if (row1 < M)
            *(float2*)(Y + (long long)row1 * sy + col) =
                make_float2(acc[t][2] + b0, acc[t][3] + b1);
    }
}

// ---------------- fused HMMA pair: Y = sp_half(X@W2+b2)@W3 + b3 + Res ----------------
__global__ __launch_bounds__(256) void gemm_m23(
    const float* __restrict__ X, int sx,
    const __nv_bfloat16* __restrict__ W2hi, const __nv_bfloat16* __restrict__ W2lo,
    const float* __restrict__ b2,
    const __nv_bfloat16* __restrict__ W3hi, const __nv_bfloat16* __restrict__ W3lo,
    const float* __restrict__ b3,
    const float* __restrict__ Res, int sr,
    float* __restrict__ Y, int sy, int M)
{
    extern __shared__ uint32_t sm[];
    int tid = threadIdx.x, wid = tid >> 5, lane = tid & 31;
    int mw = wid & 3, nw = wid >> 2;
    int g = lane >> 2, tg = lane & 3;
    int r0 = blockIdx.x * 64;

    load_A(sm, X, sx, r0, M, tid);
    load_B(sm, W2hi, W2lo, tid);
    __syncthreads();

    float acc[8][4];
    #pragma unroll
    for (int t = 0; t < 8; t++)
        #pragma unroll
        for (int i = 0; i < 4; i++) acc[t][i] = 0.0f;
    mma_core(sm, mw, nw, g, tg, acc);
    __syncthreads();   // everyone done reading A/B

    // t = sp_half(acc + b2) -> A smem (hi/lo); W3 -> B smem
    {
        uint32_t* Ahi = sm + OFF_AHI;
        uint32_t* Alo = sm + OFF_ALO;
        int rl0 = mw * 16 + g, rl1 = rl0 + 8;
        #pragma unroll
        for (int t = 0; t < 8; t++) {
            int col = nw * 64 + t * 8 + tg * 2;
            float b0 = __ldg(b2 + col), b1 = __ldg(b2 + col + 1);
            float t0 = sp_half(acc[t][0] + b0), t1 = sp_half(acc[t][1] + b1);
            float t2 = sp_half(acc[t][2] + b0), t3 = sp_half(acc[t][3] + b1);
            uint32_t h, l;
            int w0 = rl0 * ASTR + (col >> 1);
            int w1 = rl1 * ASTR + (col >> 1);
            split2(t0, t1, h, l); Ahi[w0] = h; Alo[w0] = l;
            split2(t2, t3, h, l); Ahi[w1] = h; Alo[w1] = l;
        }
    }
    load_B(sm, W3hi, W3lo, tid);
    __syncthreads();

    #pragma unroll
    for (int t = 0; t < 8; t++)
        #pragma unroll
        for (int i = 0; i < 4; i++) acc[t][i] = 0.0f;
    mma_core(sm, mw, nw, g, tg, acc);

    int row0 = r0 + mw * 16 + g, row1 = row0 + 8;
    #pragma unroll
    for (int t = 0; t < 8; t++) {
        int col = nw * 64 + t * 8 + tg * 2;
        float b0 = __ldg(b3 + col), b1 = __ldg(b3 + col + 1);
        if (row0 < M) {
            float2 r = *(const float2*)(Res + (long long)row0 * sr + col);
            *(float2*)(Y + (long long)row0 * sy + col) =
                make_float2(acc[t][0] + b0 + r.x, acc[t][1] + b1 + r.y);
        }
        if (row1 < M) {
            float2 r = *(const float2*)(Res + (long long)row1 * sr + col);
            *(float2*)(Y + (long long)row1 * sy + col) =
                make_float2(acc[t][2] + b0 + r.x, acc[t][3] + b1 + r.y);
        }
    }
}

// ---------------- fold W_c2 @ W_c3 ----------------
__global__ void fold_kernel(const float* __restrict__ Wc2, const float* __restrict__ bc2,
                            const float* __restrict__ Wc3, const float* __restrict__ bc3) {
    int k = blockIdx.x, l = blockIdx.y, j = threadIdx.x;
    __shared__ float row[DIM];
    row[j] = Wc2[((long long)l * DIM + k) * DIM + j];
    __syncthreads();
    float acc = 0.0f;
    #pragma unroll 4
    for (int m = 0; m < DIM; m++)
        acc += row[m] * Wc3[((long long)l * DIM + m) * DIM + j];
    g_Wf[((long long)l * DIM + k) * DIM + j] = acc;
    if (k == 0) {
        float bacc = bc3[l * DIM + j];
        #pragma unroll 4
        for (int m = 0; m < DIM; m++)
            bacc += bc2[l * DIM + m] * Wc3[((long long)l * DIM + m) * DIM + j];
        g_bf[l * DIM + j] = bacc;
    }
}

// ---------------- e(d) tables ----------------
__global__ void table_kernel(const float* __restrict__ Wc1, const float* __restrict__ bc1) {
    int g = blockIdx.x, l = blockIdx.y, j = threadIdx.x;
    __shared__ float rbf[32];
    __shared__ float spu[DIM];
    float dg = (float)g * (10.0f / (float)(GRID_G - 1));
    if (j < 30) {
        float c = (float)j * (10.0f / 29.0f);
        float dd = dg - c;
        rbf[j] = expf(-dd * dd * 2.9f);
    }
    __syncthreads();
    float u = bc1[l * DIM + j];
    #pragma unroll
    for (int r = 0; r < 30; r++)
        u += rbf[r] * Wc1[(l * 30 + r) * DIM + j];
    spu[j] = sp_half(u);
    __syncthreads();
    float acc = g_bf[l * DIM + j];
    #pragma unroll 4
    for (int m = 0; m < DIM; m++)
        acc += spu[m] * g_Wf[((long long)l * DIM + m) * DIM + j];
    g_Tab[((long long)l * GRID_G + g) * DIM + j] = acc;
}

// ---------------- embedding / zero ----------------
__global__ void embed_kernel(const int* __restrict__ at, const float* __restrict__ emb) {
    int i = blockIdx.x * blockDim.x + threadIdx.x;
    if (i >= N_NODES * 32) return;
    int n = i >> 5, q = i & 31;
    float4 v = __ldg((const float4*)(emb + (long long)at[n] * DIM) + q);
    *(float4*)(g_H + (long long)n * 512 + q * 4) = v;
}
__global__ void zero_node_kernel() {
    int i = blockIdx.x * blockDim.x + threadIdx.x;
    if (i < N_NODES * 32) ((float4*)g_Node)[i] = make_float4(0.f, 0.f, 0.f, 0.f);
}
__global__ void zero_out_kernel(float* out) { out[threadIdx.x] = 0.0f; }

// ---------------- SIMT GEMM (readout only) ----------------
template<int K, int NO, int ACT, bool RES>
__global__ __launch_bounds__(256) void gemm_kernel(
    const float* __restrict__ X, int sx,
    const float* __restrict__ W,
    const float* __restrict__ bias, float bias_extra,
    const float* __restrict__ Res, int sr,
    float* __restrict__ Y, int sy, int M)
{
    constexpr int BM = 128, BK = 32;
    constexpr int NP = NO / 32;
    __shared__ float Xs[BK][BM];
    __shared__ float Ws[BK][NO];

    const int tid = threadIdx.x;
    const int tx = tid & 15, ty = tid >> 4;
    const int r0 = blockIdx.x * BM;
    const int row_t = ty * 8;
    const int colp = tx * 2;

    unsigned long long acc[8][NP];
    #pragma unroll
    for (int i = 0; i < 8; i++)
        #pragma unroll
        for (int j = 0; j < NP; j++) acc[i][j] = 0ULL;

    for (int k0 = 0; k0 < K; k0 += BK) {
        #pragma unroll
        for (int t = 0; t < 4; t++) {
            int idx = tid + t * 256;
            int row = idx >> 3;
            int kq = idx & 7;
            float4 v = make_float4(0.f, 0.f, 0.f, 0.f);
            int grow = r0 + row;
            if (grow < M) v = *(const float4*)(X + (long long)grow * sx + k0 + kq * 4);
            Xs[kq * 4 + 0][row] = v.x;
            Xs[kq * 4 + 1][row] = v.y;
            Xs[kq * 4 + 2][row] = v.z;
            Xs[kq * 4 + 3][row] = v.w;
        }
        #pragma unroll
        for (int t = 0; t < (BK * NO) / 1024; t++) {
            int idx = tid + t * 256;
            int kk = idx / (NO / 4);
            int cq = idx % (NO / 4);
            *(float4*)&Ws[kk][cq * 4] =
                *(const float4*)(W + (long long)(k0 + kk) * NO + cq * 4);
        }
        __syncthreads();
        #pragma unroll
        for (int k = 0; k < BK; k++) {
            float4 xa = *(const float4*)&Xs[k][row_t];
            float4 xb = *(const float4*)&Xs[k][row_t + 4];
            unsigned long long xp[8];
            xp[0] = pack2(xa.x, xa.x); xp[1] = pack2(xa.y, xa.y);
            xp[2] = pack2(xa.z, xa.z); xp[3] = pack2(xa.w, xa.w);
            xp[4] = pack2(xb.x, xb.x); xp[5] = pack2(xb.y, xb.y);
            xp[6] = pack2(xb.z, xb.z); xp[7] = pack2(xb.w, xb.w);
            unsigned long long wp[NP];
            #pragma unroll
            for (int j = 0; j < NP; j++)
                wp[j] = *(const unsigned long long*)&Ws[k][colp + 32 * j];
            #pragma unroll
            for (int i = 0; i < 8; i++)
                #pragma unroll
                for (int j = 0; j < NP; j++)
                    acc[i][j] = ffma2(xp[i], wp[j], acc[i][j]);
        }
        __syncthreads();
    }
    #pragma unroll
    for (int i = 0; i < 8; i++) {
        int grow = r0 + row_t + i;
        if (grow < M) {
            #pragma unroll
            for (int j = 0; j < NP; j++) {
                int c = colp + 32 * j;
                float2 v = unpack2(acc[i][j]);
                v.x += bias[c] + bias_extra;
                v.y += bias[c + 1] + bias_extra;
                if (ACT == 1) { v.x = sp_half(v.x); v.y = sp_half(v.y); }
                else if (ACT == 2) { v.x = sp_one(v.x); v.y = sp_one(v.y); }
                if (RES) {
                    v.x += Res[(long long)grow * sr + c];
                    v.y += Res[(long long)grow * sr + c + 1];
                }
                *(float2*)(Y + (long long)grow * sy + c) = v;
            }
        }
    }
}

// ---------------- edge pass ----------------
__global__ __launch_bounds__(256) void edge_kernel(
    const int* __restrict__ src, const int* __restrict__ dst,
    const float* __restrict__ dist,
    const float* __restrict__ tab,
    const float* __restrict__ hn,
    float* __restrict__ node)
{
    int gt = blockIdx.x * blockDim.x + threadIdx.x;
    int e = gt >> 5;
    int lane = gt & 31;
    if (e >= N_EDGES) return;
    int s = __ldg(src + e);
    int d = __ldg(dst + e);
    float di = __ldg(dist + e);
    float t = di * ((float)(GRID_G - 1) / 10.0f);
    int g = (int)t;
    g = g < GRID_G - 2 ? g : GRID_G - 2;
    float f = t - (float)g;
    const float4* p0 = (const float4*)(tab + (long long)g * DIM) + lane;
    float4 a = __ldg(p0);
    float4 b = __ldg(p0 + 32);
    float4 h = __ldg((const float4*)(hn + (long long)s * DIM) + lane);
    float4 m;
    m.x = fmaf(f, b.x - a.x, a.x) * h.x;
    m.y = fmaf(f, b.y - a.y, a.y) * h.y;
    m.z = fmaf(f, b.z - a.z, a.z) * h.z;
    m.w = fmaf(f, b.w - a.w, a.w) * h.w;
    float* p = node + (long long)d * DIM + lane * 4;
    asm volatile("red.global.add.v4.f32 [%0], {%1,%2,%3,%4};"
                 :: "l"(p), "f"(m.x), "f"(m.y), "f"(m.z), "f"(m.w) : "memory");
}

// ---------------- readout 2nd linear + graph scatter ----------------
__global__ void readout2_kernel(const float* __restrict__ W_r2, const float* __restrict__ b_r2,
                                const int* __restrict__ gid, float* __restrict__ out) {
    int n = blockIdx.x * blockDim.x + threadIdx.x;
    if (n >= N_NODES) return;
    float acc = b_r2[0];
    const float4* t = (const float4*)(g_T1 + (long long)n * 64);
    #pragma unroll
    for (int q = 0; q < 16; q++) {
        float4 v = t[q];
        acc += v.x * __ldg(W_r2 + q * 4 + 0) + v.y * __ldg(W_r2 + q * 4 + 1)
             + v.z * __ldg(W_r2 + q * 4 + 2) + v.w * __ldg(W_r2 + q * 4 + 3);
    }
    atomicAdd(&out[gid[n]], acc);
}

// ---------------- launch ----------------
extern "C" void kernel_launch(void* const* d_in, const int* in_sizes, int n_in,
                              void* d_out, int out_size) {
    const int*   atom_type = (const int*)d_in[0];
    const int*   src  = (const int*)d_in[1];
    const int*   dst  = (const int*)d_in[2];
    const int*   gid  = (const int*)d_in[3];
    const float* dist = (const float*)d_in[4];
    const float* emb  = (const float*)d_in[5];
    const float* W_n1 = (const float*)d_in[6];  const float* b_n1 = (const float*)d_in[7];
    const float* W_c1 = (const float*)d_in[8];  const float* b_c1 = (const float*)d_in[9];
    const float* W_c2 = (const float*)d_in[10]; const float* b_c2 = (const float*)d_in[11];
    const float* W_c3 = (const float*)d_in[12]; const float* b_c3 = (const float*)d_in[13];
    const float* W_n2 = (const float*)d_in[14]; const float* b_n2 = (const float*)d_in[15];
    const float* W_n3 = (const float*)d_in[16]; const float* b_n3 = (const float*)d_in[17];
    const float* W_r1 = (const float*)d_in[18]; const float* b_r1 = (const float*)d_in[19];
    const float* W_r2 = (const float*)d_in[20]; const float* b_r2 = (const float*)d_in[21];
    float* out = (float*)d_out;

    float *H, *Hn, *Node, *T1, *Tab;
    __nv_bfloat16 *WbHi, *WbLo;
    cudaGetSymbolAddress((void**)&H,    g_H);
    cudaGetSymbolAddress((void**)&Hn,   g_Hn);
    cudaGetSymbolAddress((void**)&Node, g_Node);
    cudaGetSymbolAddress((void**)&T1,   g_T1);
    cudaGetSymbolAddress((void**)&Tab,  g_Tab);
    cudaGetSymbolAddress((void**)&WbHi, g_WbHi);
    cudaGetSymbolAddress((void**)&WbLo, g_WbLo);

    cudaFuncSetAttribute(gemm_m1,  cudaFuncAttributeMaxDynamicSharedMemorySize, TSMEM_M);
    cudaFuncSetAttribute(gemm_m23, cudaFuncAttributeMaxDynamicSharedMemorySize, TSMEM_M);

    const int M = N_NODES;
    const int GB64 = (M + 63) / 64;     // 938
    const int GB = (M + 127) / 128;     // 469

    fold_kernel<<<dim3(DIM, N_LAYERS), DIM>>>(W_c2, b_c2, W_c3, b_c3);
    table_kernel<<<dim3(GRID_G, N_LAYERS), DIM>>>(W_c1, b_c1);
    prep_w<<<dim3(9, 16), 128>>>(W_n1, W_n2, W_n3, WbHi, WbLo);
    embed_kernel<<<(N_NODES * 32 + 255) / 256, 256>>>(atom_type, emb);

    for (int l = 0; l < N_LAYERS; l++) {
        // h_new = H_l @ W_n1 + (b_n1 + 1)
        gemm_m1<<<GB64, 256, TSMEM_M>>>(
            H + l * 128, 512,
            WbHi + (long long)(0 * 3 + l) * DIM * DIM, WbLo + (long long)(0 * 3 + l) * DIM * DIM,
            b_n1 + l * 128, 1.0f, Hn, 128, M);
        zero_node_kernel<<<(N_NODES * 32 + 255) / 256, 256>>>();
        edge_kernel<<<(N_EDGES * 32) / 256, 256>>>(
            src, dst, dist, Tab + (long long)l * GRID_G * DIM, Hn, Node);
        // H_{l+1} = H_l + sp_half(Node@W_n2+b_n2)@W_n3 + b_n3
        gemm_m23<<<GB64, 256, TSMEM_M>>>(
            Node, 128,
            WbHi + (long long)(1 * 3 + l) * DIM * DIM, WbLo + (long long)(1 * 3 + l) * DIM * DIM,
            b_n2 + l * 128,
            WbHi + (long long)(2 * 3 + l) * DIM * DIM, WbLo + (long long)(2 * 3 + l) * DIM * DIM,
            b_n3 + l * 128,
            H + l * 128, 512, H + (l + 1) * 128, 512, M);
    }

    gemm_kernel<512, 64, 2, false><<<GB, 256>>>(
        H, 512, W_r1, b_r1, 0.0f, nullptr, 0, T1, 64, M);
    zero_out_kernel<<<1, N_GRAPH>>>(out);
    readout2_kernel<<<(N_NODES + 255) / 256, 256>>>(W_r2, b_r2, gid, out);
}

// round 4
// speedup vs baseline: 1.4181x; 1.0750x over previous
#include <cuda_runtime.h>
#include <cuda_bf16.h>
#include <cuda_fp16.h>
#include <math.h>
#include <stdint.h>

#define N_NODES 60000
#define N_EDGES 600000
#define N_GRAPH 512
#define DIM 128
#define N_LAYERS 3
#define GRID_G 8192
#define TAB_STRIDE 768   // 128*fp32 + 128*fp16 per grid point

// ---------------- device scratch ----------------
__device__ float g_H[(long long)N_NODES * 512];
__device__ __half g_Hn2[(long long)N_NODES * DIM];       // h_new (+1 baked), fp16
__device__ float g_Node[(long long)N_NODES * DIM];
__device__ float g_Wf[N_LAYERS * DIM * DIM];
__device__ float g_bf[N_LAYERS * DIM];
__device__ float g_Tab[(long long)N_LAYERS * GRID_G * DIM];
__device__ __align__(256) unsigned char g_TabP[(long long)N_LAYERS * GRID_G * TAB_STRIDE];
// bf16 hi/lo weights as B-operand [N][K], 9 matrices (n1,n2,n3 x 3 layers)
__device__ __align__(256) __nv_bfloat16 g_WbHi[9 * DIM * DIM];
__device__ __align__(256) __nv_bfloat16 g_WbLo[9 * DIM * DIM];
// readout W_r1 as B-operand [64][512]
__device__ __align__(256) __nv_bfloat16 g_WrHi[64 * 512];
__device__ __align__(256) __nv_bfloat16 g_WrLo[64 * 512];

// ---------------- scalar helpers ----------------
__device__ __forceinline__ float sp_half(float x) {
    float bx = 0.5f * x;
    return bx > 14.0f ? x : 2.0f * log1pf(expf(bx));
}
__device__ __forceinline__ float sp_one(float x) {
    return x > 20.0f ? x : log1pf(expf(x));
}

// ---------------- HMMA helpers ----------------
__device__ __forceinline__ void mma16816(float* d, const uint32_t* a,
                                         uint32_t b0, uint32_t b1) {
    asm volatile(
        "mma.sync.aligned.m16n8k16.row.col.f32.bf16.bf16.f32 "
        "{%0,%1,%2,%3}, {%4,%5,%6,%7}, {%8,%9}, {%0,%1,%2,%3};"
        : "+f"(d[0]), "+f"(d[1]), "+f"(d[2]), "+f"(d[3])
        : "r"(a[0]), "r"(a[1]), "r"(a[2]), "r"(a[3]), "r"(b0), "r"(b1));
}

// smem layout (uint32 words): padded row stride 68 words (136 bf16)
#define ASTR 68
#define A_WORDS (64 * ASTR)            // 4352
#define B_WORDS (128 * ASTR)           // 8704
#define OFF_AHI 0
#define OFF_ALO A_WORDS
#define OFF_BHI (2 * A_WORDS)
#define OFF_BLO (2 * A_WORDS + B_WORDS)
#define TSMEM_M ((2 * A_WORDS + 2 * B_WORDS) * 4)   // 104448
// readout: B is 64 rows
#define BR_WORDS (64 * ASTR)
#define OFF_BHI_R (2 * A_WORDS)
#define OFF_BLO_R (2 * A_WORDS + BR_WORDS)
#define TSMEM_R ((2 * A_WORDS + 2 * BR_WORDS) * 4)  // 69632

__device__ __forceinline__ void split2(float x, float y, uint32_t& h, uint32_t& l) {
    __nv_bfloat162 hb = __floats2bfloat162_rn(x, y);
    float2 hf = __bfloat1622float2(hb);
    __nv_bfloat162 lb = __floats2bfloat162_rn(x - hf.x, y - hf.y);
    h = *(uint32_t*)&hb;
    l = *(uint32_t*)&lb;
}

// generic MMA core: acc[NT][4] += A(mw rows) @ B(nwbase..), K=128, 3-product split
template<int NT>
__device__ __forceinline__ void mma_core_t(const uint32_t* __restrict__ sm,
                                           int mw, int nwbase, int g, int tg,
                                           float acc[NT][4], int offBhi, int offBlo) {
    const uint32_t* Ahi = sm + OFF_AHI;
    const uint32_t* Alo = sm + OFF_ALO;
    const uint32_t* Bhi = sm + offBhi;
    const uint32_t* Blo = sm + offBlo;
    int ra0 = (mw * 16 + g) * ASTR;
    int ra1 = ra0 + 8 * ASTR;
    #pragma unroll
    for (int ks = 0; ks < 8; ks++) {
        int c = ks * 8 + tg;
        uint32_t ah[4], al[4];
        ah[0] = Ahi[ra0 + c];     ah[1] = Ahi[ra1 + c];
        ah[2] = Ahi[ra0 + c + 4]; ah[3] = Ahi[ra1 + c + 4];
        al[0] = Alo[ra0 + c];     al[1] = Alo[ra1 + c];
        al[2] = Alo[ra0 + c + 4]; al[3] = Alo[ra1 + c + 4];
        #pragma unroll
        for (int t = 0; t < NT; t++) {
            int rb = (nwbase + t * 8 + g) * ASTR;
            uint32_t bh0 = Bhi[rb + c], bh1 = Bhi[rb + c + 4];
            uint32_t bl0 = Blo[rb + c], bl1 = Blo[rb + c + 4];
            mma16816(acc[t], ah, bh0, bh1);
            mma16816(acc[t], ah, bl0, bl1);
            mma16816(acc[t], al, bh0, bh1);
        }
    }
}

// load X tile (64 rows x 128 f32 at col offset c0) -> A smem hi/lo
__device__ __forceinline__ void load_A(uint32_t* sm, const float* __restrict__ X,
                                       int sx, int c0, int r0, int M, int tid) {
    uint32_t* Ahi = sm + OFF_AHI;
    uint32_t* Alo = sm + OFF_ALO;
    #pragma unroll
    for (int j = 0; j < 8; j++) {
        int f = tid + j * 256;
        int row = f >> 5, q = f & 31;
        float4 v = make_float4(0.f, 0.f, 0.f, 0.f);
        int gr = r0 + row;
        if (gr < M) v = *(const float4*)(X + (long long)gr * sx + c0 + q * 4);
        uint32_t h0, l0, h1, l1;
        split2(v.x, v.y, h0, l0);
        split2(v.z, v.w, h1, l1);
        int w = row * ASTR + q * 2;
        *(uint2*)(Ahi + w) = make_uint2(h0, h1);
        *(uint2*)(Alo + w) = make_uint2(l0, l1);
    }
}

// copy packed W [128][64 words] -> B smem (padded)
__device__ __forceinline__ void load_B(uint32_t* sm, const __nv_bfloat16* __restrict__ Whi,
                                       const __nv_bfloat16* __restrict__ Wlo, int tid) {
    uint32_t* Bhi = sm + OFF_BHI;
    uint32_t* Blo = sm + OFF_BLO;
    const uint4* s1 = (const uint4*)Whi;
    const uint4* s2 = (const uint4*)Wlo;
    #pragma unroll
    for (int j = 0; j < 8; j++) {
        int i = tid + j * 256;
        int row = i >> 4, cq = (i & 15) * 4;
        *(uint4*)(Bhi + row * ASTR + cq) = s1[i];
        *(uint4*)(Blo + row * ASTR + cq) = s2[i];
    }
}

// readout B: 64 rows, chunk c of K=512 (row stride 256 words in gmem)
__device__ __forceinline__ void load_B_r(uint32_t* sm, const __nv_bfloat16* __restrict__ Whi,
                                         const __nv_bfloat16* __restrict__ Wlo,
                                         int chunk, int tid) {
    uint32_t* Bhi = sm + OFF_BHI_R;
    uint32_t* Blo = sm + OFF_BLO_R;
    const uint4* s1 = (const uint4*)Whi;
    const uint4* s2 = (const uint4*)Wlo;
    #pragma unroll
    for (int j = 0; j < 4; j++) {
        int i = tid + j * 256;                 // 1024 uint4
        int row = i >> 4, q = i & 15;
        int si = row * 64 + chunk * 16 + q;
        *(uint4*)(Bhi + row * ASTR + q * 4) = s1[si];
        *(uint4*)(Blo + row * ASTR + q * 4) = s2[si];
    }
}

// ---------------- weight prep ----------------
__global__ void prep_w(const float* __restrict__ Wn1, const float* __restrict__ Wn2,
                       const float* __restrict__ Wn3,
                       __nv_bfloat16* __restrict__ Hi, __nv_bfloat16* __restrict__ Lo) {
    int m = blockIdx.x;
    const float* src = (m < 3 ? Wn1 : (m < 6 ? Wn2 : Wn3)) + (long long)(m % 3) * DIM * DIM;
    __nv_bfloat16* dh = Hi + (long long)m * DIM * DIM;
    __nv_bfloat16* dl = Lo + (long long)m * DIM * DIM;
    int idx0 = blockIdx.y * 1024;
    for (int i = 0; i < 8; i++) {
        int idx = idx0 + i * 128 + threadIdx.x;
        int k = idx >> 7, n = idx & 127;
        float v = src[idx];
        __nv_bfloat16 h = __float2bfloat16(v);
        __nv_bfloat16 l = __float2bfloat16(v - __bfloat162float(h));
        dh[n * DIM + k] = h;
        dl[n * DIM + k] = l;
    }
}
__global__ void prep_r(const float* __restrict__ Wr1,
                       __nv_bfloat16* __restrict__ Hi, __nv_bfloat16* __restrict__ Lo) {
    int idx = blockIdx.x * 1024 + threadIdx.x;   // 32 blocks x 128 thr x 8
    for (int i = 0; i < 8; i++) {
        int f = idx + i * 128;
        int k = f >> 6, n = f & 63;
        float v = Wr1[f];
        __nv_bfloat16 h = __float2bfloat16(v);
        __nv_bfloat16 l = __float2bfloat16(v - __bfloat162float(h));
        Hi[n * 512 + k] = h;
        Lo[n * 512 + k] = l;
    }
}

// ---------------- fold W_c2 @ W_c3 ----------------
__global__ void fold_kernel(const float* __restrict__ Wc2, const float* __restrict__ bc2,
                            const float* __restrict__ Wc3, const float* __restrict__ bc3) {
    int k = blockIdx.x, l = blockIdx.y, j = threadIdx.x;
    __shared__ float row[DIM];
    row[j] = Wc2[((long long)l * DIM + k) * DIM + j];
    __syncthreads();
    float acc = 0.0f;
    #pragma unroll 4
    for (int m = 0; m < DIM; m++)
        acc += row[m] * Wc3[((long long)l * DIM + m) * DIM + j];
    g_Wf[((long long)l * DIM + k) * DIM + j] = acc;
    if (k == 0) {
        float bacc = bc3[l * DIM + j];
        #pragma unroll 4
        for (int m = 0; m < DIM; m++)
            bacc += bc2[l * DIM + m] * Wc3[((long long)l * DIM + m) * DIM + j];
        g_bf[l * DIM + j] = bacc;
    }
}

// ---------------- e(d) tables ----------------
__global__ void table_kernel(const float* __restrict__ Wc1, const float* __restrict__ bc1) {
    int g = blockIdx.x, l = blockIdx.y, j = threadIdx.x;
    __shared__ float rbf[32];
    __shared__ float spu[DIM];
    float dg = (float)g * (10.0f / (float)(GRID_G - 1));
    if (j < 30) {
        float c = (float)j * (10.0f / 29.0f);
        float dd = dg - c;
        rbf[j] = expf(-dd * dd * 2.9f);
    }
    __syncthreads();
    float u = bc1[l * DIM + j];
    #pragma unroll
    for (int r = 0; r < 30; r++)
        u += rbf[r] * Wc1[(l * 30 + r) * DIM + j];
    spu[j] = sp_half(u);
    __syncthreads();
    float acc = g_bf[l * DIM + j];
    #pragma unroll 4
    for (int m = 0; m < DIM; m++)
        acc += spu[m] * g_Wf[((long long)l * DIM + m) * DIM + j];
    g_Tab[((long long)l * GRID_G + g) * DIM + j] = acc;
}

// pack: value fp32 + delta fp16 per grid point
__global__ void pack_kernel() {
    int g = blockIdx.x, l = blockIdx.y, j = threadIdx.x;
    float v = g_Tab[((long long)l * GRID_G + g) * DIM + j];
    float nx = (g < GRID_G - 1) ? g_Tab[((long long)l * GRID_G + g + 1) * DIM + j] : v;
    unsigned char* row = g_TabP + ((long long)l * GRID_G + g) * TAB_STRIDE;
    ((float*)row)[j] = v;
    ((__half*)(row + 512))[j] = __float2half(nx - v);
}

// ---------------- embedding ----------------
__global__ void embed_kernel(const int* __restrict__ at, const float* __restrict__ emb) {
    int i = blockIdx.x * blockDim.x + threadIdx.x;
    if (i >= N_NODES * 32) return;
    int n = i >> 5, q = i & 31;
    float4 v = __ldg((const float4*)(emb + (long long)at[n] * DIM) + q);
    *(float4*)(g_H + (long long)n * 512 + q * 4) = v;
}
__global__ void zero_out_kernel(float* out) { out[threadIdx.x] = 0.0f; }

// ---------------- HMMA GEMM1: Hn2 = fp16(X @ W + b + 1), zero Node rows ----------------
__global__ __launch_bounds__(256) void gemm_m1(
    const float* __restrict__ X, int sx,
    const __nv_bfloat16* __restrict__ Whi, const __nv_bfloat16* __restrict__ Wlo,
    const float* __restrict__ bias, float bextra,
    __half* __restrict__ Hn2, float* __restrict__ Node, int M)
{
    extern __shared__ uint32_t sm[];
    int tid = threadIdx.x, wid = tid >> 5, lane = tid & 31;
    int mw = wid & 3, nw = wid >> 2;
    int g = lane >> 2, tg = lane & 3;
    int r0 = blockIdx.x * 64;

    load_A(sm, X, sx, 0, r0, M, tid);
    load_B(sm, Whi, Wlo, tid);
    // zero Node rows r0..r0+63 (used later by edge scatter)
    #pragma unroll
    for (int j = 0; j < 8; j++) {
        int i = tid + j * 256;           // 2048 float4 = 64x128 floats
        int row = r0 + (i >> 5);
        if (row < M) ((float4*)(Node + (long long)row * DIM))[i & 31] =
            make_float4(0.f, 0.f, 0.f, 0.f);
    }
    __syncthreads();

    float acc[8][4];
    #pragma unroll
    for (int t = 0; t < 8; t++)
        #pragma unroll
        for (int i = 0; i < 4; i++) acc[t][i] = 0.0f;
    mma_core_t<8>(sm, mw, nw * 64, g, tg, acc, OFF_BHI, OFF_BLO);

    int row0 = r0 + mw * 16 + g, row1 = row0 + 8;
    #pragma unroll
    for (int t = 0; t < 8; t++) {
        int col = nw * 64 + t * 8 + tg * 2;
        float b0 = __ldg(bias + col) + bextra;
        float b1 = __ldg(bias + col + 1) + bextra;
        if (row0 < M)
            *(__half2*)(Hn2 + (long long)row0 * DIM + col) =
                __floats2half2_rn(acc[t][0] + b0, acc[t][1] + b1);
        if (row1 < M)
            *(__half2*)(Hn2 + (long long)row1 * DIM + col) =
                __floats2half2_rn(acc[t][2] + b0, acc[t][3] + b1);
    }
}

// ---------------- fused: H' = H + sp(X@W2+b2)@W3+b3 ; optionally next Hn + zero Node ----------------
__global__ __launch_bounds__(256) void gemm_m23(
    const float* __restrict__ X, int sx,
    const __nv_bfloat16* __restrict__ W2hi, const __nv_bfloat16* __restrict__ W2lo,
    const float* __restrict__ b2,
    const __nv_bfloat16* __restrict__ W3hi, const __nv_bfloat16* __restrict__ W3lo,
    const float* __restrict__ b3,
    const float* __restrict__ Res, int sr,
    float* __restrict__ Y, int sy,
    const __nv_bfloat16* __restrict__ W1hi, const __nv_bfloat16* __restrict__ W1lo,
    const float* __restrict__ b1n,
    __half* __restrict__ Hn2, float* __restrict__ Node,
    int has_next, int M)
{
    extern __shared__ uint32_t sm[];
    uint32_t* Ahi = sm + OFF_AHI;
    uint32_t* Alo = sm + OFF_ALO;
    int tid = threadIdx.x, wid = tid >> 5, lane = tid & 31;
    int mw = wid & 3, nw = wid >> 2;
    int g = lane >> 2, tg = lane & 3;
    int r0 = blockIdx.x * 64;
    int rl0 = mw * 16 + g, rl1 = rl0 + 8;
    int row0 = r0 + rl0, row1 = row0 + 8;

    load_A(sm, X, sx, 0, r0, M, tid);
    load_B(sm, W2hi, W2lo, tid);
    __syncthreads();

    float acc[8][4];
    #pragma unroll
    for (int t = 0; t < 8; t++)
        #pragma unroll
        for (int i = 0; i < 4; i++) acc[t][i] = 0.0f;
    mma_core_t<8>(sm, mw, nw * 64, g, tg, acc, OFF_BHI, OFF_BLO);

    // t = sp_half(acc + b2) -> A smem (warp-local rows, no sync needed before)
    #pragma unroll
    for (int t = 0; t < 8; t++) {
        int col = nw * 64 + t * 8 + tg * 2;
        float b0 = __ldg(b2 + col), b1 = __ldg(b2 + col + 1);
        float t0 = sp_half(acc[t][0] + b0), t1 = sp_half(acc[t][1] + b1);
        float t2 = sp_half(acc[t][2] + b0), t3 = sp_half(acc[t][3] + b1);
        uint32_t h, l;
        int w0 = rl0 * ASTR + (col >> 1);
        int w1 = rl1 * ASTR + (col >> 1);
        split2(t0, t1, h, l); Ahi[w0] = h; Alo[w0] = l;
        split2(t2, t3, h, l); Ahi[w1] = h; Alo[w1] = l;
    }
    __syncthreads();
    load_B(sm, W3hi, W3lo, tid);
    __syncthreads();

    #pragma unroll
    for (int t = 0; t < 8; t++)
        #pragma unroll
        for (int i = 0; i < 4; i++) acc[t][i] = 0.0f;
    mma_core_t<8>(sm, mw, nw * 64, g, tg, acc, OFF_BHI, OFF_BLO);

    // Y = acc + b3 + Res -> gmem, and (if has_next) split Y into A smem
    #pragma unroll
    for (int t = 0; t < 8; t++) {
        int col = nw * 64 + t * 8 + tg * 2;
        float b0 = __ldg(b3 + col), b1 = __ldg(b3 + col + 1);
        float y0 = acc[t][0] + b0, y1 = acc[t][1] + b1;
        float y2 = acc[t][2] + b0, y3 = acc[t][3] + b1;
        if (row0 < M) {
            float2 r = *(const float2*)(Res + (long long)row0 * sr + col);
            y0 += r.x; y1 += r.y;
            *(float2*)(Y + (long long)row0 * sy + col) = make_float2(y0, y1);
        }
        if (row1 < M) {
            float2 r = *(const float2*)(Res + (long long)row1 * sr + col);
            y2 += r.x; y3 += r.y;
            *(float2*)(Y + (long long)row1 * sy + col) = make_float2(y2, y3);
        }
        if (has_next) {
            uint32_t h, l;
            int w0 = rl0 * ASTR + (col >> 1);
            int w1 = rl1 * ASTR + (col >> 1);
            split2(y0, y1, h, l); Ahi[w0] = h; Alo[w0] = l;
            split2(y2, y3, h, l); Ahi[w1] = h; Alo[w1] = l;
        }
    }
    if (!has_next) return;

    __syncthreads();
    load_B(sm, W1hi, W1lo, tid);
    // zero Node rows for the next edge pass
    #pragma unroll
    for (int j = 0; j < 8; j++) {
        int i = tid + j * 256;
        int row = r0 + (i >> 5);
        if (row < M) ((float4*)(Node + (long long)row * DIM))[i & 31] =
            make_float4(0.f, 0.f, 0.f, 0.f);
    }
    __syncthreads();

    #pragma unroll
    for (int t = 0; t < 8; t++)
        #pragma unroll
        for (int i = 0; i < 4; i++) acc[t][i] = 0.0f;
    mma_core_t<8>(sm, mw, nw * 64, g, tg, acc, OFF_BHI, OFF_BLO);

    #pragma unroll
    for (int t = 0; t < 8; t++) {
        int col = nw * 64 + t * 8 + tg * 2;
        float b0 = __ldg(b1n + col) + 1.0f;
        float b1 = __ldg(b1n + col + 1) + 1.0f;
        if (row0 < M)
            *(__half2*)(Hn2 + (long long)row0 * DIM + col) =
                __floats2half2_rn(acc[t][0] + b0, acc[t][1] + b1);
        if (row1 < M)
            *(__half2*)(Hn2 + (long long)row1 * DIM + col) =
                __floats2half2_rn(acc[t][2] + b0, acc[t][3] + b1);
    }
}

// ---------------- fused readout: out[gid] += sp1(hcat@Wr1+br1) . Wr2 + br2 ----------------
__global__ __launch_bounds__(256) void gemm_r(
    const float* __restrict__ X,                 // g_H, stride 512
    const __nv_bfloat16* __restrict__ Whi, const __nv_bfloat16* __restrict__ Wlo,
    const float* __restrict__ br1, const float* __restrict__ Wr2,
    const float* __restrict__ br2,
    const int* __restrict__ gid, float* __restrict__ out, int M)
{
    extern __shared__ uint32_t sm[];
    __shared__ float res[64];
    int tid = threadIdx.x, wid = tid >> 5, lane = tid & 31;
    int mw = wid & 3, nw = wid >> 2;
    int g = lane >> 2, tg = lane & 3;
    int r0 = blockIdx.x * 64;
    if (tid < 64) res[tid] = 0.0f;

    float acc[4][4];
    #pragma unroll
    for (int t = 0; t < 4; t++)
        #pragma unroll
        for (int i = 0; i < 4; i++) acc[t][i] = 0.0f;

    for (int ch = 0; ch < 4; ch++) {
        load_A(sm, X, 512, ch * 128, r0, M, tid);
        load_B_r(sm, g_WrHi, g_WrLo, ch, tid);
        __syncthreads();
        mma_core_t<4>(sm, mw, nw * 32, g, tg, acc, OFF_BHI_R, OFF_BLO_R);
        __syncthreads();
    }

    float p0 = 0.0f, p1 = 0.0f;
    #pragma unroll
    for (int t = 0; t < 4; t++) {
        int col = nw * 32 + t * 8 + tg * 2;
        float b0 = __ldg(br1 + col), b1 = __ldg(br1 + col + 1);
        float w0 = __ldg(Wr2 + col), w1 = __ldg(Wr2 + col + 1);
        p0 += sp_one(acc[t][0] + b0) * w0 + sp_one(acc[t][1] + b1) * w1;
        p1 += sp_one(acc[t][2] + b0) * w0 + sp_one(acc[t][3] + b1) * w1;
    }
    p0 += __shfl_down_sync(0xffffffff, p0, 1);
    p0 += __shfl_down_sync(0xffffffff, p0, 2);
    p1 += __shfl_down_sync(0xffffffff, p1, 1);
    p1 += __shfl_down_sync(0xffffffff, p1, 2);
    if (tg == 0) {
        atomicAdd(&res[mw * 16 + g], p0);
        atomicAdd(&res[mw * 16 + g + 8], p1);
    }
    __syncthreads();
    if (tid < 64) {
        int row = r0 + tid;
        if (row < M) atomicAdd(out + __ldg(gid + row), res[tid] + __ldg(br2));
    }
}

// ---------------- edge pass: msg = (val + f*delta) * hn, scatter-add ----------------
__global__ __launch_bounds__(256) void edge_kernel(
    const int* __restrict__ src, const int* __restrict__ dst,
    const float* __restrict__ dist,
    const unsigned char* __restrict__ tabp,   // this layer's packed table
    const __half* __restrict__ hn,
    float* __restrict__ node)
{
    int gt = blockIdx.x * blockDim.x + threadIdx.x;
    int e = gt >> 5;
    int lane = gt & 31;
    if (e >= N_EDGES) return;
    int s = __ldg(src + e);
    int d = __ldg(dst + e);
    float di = __ldg(dist + e);
    float t = di * ((float)(GRID_G - 1) / 10.0f);
    int g = (int)t;
    g = g < GRID_G - 2 ? g : GRID_G - 2;
    float f = t - (float)g;

    const unsigned char* row = tabp + (long long)g * TAB_STRIDE;
    float4 a = __ldg((const float4*)row + lane);
    uint2 draw = __ldg((const uint2*)(row + 512) + lane);
    float2 d01 = __half22float2(*(__half2*)&draw.x);
    float2 d23 = __half22float2(*(__half2*)&draw.y);
    uint2 hraw = __ldg((const uint2*)(hn + (long long)s * DIM) + lane);
    float2 h01 = __half22float2(*(__half2*)&hraw.x);
    float2 h23 = __half22float2(*(__half2*)&hraw.y);

    float4 m;
    m.x = fmaf(f, d01.x, a.x) * h01.x;
    m.y = fmaf(f, d01.y, a.y) * h01.y;
    m.z = fmaf(f, d23.x, a.z) * h23.x;
    m.w = fmaf(f, d23.y, a.w) * h23.y;
    float* p = node + (long long)d * DIM + lane * 4;
    asm volatile("red.global.add.v4.f32 [%0], {%1,%2,%3,%4};"
                 :: "l"(p), "f"(m.x), "f"(m.y), "f"(m.z), "f"(m.w) : "memory");
}

// ---------------- launch ----------------
extern "C" void kernel_launch(void* const* d_in, const int* in_sizes, int n_in,
                              void* d_out, int out_size) {
    const int*   atom_type = (const int*)d_in[0];
    const int*   src  = (const int*)d_in[1];
    const int*   dst  = (const int*)d_in[2];
    const int*   gid  = (const int*)d_in[3];
    const float* dist = (const float*)d_in[4];
    const float* emb  = (const float*)d_in[5];
    const float* W_n1 = (const float*)d_in[6];  const float* b_n1 = (const float*)d_in[7];
    const float* W_c1 = (const float*)d_in[8];  const float* b_c1 = (const float*)d_in[9];
    const float* W_c2 = (const float*)d_in[10]; const float* b_c2 = (const float*)d_in[11];
    const float* W_c3 = (const float*)d_in[12]; const float* b_c3 = (const float*)d_in[13];
    const float* W_n2 = (const float*)d_in[14]; const float* b_n2 = (const float*)d_in[15];
    const float* W_n3 = (const float*)d_in[16]; const float* b_n3 = (const float*)d_in[17];
    const float* W_r1 = (const float*)d_in[18]; const float* b_r1 = (const float*)d_in[19];
    const float* W_r2 = (const float*)d_in[20]; const float* b_r2 = (const float*)d_in[21];
    float* out = (float*)d_out;

    float *H, *Node;
    __half* Hn2;
    unsigned char* TabP;
    __nv_bfloat16 *WbHi, *WbLo, *WrHi, *WrLo;
    cudaGetSymbolAddress((void**)&H,    g_H);
    cudaGetSymbolAddress((void**)&Hn2,  g_Hn2);
    cudaGetSymbolAddress((void**)&Node, g_Node);
    cudaGetSymbolAddress((void**)&TabP, g_TabP);
    cudaGetSymbolAddress((void**)&WbHi, g_WbHi);
    cudaGetSymbolAddress((void**)&WbLo, g_WbLo);
    cudaGetSymbolAddress((void**)&WrHi, g_WrHi);
    cudaGetSymbolAddress((void**)&WrLo, g_WrLo);

    cudaFuncSetAttribute(gemm_m1,  cudaFuncAttributeMaxDynamicSharedMemorySize, TSMEM_M);
    cudaFuncSetAttribute(gemm_m23, cudaFuncAttributeMaxDynamicSharedMemorySize, TSMEM_M);
    cudaFuncSetAttribute(gemm_r,   cudaFuncAttributeMaxDynamicSharedMemorySize, TSMEM_R);

    const int M = N_NODES;
    const int GB64 = (M + 63) / 64;     // 938

    fold_kernel<<<dim3(DIM, N_LAYERS), DIM>>>(W_c2, b_c2, W_c3, b_c3);
    table_kernel<<<dim3(GRID_G, N_LAYERS), DIM>>>(W_c1, b_c1);
    pack_kernel<<<dim3(GRID_G, N_LAYERS), DIM>>>();
    prep_w<<<dim3(9, 16), 128>>>(W_n1, W_n2, W_n3, WbHi, WbLo);
    prep_r<<<32, 128>>>(W_r1, WrHi, WrLo);
    embed_kernel<<<(N_NODES * 32 + 255) / 256, 256>>>(atom_type, emb);

    // layer 0 h_new (+zero Node)
    gemm_m1<<<GB64, 256, TSMEM_M>>>(
        H, 512, WbHi, WbLo, b_n1, 1.0f, Hn2, Node, M);

    for (int l = 0; l < N_LAYERS; l++) {
        edge_kernel<<<(N_EDGES * 32) / 256, 256>>>(
            src, dst, dist, TabP + (long long)l * GRID_G * TAB_STRIDE, Hn2, Node);
        int nl = l + 1;
        int has_next = (nl < N_LAYERS);
        gemm_m23<<<GB64, 256, TSMEM_M>>>(
            Node, 128,
            WbHi + (long long)(3 + l) * DIM * DIM, WbLo + (long long)(3 + l) * DIM * DIM,
            b_n2 + l * 128,
            WbHi + (long long)(6 + l) * DIM * DIM, WbLo + (long long)(6 + l) * DIM * DIM,
            b_n3 + l * 128,
            H + l * 128, 512, H + nl * 128, 512,
            WbHi + (long long)(has_next ? nl : 0) * DIM * DIM,
            WbLo + (long long)(has_next ? nl : 0) * DIM * DIM,
            b_n1 + (has_next ? nl : 0) * 128,
            Hn2, Node, has_next, M);
    }

    zero_out_kernel<<<1, N_GRAPH>>>(out);
    gemm_r<<<GB64, 256, TSMEM_R>>>(H, WrHi, WrLo, b_r1, W_r2, b_r2, gid, out, M);
}

// round 5
// speedup vs baseline: 1.8088x; 1.2755x over previous
#include <cuda_runtime.h>
#include <cuda_bf16.h>
#include <cuda_fp16.h>
#include <math.h>
#include <stdint.h>

#define N_NODES 60000
#define N_EDGES 600000
#define N_GRAPH 512
#define DIM 128
#define N_LAYERS 3
#define GRID_G 4096
#define TAB_STRIDE 768   // 128*fp32 + 128*fp16 per grid point
#define NB_SCAN 235      // ceil(60000/256)

// ---------------- device scratch ----------------
__device__ float g_H[(long long)N_NODES * 512];
__device__ __half g_Hn2[(long long)N_NODES * DIM];       // h_new (+1 baked), fp16
__device__ float g_Node[(long long)N_NODES * DIM];
__device__ float g_Wf[N_LAYERS * DIM * DIM];
__device__ float g_bf[N_LAYERS * DIM];
__device__ float g_Tab[(long long)N_LAYERS * GRID_G * DIM];
__device__ __align__(256) unsigned char g_TabP[(long long)N_LAYERS * GRID_G * TAB_STRIDE];
__device__ __align__(256) __nv_bfloat16 g_WbHi[9 * DIM * DIM];
__device__ __align__(256) __nv_bfloat16 g_WbLo[9 * DIM * DIM];
__device__ __align__(256) __nv_bfloat16 g_WrHi[64 * 512];
__device__ __align__(256) __nv_bfloat16 g_WrLo[64 * 512];
// CSR build
__device__ int g_cnt[N_NODES];
__device__ int g_scan[N_NODES];
__device__ int g_bsum[NB_SCAN];
__device__ int g_boff[NB_SCAN];
__device__ int g_off[N_NODES + 1];
__device__ int g_cur[N_NODES];
__device__ uint2 g_rec[N_EDGES];

// ---------------- scalar helpers ----------------
__device__ __forceinline__ float sp_half(float x) {
    float bx = 0.5f * x;
    return bx > 14.0f ? x : 2.0f * log1pf(expf(bx));
}
__device__ __forceinline__ float sp_one(float x) {
    return x > 20.0f ? x : log1pf(expf(x));
}

// ---------------- HMMA helpers ----------------
__device__ __forceinline__ void mma16816(float* d, const uint32_t* a,
                                         uint32_t b0, uint32_t b1) {
    asm volatile(
        "mma.sync.aligned.m16n8k16.row.col.f32.bf16.bf16.f32 "
        "{%0,%1,%2,%3}, {%4,%5,%6,%7}, {%8,%9}, {%0,%1,%2,%3};"
        : "+f"(d[0]), "+f"(d[1]), "+f"(d[2]), "+f"(d[3])
        : "r"(a[0]), "r"(a[1]), "r"(a[2]), "r"(a[3]), "r"(b0), "r"(b1));
}

#define ASTR 68
#define A_WORDS (64 * ASTR)
#define B_WORDS (128 * ASTR)
#define OFF_AHI 0
#define OFF_ALO A_WORDS
#define OFF_BHI (2 * A_WORDS)
#define OFF_BLO (2 * A_WORDS + B_WORDS)
#define TSMEM_M ((2 * A_WORDS + 2 * B_WORDS) * 4)   // 104448
#define BR_WORDS (64 * ASTR)
#define OFF_BHI_R (2 * A_WORDS)
#define OFF_BLO_R (2 * A_WORDS + BR_WORDS)
#define TSMEM_R ((2 * A_WORDS + 2 * BR_WORDS) * 4)  // 69632

__device__ __forceinline__ void split2(float x, float y, uint32_t& h, uint32_t& l) {
    __nv_bfloat162 hb = __floats2bfloat162_rn(x, y);
    float2 hf = __bfloat1622float2(hb);
    __nv_bfloat162 lb = __floats2bfloat162_rn(x - hf.x, y - hf.y);
    h = *(uint32_t*)&hb;
    l = *(uint32_t*)&lb;
}

template<int NT>
__device__ __forceinline__ void mma_core_t(const uint32_t* __restrict__ sm,
                                           int mw, int nwbase, int g, int tg,
                                           float acc[NT][4], int offBhi, int offBlo) {
    const uint32_t* Ahi = sm + OFF_AHI;
    const uint32_t* Alo = sm + OFF_ALO;
    const uint32_t* Bhi = sm + offBhi;
    const uint32_t* Blo = sm + offBlo;
    int ra0 = (mw * 16 + g) * ASTR;
    int ra1 = ra0 + 8 * ASTR;
    #pragma unroll
    for (int ks = 0; ks < 8; ks++) {
        int c = ks * 8 + tg;
        uint32_t ah[4], al[4];
        ah[0] = Ahi[ra0 + c];     ah[1] = Ahi[ra1 + c];
        ah[2] = Ahi[ra0 + c + 4]; ah[3] = Ahi[ra1 + c + 4];
        al[0] = Alo[ra0 + c];     al[1] = Alo[ra1 + c];
        al[2] = Alo[ra0 + c + 4]; al[3] = Alo[ra1 + c + 4];
        #pragma unroll
        for (int t = 0; t < NT; t++) {
            int rb = (nwbase + t * 8 + g) * ASTR;
            uint32_t bh0 = Bhi[rb + c], bh1 = Bhi[rb + c + 4];
            uint32_t bl0 = Blo[rb + c], bl1 = Blo[rb + c + 4];
            mma16816(acc[t], ah, bh0, bh1);
            mma16816(acc[t], ah, bl0, bl1);
            mma16816(acc[t], al, bh0, bh1);
        }
    }
}

__device__ __forceinline__ void load_A(uint32_t* sm, const float* __restrict__ X,
                                       int sx, int c0, int r0, int M, int tid) {
    uint32_t* Ahi = sm + OFF_AHI;
    uint32_t* Alo = sm + OFF_ALO;
    #pragma unroll
    for (int j = 0; j < 8; j++) {
        int f = tid + j * 256;
        int row = f >> 5, q = f & 31;
        float4 v = make_float4(0.f, 0.f, 0.f, 0.f);
        int gr = r0 + row;
        if (gr < M) v = *(const float4*)(X + (long long)gr * sx + c0 + q * 4);
        uint32_t h0, l0, h1, l1;
        split2(v.x, v.y, h0, l0);
        split2(v.z, v.w, h1, l1);
        int w = row * ASTR + q * 2;
        *(uint2*)(Ahi + w) = make_uint2(h0, h1);
        *(uint2*)(Alo + w) = make_uint2(l0, l1);
    }
}

__device__ __forceinline__ void load_B(uint32_t* sm, const __nv_bfloat16* __restrict__ Whi,
                                       const __nv_bfloat16* __restrict__ Wlo, int tid) {
    uint32_t* Bhi = sm + OFF_BHI;
    uint32_t* Blo = sm + OFF_BLO;
    const uint4* s1 = (const uint4*)Whi;
    const uint4* s2 = (const uint4*)Wlo;
    #pragma unroll
    for (int j = 0; j < 8; j++) {
        int i = tid + j * 256;
        int row = i >> 4, cq = (i & 15) * 4;
        *(uint4*)(Bhi + row * ASTR + cq) = s1[i];
        *(uint4*)(Blo + row * ASTR + cq) = s2[i];
    }
}

__device__ __forceinline__ void load_B_r(uint32_t* sm, const __nv_bfloat16* __restrict__ Whi,
                                         const __nv_bfloat16* __restrict__ Wlo,
                                         int chunk, int tid) {
    uint32_t* Bhi = sm + OFF_BHI_R;
    uint32_t* Blo = sm + OFF_BLO_R;
    const uint4* s1 = (const uint4*)Whi;
    const uint4* s2 = (const uint4*)Wlo;
    #pragma unroll
    for (int j = 0; j < 4; j++) {
        int i = tid + j * 256;
        int row = i >> 4, q = i & 15;
        int si = row * 64 + chunk * 16 + q;
        *(uint4*)(Bhi + row * ASTR + q * 4) = s1[si];
        *(uint4*)(Blo + row * ASTR + q * 4) = s2[si];
    }
}

// ---------------- weight prep ----------------
__global__ void prep_w(const float* __restrict__ Wn1, const float* __restrict__ Wn2,
                       const float* __restrict__ Wn3,
                       __nv_bfloat16* __restrict__ Hi, __nv_bfloat16* __restrict__ Lo) {
    int m = blockIdx.x;
    const float* src = (m < 3 ? Wn1 : (m < 6 ? Wn2 : Wn3)) + (long long)(m % 3) * DIM * DIM;
    __nv_bfloat16* dh = Hi + (long long)m * DIM * DIM;
    __nv_bfloat16* dl = Lo + (long long)m * DIM * DIM;
    int idx0 = blockIdx.y * 1024;
    for (int i = 0; i < 8; i++) {
        int idx = idx0 + i * 128 + threadIdx.x;
        int k = idx >> 7, n = idx & 127;
        float v = src[idx];
        __nv_bfloat16 h = __float2bfloat16(v);
        __nv_bfloat16 l = __float2bfloat16(v - __bfloat162float(h));
        dh[n * DIM + k] = h;
        dl[n * DIM + k] = l;
    }
}
__global__ void prep_r(const float* __restrict__ Wr1,
                       __nv_bfloat16* __restrict__ Hi, __nv_bfloat16* __restrict__ Lo) {
    int idx = blockIdx.x * 1024 + threadIdx.x;
    for (int i = 0; i < 8; i++) {
        int f = idx + i * 128;
        int k = f >> 6, n = f & 63;
        float v = Wr1[f];
        __nv_bfloat16 h = __float2bfloat16(v);
        __nv_bfloat16 l = __float2bfloat16(v - __bfloat162float(h));
        Hi[n * 512 + k] = h;
        Lo[n * 512 + k] = l;
    }
}

// ---------------- fold W_c2 @ W_c3 ----------------
__global__ void fold_kernel(const float* __restrict__ Wc2, const float* __restrict__ bc2,
                            const float* __restrict__ Wc3, const float* __restrict__ bc3) {
    int k = blockIdx.x, l = blockIdx.y, j = threadIdx.x;
    __shared__ float row[DIM];
    row[j] = Wc2[((long long)l * DIM + k) * DIM + j];
    __syncthreads();
    float acc = 0.0f;
    #pragma unroll 4
    for (int m = 0; m < DIM; m++)
        acc += row[m] * Wc3[((long long)l * DIM + m) * DIM + j];
    g_Wf[((long long)l * DIM + k) * DIM + j] = acc;
    if (k == 0) {
        float bacc = bc3[l * DIM + j];
        #pragma unroll 4
        for (int m = 0; m < DIM; m++)
            bacc += bc2[l * DIM + m] * Wc3[((long long)l * DIM + m) * DIM + j];
        g_bf[l * DIM + j] = bacc;
    }
}

// ---------------- e(d) tables ----------------
__global__ void table_kernel(const float* __restrict__ Wc1, const float* __restrict__ bc1) {
    int g = blockIdx.x, l = blockIdx.y, j = threadIdx.x;
    __shared__ float rbf[32];
    __shared__ float spu[DIM];
    float dg = (float)g * (10.0f / (float)(GRID_G - 1));
    if (j < 30) {
        float c = (float)j * (10.0f / 29.0f);
        float dd = dg - c;
        rbf[j] = expf(-dd * dd * 2.9f);
    }
    __syncthreads();
    float u = bc1[l * DIM + j];
    #pragma unroll
    for (int r = 0; r < 30; r++)
        u += rbf[r] * Wc1[(l * 30 + r) * DIM + j];
    spu[j] = sp_half(u);
    __syncthreads();
    float acc = g_bf[l * DIM + j];
    #pragma unroll 4
    for (int m = 0; m < DIM; m++)
        acc += spu[m] * g_Wf[((long long)l * DIM + m) * DIM + j];
    g_Tab[((long long)l * GRID_G + g) * DIM + j] = acc;
}

__global__ void pack_kernel() {
    int g = blockIdx.x, l = blockIdx.y, j = threadIdx.x;
    float v = g_Tab[((long long)l * GRID_G + g) * DIM + j];
    float nx = (g < GRID_G - 1) ? g_Tab[((long long)l * GRID_G + g + 1) * DIM + j] : v;
    unsigned char* row = g_TabP + ((long long)l * GRID_G + g) * TAB_STRIDE;
    ((float*)row)[j] = v;
    ((__half*)(row + 512))[j] = __float2half(nx - v);
}

// ---------------- embedding ----------------
__global__ void embed_kernel(const int* __restrict__ at, const float* __restrict__ emb) {
    int i = blockIdx.x * blockDim.x + threadIdx.x;
    if (i >= N_NODES * 32) return;
    int n = i >> 5, q = i & 31;
    float4 v = __ldg((const float4*)(emb + (long long)at[n] * DIM) + q);
    *(float4*)(g_H + (long long)n * 512 + q * 4) = v;
}
__global__ void zero_out_kernel(float* out) { out[threadIdx.x] = 0.0f; }

// ---------------- CSR build ----------------
__global__ void zero_cnt() {
    int i = blockIdx.x * 256 + threadIdx.x;
    if (i < N_NODES) g_cnt[i] = 0;
}
__global__ void hist_kernel(const int* __restrict__ dst) {
    int e = blockIdx.x * 256 + threadIdx.x;
    if (e < N_EDGES) atomicAdd(&g_cnt[dst[e]], 1);
}
__global__ void scan1() {
    __shared__ int sh[256];
    int tid = threadIdx.x;
    int n = blockIdx.x * 256 + tid;
    int v = (n < N_NODES) ? g_cnt[n] : 0;
    sh[tid] = v; __syncthreads();
    #pragma unroll
    for (int o = 1; o < 256; o <<= 1) {
        int t = (tid >= o) ? sh[tid - o] : 0;
        __syncthreads();
        sh[tid] += t;
        __syncthreads();
    }
    if (n < N_NODES) g_scan[n] = sh[tid] - v;
    if (tid == 255) g_bsum[blockIdx.x] = sh[tid];
}
__global__ void scan2() {
    __shared__ int sh[256];
    int tid = threadIdx.x;
    int v = (tid < NB_SCAN) ? g_bsum[tid] : 0;
    sh[tid] = v; __syncthreads();
    #pragma unroll
    for (int o = 1; o < 256; o <<= 1) {
        int t = (tid >= o) ? sh[tid - o] : 0;
        __syncthreads();
        sh[tid] += t;
        __syncthreads();
    }
    if (tid < NB_SCAN) g_boff[tid] = sh[tid] - v;
}
__global__ void scan3() {
    int n = blockIdx.x * 256 + threadIdx.x;
    if (n < N_NODES) {
        int o = g_scan[n] + g_boff[blockIdx.x];
        g_off[n] = o;
        g_cur[n] = o;
    }
    if (n == 0) g_off[N_NODES] = N_EDGES;
}
__global__ void scatter_kernel(const int* __restrict__ src, const int* __restrict__ dst,
                               const float* __restrict__ dist) {
    int e = blockIdx.x * 256 + threadIdx.x;
    if (e >= N_EDGES) return;
    int d = __ldg(dst + e);
    int pos = atomicAdd(&g_cur[d], 1);
    float di = __ldg(dist + e);
    float t = di * ((float)(GRID_G - 1) / 10.0f);
    int gg = (int)t;
    gg = gg < GRID_G - 2 ? gg : GRID_G - 2;
    float f = t - (float)gg;
    unsigned int fp = (unsigned int)__half_as_ushort(__float2half_rn(f));
    g_rec[pos] = make_uint2((unsigned)__ldg(src + e), (unsigned)gg | (fp << 16));
}

// ---------------- edge gather: Node[n] = sum_in (val + f*delta) * hn[src] ----------------
__global__ __launch_bounds__(256) void edge_gather(
    const unsigned char* __restrict__ tabp,
    const __half* __restrict__ hn,
    float* __restrict__ node)
{
    int wid = threadIdx.x >> 5, lane = threadIdx.x & 31;
    int n = blockIdx.x * 8 + wid;
    if (n >= N_NODES) return;
    int beg = __ldg(&g_off[n]);
    int end = __ldg(&g_off[n + 1]);
    float4 acc = make_float4(0.f, 0.f, 0.f, 0.f);
    for (int i = beg; i < end; i++) {
        uint2 r = __ldg(&g_rec[i]);
        int s = (int)r.x;
        int gg = (int)(r.y & 0xffffu);
        float f = __half2float(__ushort_as_half((unsigned short)(r.y >> 16)));
        const unsigned char* row = tabp + (long long)gg * TAB_STRIDE;
        float4 a = __ldg((const float4*)row + lane);
        uint2 draw = __ldg((const uint2*)(row + 512) + lane);
        float2 d01 = __half22float2(*(__half2*)&draw.x);
        float2 d23 = __half22float2(*(__half2*)&draw.y);
        uint2 hraw = __ldg((const uint2*)(hn + (long long)s * DIM) + lane);
        float2 h01 = __half22float2(*(__half2*)&hraw.x);
        float2 h23 = __half22float2(*(__half2*)&hraw.y);
        acc.x += fmaf(f, d01.x, a.x) * h01.x;
        acc.y += fmaf(f, d01.y, a.y) * h01.y;
        acc.z += fmaf(f, d23.x, a.z) * h23.x;
        acc.w += fmaf(f, d23.y, a.w) * h23.y;
    }
    *(float4*)(node + (long long)n * DIM + lane * 4) = acc;
}

// ---------------- HMMA GEMM1: Hn2 = fp16(X @ W + b + 1) ----------------
__global__ __launch_bounds__(256) void gemm_m1(
    const float* __restrict__ X, int sx,
    const __nv_bfloat16* __restrict__ Whi, const __nv_bfloat16* __restrict__ Wlo,
    const float* __restrict__ bias, float bextra,
    __half* __restrict__ Hn2, int M)
{
    extern __shared__ uint32_t sm[];
    int tid = threadIdx.x, wid = tid >> 5, lane = tid & 31;
    int mw = wid & 3, nw = wid >> 2;
    int g = lane >> 2, tg = lane & 3;
    int r0 = blockIdx.x * 64;

    load_A(sm, X, sx, 0, r0, M, tid);
    load_B(sm, Whi, Wlo, tid);
    __syncthreads();

    float acc[8][4];
    #pragma unroll
    for (int t = 0; t < 8; t++)
        #pragma unroll
        for (int i = 0; i < 4; i++) acc[t][i] = 0.0f;
    mma_core_t<8>(sm, mw, nw * 64, g, tg, acc, OFF_BHI, OFF_BLO);

    int row0 = r0 + mw * 16 + g, row1 = row0 + 8;
    #pragma unroll
    for (int t = 0; t < 8; t++) {
        int col = nw * 64 + t * 8 + tg * 2;
        float b0 = __ldg(bias + col) + bextra;
        float b1 = __ldg(bias + col + 1) + bextra;
        if (row0 < M)
            *(__half2*)(Hn2 + (long long)row0 * DIM + col) =
                __floats2half2_rn(acc[t][0] + b0, acc[t][1] + b1);
        if (row1 < M)
            *(__half2*)(Hn2 + (long long)row1 * DIM + col) =
                __floats2half2_rn(acc[t][2] + b0, acc[t][3] + b1);
    }
}

// ---------------- fused: H' = H + sp(X@W2+b2)@W3+b3 ; optionally next Hn ----------------
__global__ __launch_bounds__(256) void gemm_m23(
    const float* __restrict__ X, int sx,
    const __nv_bfloat16* __restrict__ W2hi, const __nv_bfloat16* __restrict__ W2lo,
    const float* __restrict__ b2,
    const __nv_bfloat16* __restrict__ W3hi, const __nv_bfloat16* __restrict__ W3lo,
    const float* __restrict__ b3,
    const float* __restrict__ Res, int sr,
    float* __restrict__ Y, int sy,
    const __nv_bfloat16* __restrict__ W1hi, const __nv_bfloat16* __restrict__ W1lo,
    const float* __restrict__ b1n,
    __half* __restrict__ Hn2,
    int has_next, int M)
{
    extern __shared__ uint32_t sm[];
    uint32_t* Ahi = sm + OFF_AHI;
    uint32_t* Alo = sm + OFF_ALO;
    int tid = threadIdx.x, wid = tid >> 5, lane = tid & 31;
    int mw = wid & 3, nw = wid >> 2;
    int g = lane >> 2, tg = lane & 3;
    int r0 = blockIdx.x * 64;
    int rl0 = mw * 16 + g, rl1 = rl0 + 8;
    int row0 = r0 + rl0, row1 = row0 + 8;

    load_A(sm, X, sx, 0, r0, M, tid);
    load_B(sm, W2hi, W2lo, tid);
    __syncthreads();

    float acc[8][4];
    #pragma unroll
    for (int t = 0; t < 8; t++)
        #pragma unroll
        for (int i = 0; i < 4; i++) acc[t][i] = 0.0f;
    mma_core_t<8>(sm, mw, nw * 64, g, tg, acc, OFF_BHI, OFF_BLO);

    #pragma unroll
    for (int t = 0; t < 8; t++) {
        int col = nw * 64 + t * 8 + tg * 2;
        float b0 = __ldg(b2 + col), b1 = __ldg(b2 + col + 1);
        float t0 = sp_half(acc[t][0] + b0), t1 = sp_half(acc[t][1] + b1);
        float t2 = sp_half(acc[t][2] + b0), t3 = sp_half(acc[t][3] + b1);
        uint32_t h, l;
        int w0 = rl0 * ASTR + (col >> 1);
        int w1 = rl1 * ASTR + (col >> 1);
        split2(t0, t1, h, l); Ahi[w0] = h; Alo[w0] = l;
        split2(t2, t3, h, l); Ahi[w1] = h; Alo[w1] = l;
    }
    __syncthreads();
    load_B(sm, W3hi, W3lo, tid);
    __syncthreads();

    #pragma unroll
    for (int t = 0; t < 8; t++)
        #pragma unroll
        for (int i = 0; i < 4; i++) acc[t][i] = 0.0f;
    mma_core_t<8>(sm, mw, nw * 64, g, tg, acc, OFF_BHI, OFF_BLO);

    #pragma unroll
    for (int t = 0; t < 8; t++) {
        int col = nw * 64 + t * 8 + tg * 2;
        float b0 = __ldg(b3 + col), b1 = __ldg(b3 + col + 1);
        float y0 = acc[t][0] + b0, y1 = acc[t][1] + b1;
        float y2 = acc[t][2] + b0, y3 = acc[t][3] + b1;
        if (row0 < M) {
            float2 r = *(const float2*)(Res + (long long)row0 * sr + col);
            y0 += r.x; y1 += r.y;
            *(float2*)(Y + (long long)row0 * sy + col) = make_float2(y0, y1);
        }
        if (row1 < M) {
            float2 r = *(const float2*)(Res + (long long)row1 * sr + col);
            y2 += r.x; y3 += r.y;
            *(float2*)(Y + (long long)row1 * sy + col) = make_float2(y2, y3);
        }
        if (has_next) {
            uint32_t h, l;
            int w0 = rl0 * ASTR + (col >> 1);
            int w1 = rl1 * ASTR + (col >> 1);
            split2(y0, y1, h, l); Ahi[w0] = h; Alo[w0] = l;
            split2(y2, y3, h, l); Ahi[w1] = h; Alo[w1] = l;
        }
    }
    if (!has_next) return;

    __syncthreads();
    load_B(sm, W1hi, W1lo, tid);
    __syncthreads();

    #pragma unroll
    for (int t = 0; t < 8; t++)
        #pragma unroll
        for (int i = 0; i < 4; i++) acc[t][i] = 0.0f;
    mma_core_t<8>(sm, mw, nw * 64, g, tg, acc, OFF_BHI, OFF_BLO);

    #pragma unroll
    for (int t = 0; t < 8; t++) {
        int col = nw * 64 + t * 8 + tg * 2;
        float b0 = __ldg(b1n + col) + 1.0f;
        float b1 = __ldg(b1n + col + 1) + 1.0f;
        if (row0 < M)
            *(__half2*)(Hn2 + (long long)row0 * DIM + col) =
                __floats2half2_rn(acc[t][0] + b0, acc[t][1] + b1);
        if (row1 < M)
            *(__half2*)(Hn2 + (long long)row1 * DIM + col) =
                __floats2half2_rn(acc[t][2] + b0, acc[t][3] + b1);
    }
}

// ---------------- fused readout ----------------
__global__ __launch_bounds__(256) void gemm_r(
    const float* __restrict__ X,
    const __nv_bfloat16* __restrict__ Whi, const __nv_bfloat16* __restrict__ Wlo,
    const float* __restrict__ br1, const float* __restrict__ Wr2,
    const float* __restrict__ br2,
    const int* __restrict__ gid, float* __restrict__ out, int M)
{
    extern __shared__ uint32_t sm[];
    __shared__ float res[64];
    int tid = threadIdx.x, wid = tid >> 5, lane = tid & 31;
    int mw = wid & 3, nw = wid >> 2;
    int g = lane >> 2, tg = lane & 3;
    int r0 = blockIdx.x * 64;
    if (tid < 64) res[tid] = 0.0f;

    float acc[4][4];
    #pragma unroll
    for (int t = 0; t < 4; t++)
        #pragma unroll
        for (int i = 0; i < 4; i++) acc[t][i] = 0.0f;

    for (int ch = 0; ch < 4; ch++) {
        load_A(sm, X, 512, ch * 128, r0, M, tid);
        load_B_r(sm, g_WrHi, g_WrLo, ch, tid);
        __syncthreads();
        mma_core_t<4>(sm, mw, nw * 32, g, tg, acc, OFF_BHI_R, OFF_BLO_R);
        __syncthreads();
    }

    float p0 = 0.0f, p1 = 0.0f;
    #pragma unroll
    for (int t = 0; t < 4; t++) {
        int col = nw * 32 + t * 8 + tg * 2;
        float b0 = __ldg(br1 + col), b1 = __ldg(br1 + col + 1);
        float w0 = __ldg(Wr2 + col), w1 = __ldg(Wr2 + col + 1);
        p0 += sp_one(acc[t][0] + b0) * w0 + sp_one(acc[t][1] + b1) * w1;
        p1 += sp_one(acc[t][2] + b0) * w0 + sp_one(acc[t][3] + b1) * w1;
    }
    p0 += __shfl_down_sync(0xffffffff, p0, 1);
    p0 += __shfl_down_sync(0xffffffff, p0, 2);
    p1 += __shfl_down_sync(0xffffffff, p1, 1);
    p1 += __shfl_down_sync(0xffffffff, p1, 2);
    if (tg == 0) {
        atomicAdd(&res[mw * 16 + g], p0);
        atomicAdd(&res[mw * 16 + g + 8], p1);
    }
    __syncthreads();
    if (tid < 64) {
        int row = r0 + tid;
        if (row < M) atomicAdd(out + __ldg(gid + row), res[tid] + __ldg(br2));
    }
}

// ---------------- launch ----------------
extern "C" void kernel_launch(void* const* d_in, const int* in_sizes, int n_in,
                              void* d_out, int out_size) {
    const int*   atom_type = (const int*)d_in[0];
    const int*   src  = (const int*)d_in[1];
    const int*   dst  = (const int*)d_in[2];
    const int*   gid  = (const int*)d_in[3];
    const float* dist = (const float*)d_in[4];
    const float* emb  = (const float*)d_in[5];
    const float* W_n1 = (const float*)d_in[6];  const float* b_n1 = (const float*)d_in[7];
    const float* W_c1 = (const float*)d_in[8];  const float* b_c1 = (const float*)d_in[9];
    const float* W_c2 = (const float*)d_in[10]; const float* b_c2 = (const float*)d_in[11];
    const float* W_c3 = (const float*)d_in[12]; const float* b_c3 = (const float*)d_in[13];
    const float* W_n2 = (const float*)d_in[14]; const float* b_n2 = (const float*)d_in[15];
    const float* W_n3 = (const float*)d_in[16]; const float* b_n3 = (const float*)d_in[17];
    const float* W_r1 = (const float*)d_in[18]; const float* b_r1 = (const float*)d_in[19];
    const float* W_r2 = (const float*)d_in[20]; const float* b_r2 = (const float*)d_in[21];
    float* out = (float*)d_out;

    float *H, *Node;
    __half* Hn2;
    unsigned char* TabP;
    __nv_bfloat16 *WbHi, *WbLo, *WrHi, *WrLo;
    cudaGetSymbolAddress((void**)&H,    g_H);
    cudaGetSymbolAddress((void**)&Hn2,  g_Hn2);
    cudaGetSymbolAddress((void**)&Node, g_Node);
    cudaGetSymbolAddress((void**)&TabP, g_TabP);
    cudaGetSymbolAddress((void**)&WbHi, g_WbHi);
    cudaGetSymbolAddress((void**)&WbLo, g_WbLo);
    cudaGetSymbolAddress((void**)&WrHi, g_WrHi);
    cudaGetSymbolAddress((void**)&WrLo, g_WrLo);

    cudaFuncSetAttribute(gemm_m1,  cudaFuncAttributeMaxDynamicSharedMemorySize, TSMEM_M);
    cudaFuncSetAttribute(gemm_m23, cudaFuncAttributeMaxDynamicSharedMemorySize, TSMEM_M);
    cudaFuncSetAttribute(gemm_r,   cudaFuncAttributeMaxDynamicSharedMemorySize, TSMEM_R);

    const int M = N_NODES;
    const int GB64 = (M + 63) / 64;     // 938
    const int EB = (N_EDGES + 255) / 256;

    // precompute: tables + weights + embedding + CSR
    fold_kernel<<<dim3(DIM, N_LAYERS), DIM>>>(W_c2, b_c2, W_c3, b_c3);
    table_kernel<<<dim3(GRID_G, N_LAYERS), DIM>>>(W_c1, b_c1);
    pack_kernel<<<dim3(GRID_G, N_LAYERS), DIM>>>();
    prep_w<<<dim3(9, 16), 128>>>(W_n1, W_n2, W_n3, WbHi, WbLo);
    prep_r<<<32, 128>>>(W_r1, WrHi, WrLo);
    embed_kernel<<<(N_NODES * 32 + 255) / 256, 256>>>(atom_type, emb);

    zero_cnt<<<NB_SCAN, 256>>>();
    hist_kernel<<<EB, 256>>>(dst);
    scan1<<<NB_SCAN, 256>>>();
    scan2<<<1, 256>>>();
    scan3<<<NB_SCAN, 256>>>();
    scatter_kernel<<<EB, 256>>>(src, dst, dist);

    // layer 0 h_new
    gemm_m1<<<GB64, 256, TSMEM_M>>>(H, 512, WbHi, WbLo, b_n1, 1.0f, Hn2, M);

    for (int l = 0; l < N_LAYERS; l++) {
        edge_gather<<<(N_NODES + 7) / 8, 256>>>(
            TabP + (long long)l * GRID_G * TAB_STRIDE, Hn2, Node);
        int nl = l + 1;
        int has_next = (nl < N_LAYERS);
        gemm_m23<<<GB64, 256, TSMEM_M>>>(
            Node, 128,
            WbHi + (long long)(3 + l) * DIM * DIM, WbLo + (long long)(3 + l) * DIM * DIM,
            b_n2 + l * 128,
            WbHi + (long long)(6 + l) * DIM * DIM, WbLo + (long long)(6 + l) * DIM * DIM,
            b_n3 + l * 128,
            H + l * 128, 512, H + nl * 128, 512,
            WbHi + (long long)(has_next ? nl : 0) * DIM * DIM,
            WbLo + (long long)(has_next ? nl : 0) * DIM * DIM,
            b_n1 + (has_next ? nl : 0) * 128,
            Hn2, has_next, M);
    }

    zero_out_kernel<<<1, N_GRAPH>>>(out);
    gemm_r<<<GB64, 256, TSMEM_R>>>(H, WrHi, WrLo, b_r1, W_r2, b_r2, gid, out, M);
}

// round 6
// speedup vs baseline: 1.8922x; 1.0461x over previous
#include <cuda_runtime.h>
#include <cuda_bf16.h>
#include <cuda_fp16.h>
#include <math.h>
#include <stdint.h>

#define N_NODES 60000
#define N_EDGES 600000
#define N_GRAPH 512
#define DIM 128
#define N_LAYERS 3
#define GRID_G 4096
#define TAB_STRIDE 512   // 128 x half2(v, dv) per grid point
#define NB_SCAN 235      // ceil(60000/256)

// ---------------- device scratch ----------------
__device__ float g_H[(long long)N_NODES * 512];
__device__ __half g_Hn2[(long long)N_NODES * DIM];
__device__ float g_Node[(long long)N_NODES * DIM];
__device__ float g_bf[N_LAYERS * DIM];
__device__ float g_Spu[(long long)N_LAYERS * GRID_G * DIM];
__device__ float g_Tab[(long long)N_LAYERS * GRID_G * DIM];
__device__ __align__(256) unsigned char g_TabP[(long long)N_LAYERS * GRID_G * TAB_STRIDE];
__device__ __align__(256) __nv_bfloat16 g_WbHi[9 * DIM * DIM];
__device__ __align__(256) __nv_bfloat16 g_WbLo[9 * DIM * DIM];
__device__ __align__(256) __nv_bfloat16 g_WfHi[N_LAYERS * DIM * DIM];
__device__ __align__(256) __nv_bfloat16 g_WfLo[N_LAYERS * DIM * DIM];
__device__ __align__(256) __nv_bfloat16 g_WrHi[64 * 512];
__device__ __align__(256) __nv_bfloat16 g_WrLo[64 * 512];
// CSR build
__device__ int g_cnt[N_NODES];
__device__ int g_scan[N_NODES];
__device__ int g_bsum[NB_SCAN];
__device__ int g_boff[NB_SCAN];
__device__ int g_off[N_NODES + 1];
__device__ int g_cur[N_NODES];
__device__ uint2 g_rec[N_EDGES];

// ---------------- scalar helpers ----------------
__device__ __forceinline__ float sp_half(float x) {
    float bx = 0.5f * x;
    return bx > 14.0f ? x : 2.0f * log1pf(expf(bx));
}
__device__ __forceinline__ float sp_one(float x) {
    return x > 20.0f ? x : log1pf(expf(x));
}

// ---------------- HMMA helpers ----------------
__device__ __forceinline__ void mma16816(float* d, const uint32_t* a,
                                         uint32_t b0, uint32_t b1) {
    asm volatile(
        "mma.sync.aligned.m16n8k16.row.col.f32.bf16.bf16.f32 "
        "{%0,%1,%2,%3}, {%4,%5,%6,%7}, {%8,%9}, {%0,%1,%2,%3};"
        : "+f"(d[0]), "+f"(d[1]), "+f"(d[2]), "+f"(d[3])
        : "r"(a[0]), "r"(a[1]), "r"(a[2]), "r"(a[3]), "r"(b0), "r"(b1));
}

#define ASTR 68
#define A_WORDS (64 * ASTR)
#define B_WORDS (128 * ASTR)
#define OFF_AHI 0
#define OFF_ALO A_WORDS
#define OFF_BHI (2 * A_WORDS)
#define OFF_BLO (2 * A_WORDS + B_WORDS)
#define TSMEM_M ((2 * A_WORDS + 2 * B_WORDS) * 4)   // 104448
#define BR_WORDS (64 * ASTR)
#define OFF_BHI_R (2 * A_WORDS)
#define OFF_BLO_R (2 * A_WORDS + BR_WORDS)
#define TSMEM_R ((2 * A_WORDS + 2 * BR_WORDS) * 4)  // 69632

__device__ __forceinline__ void split2(float x, float y, uint32_t& h, uint32_t& l) {
    __nv_bfloat162 hb = __floats2bfloat162_rn(x, y);
    float2 hf = __bfloat1622float2(hb);
    __nv_bfloat162 lb = __floats2bfloat162_rn(x - hf.x, y - hf.y);
    h = *(uint32_t*)&hb;
    l = *(uint32_t*)&lb;
}

template<int NT>
__device__ __forceinline__ void mma_core_t(const uint32_t* __restrict__ sm,
                                           int mw, int nwbase, int g, int tg,
                                           float acc[NT][4], int offBhi, int offBlo) {
    const uint32_t* Ahi = sm + OFF_AHI;
    const uint32_t* Alo = sm + OFF_ALO;
    const uint32_t* Bhi = sm + offBhi;
    const uint32_t* Blo = sm + offBlo;
    int ra0 = (mw * 16 + g) * ASTR;
    int ra1 = ra0 + 8 * ASTR;
    #pragma unroll
    for (int ks = 0; ks < 8; ks++) {
        int c = ks * 8 + tg;
        uint32_t ah[4], al[4];
        ah[0] = Ahi[ra0 + c];     ah[1] = Ahi[ra1 + c];
        ah[2] = Ahi[ra0 + c + 4]; ah[3] = Ahi[ra1 + c + 4];
        al[0] = Alo[ra0 + c];     al[1] = Alo[ra1 + c];
        al[2] = Alo[ra0 + c + 4]; al[3] = Alo[ra1 + c + 4];
        #pragma unroll
        for (int t = 0; t < NT; t++) {
            int rb = (nwbase + t * 8 + g) * ASTR;
            uint32_t bh0 = Bhi[rb + c], bh1 = Bhi[rb + c + 4];
            uint32_t bl0 = Blo[rb + c], bl1 = Blo[rb + c + 4];
            mma16816(acc[t], ah, bh0, bh1);
            mma16816(acc[t], ah, bl0, bl1);
            mma16816(acc[t], al, bh0, bh1);
        }
    }
}

__device__ __forceinline__ void load_A(uint32_t* sm, const float* __restrict__ X,
                                       int sx, int c0, int r0, int M, int tid) {
    uint32_t* Ahi = sm + OFF_AHI;
    uint32_t* Alo = sm + OFF_ALO;
    #pragma unroll
    for (int j = 0; j < 8; j++) {
        int f = tid + j * 256;
        int row = f >> 5, q = f & 31;
        float4 v = make_float4(0.f, 0.f, 0.f, 0.f);
        int gr = r0 + row;
        if (gr < M) v = *(const float4*)(X + (long long)gr * sx + c0 + q * 4);
        uint32_t h0, l0, h1, l1;
        split2(v.x, v.y, h0, l0);
        split2(v.z, v.w, h1, l1);
        int w = row * ASTR + q * 2;
        *(uint2*)(Ahi + w) = make_uint2(h0, h1);
        *(uint2*)(Alo + w) = make_uint2(l0, l1);
    }
}

__device__ __forceinline__ void load_B(uint32_t* sm, const __nv_bfloat16* __restrict__ Whi,
                                       const __nv_bfloat16* __restrict__ Wlo, int tid) {
    uint32_t* Bhi = sm + OFF_BHI;
    uint32_t* Blo = sm + OFF_BLO;
    const uint4* s1 = (const uint4*)Whi;
    const uint4* s2 = (const uint4*)Wlo;
    #pragma unroll
    for (int j = 0; j < 8; j++) {
        int i = tid + j * 256;
        int row = i >> 4, cq = (i & 15) * 4;
        *(uint4*)(Bhi + row * ASTR + cq) = s1[i];
        *(uint4*)(Blo + row * ASTR + cq) = s2[i];
    }
}

__device__ __forceinline__ void load_B_r(uint32_t* sm, const __nv_bfloat16* __restrict__ Whi,
                                         const __nv_bfloat16* __restrict__ Wlo,
                                         int chunk, int tid) {
    uint32_t* Bhi = sm + OFF_BHI_R;
    uint32_t* Blo = sm + OFF_BLO_R;
    const uint4* s1 = (const uint4*)Whi;
    const uint4* s2 = (const uint4*)Wlo;
    #pragma unroll
    for (int j = 0; j < 4; j++) {
        int i = tid + j * 256;
        int row = i >> 4, q = i & 15;
        int si = row * 64 + chunk * 16 + q;
        *(uint4*)(Bhi + row * ASTR + q * 4) = s1[si];
        *(uint4*)(Blo + row * ASTR + q * 4) = s2[si];
    }
}

// ---------------- weight prep ----------------
__global__ void prep_w(const float* __restrict__ Wn1, const float* __restrict__ Wn2,
                       const float* __restrict__ Wn3,
                       __nv_bfloat16* __restrict__ Hi, __nv_bfloat16* __restrict__ Lo) {
    int m = blockIdx.x;
    const float* src = (m < 3 ? Wn1 : (m < 6 ? Wn2 : Wn3)) + (long long)(m % 3) * DIM * DIM;
    __nv_bfloat16* dh = Hi + (long long)m * DIM * DIM;
    __nv_bfloat16* dl = Lo + (long long)m * DIM * DIM;
    int idx0 = blockIdx.y * 1024;
    for (int i = 0; i < 8; i++) {
        int idx = idx0 + i * 128 + threadIdx.x;
        int k = idx >> 7, n = idx & 127;
        float v = src[idx];
        __nv_bfloat16 h = __float2bfloat16(v);
        __nv_bfloat16 l = __float2bfloat16(v - __bfloat162float(h));
        dh[n * DIM + k] = h;
        dl[n * DIM + k] = l;
    }
}
__global__ void prep_r(const float* __restrict__ Wr1,
                       __nv_bfloat16* __restrict__ Hi, __nv_bfloat16* __restrict__ Lo) {
    int idx = blockIdx.x * 1024 + threadIdx.x;
    for (int i = 0; i < 8; i++) {
        int f = idx + i * 128;
        int k = f >> 6, n = f & 63;
        float v = Wr1[f];
        __nv_bfloat16 h = __float2bfloat16(v);
        __nv_bfloat16 l = __float2bfloat16(v - __bfloat162float(h));
        Hi[n * 512 + k] = h;
        Lo[n * 512 + k] = l;
    }
}

// ---------------- fold W_c2 @ W_c3 -> bf16 hi/lo B-layout ----------------
__global__ void fold_kernel(const float* __restrict__ Wc2, const float* __restrict__ bc2,
                            const float* __restrict__ Wc3, const float* __restrict__ bc3) {
    int k = blockIdx.x, l = blockIdx.y, j = threadIdx.x;
    __shared__ float row[DIM];
    row[j] = Wc2[((long long)l * DIM + k) * DIM + j];
    __syncthreads();
    float acc = 0.0f;
    #pragma unroll 4
    for (int m = 0; m < DIM; m++)
        acc += row[m] * Wc3[((long long)l * DIM + m) * DIM + j];
    __nv_bfloat16 h = __float2bfloat16(acc);
    __nv_bfloat16 lo = __float2bfloat16(acc - __bfloat162float(h));
    g_WfHi[(long long)l * DIM * DIM + j * DIM + k] = h;   // B layout [n=j][k]
    g_WfLo[(long long)l * DIM * DIM + j * DIM + k] = lo;
    if (k == 0) {
        float bacc = bc3[l * DIM + j];
        #pragma unroll 4
        for (int m = 0; m < DIM; m++)
            bacc += bc2[l * DIM + m] * Wc3[((long long)l * DIM + m) * DIM + j];
        g_bf[l * DIM + j] = bacc;
    }
}

// ---------------- spu table: softplus(rbf @ Wc1 + bc1) ----------------
__global__ void spu_kernel(const float* __restrict__ Wc1, const float* __restrict__ bc1) {
    __shared__ float wc[30 * DIM];
    __shared__ float bc[DIM];
    __shared__ float rbf[32];
    int l = blockIdx.y, tid = threadIdx.x;
    const float* W = Wc1 + (long long)l * 30 * DIM;
    for (int i = tid; i < 30 * DIM; i += 128) wc[i] = W[i];
    bc[tid] = bc1[l * DIM + tid];
    __syncthreads();
    for (int gi = 0; gi < 8; gi++) {
        int g = blockIdx.x * 8 + gi;
        if (tid < 30) {
            float dg = (float)g * (10.0f / (float)(GRID_G - 1));
            float c = (float)tid * (10.0f / 29.0f);
            float dd = dg - c;
            rbf[tid] = expf(-dd * dd * 2.9f);
        }
        __syncthreads();
        float u = bc[tid];
        #pragma unroll
        for (int r = 0; r < 30; r++)
            u += rbf[r] * wc[r * DIM + tid];
        g_Spu[((long long)l * GRID_G + g) * DIM + tid] = sp_half(u);
        __syncthreads();
    }
}

// ---------------- table GEMM: Tab = Spu @ Wf + bf (HMMA) ----------------
__global__ __launch_bounds__(256) void gemm_tab() {
    extern __shared__ uint32_t sm[];
    int tid = threadIdx.x, wid = tid >> 5, lane = tid & 31;
    int mw = wid & 3, nw = wid >> 2;
    int g = lane >> 2, tg = lane & 3;
    int l = blockIdx.y;
    int r0 = blockIdx.x * 64;
    const float* X = g_Spu + (long long)l * GRID_G * DIM;
    float* Y = g_Tab + (long long)l * GRID_G * DIM;

    load_A(sm, X, DIM, 0, r0, GRID_G, tid);
    load_B(sm, g_WfHi + (long long)l * DIM * DIM, g_WfLo + (long long)l * DIM * DIM, tid);
    __syncthreads();

    float acc[8][4];
    #pragma unroll
    for (int t = 0; t < 8; t++)
        #pragma unroll
        for (int i = 0; i < 4; i++) acc[t][i] = 0.0f;
    mma_core_t<8>(sm, mw, nw * 64, g, tg, acc, OFF_BHI, OFF_BLO);

    int row0 = r0 + mw * 16 + g, row1 = row0 + 8;
    #pragma unroll
    for (int t = 0; t < 8; t++) {
        int col = nw * 64 + t * 8 + tg * 2;
        float b0 = g_bf[l * DIM + col], b1 = g_bf[l * DIM + col + 1];
        *(float2*)(Y + (long long)row0 * DIM + col) = make_float2(acc[t][0] + b0, acc[t][1] + b1);
        *(float2*)(Y + (long long)row1 * DIM + col) = make_float2(acc[t][2] + b0, acc[t][3] + b1);
    }
}

// ---------------- pack: (v, v_next - v) as half2 ----------------
__global__ void pack_kernel() {
    int g = blockIdx.x, l = blockIdx.y, j = threadIdx.x;
    float v = g_Tab[((long long)l * GRID_G + g) * DIM + j];
    float nx = (g < GRID_G - 1) ? g_Tab[((long long)l * GRID_G + g + 1) * DIM + j] : v;
    __half2* row = (__half2*)(g_TabP + ((long long)l * GRID_G + g) * TAB_STRIDE);
    row[j] = __floats2half2_rn(v, nx - v);
}

// ---------------- embedding ----------------
__global__ void embed_kernel(const int* __restrict__ at, const float* __restrict__ emb) {
    int i = blockIdx.x * blockDim.x + threadIdx.x;
    if (i >= N_NODES * 32) return;
    int n = i >> 5, q = i & 31;
    float4 v = __ldg((const float4*)(emb + (long long)at[n] * DIM) + q);
    *(float4*)(g_H + (long long)n * 512 + q * 4) = v;
}
__global__ void zero_out_kernel(float* out) { out[threadIdx.x] = 0.0f; }

// ---------------- CSR build ----------------
__global__ void zero_cnt() {
    int i = blockIdx.x * 256 + threadIdx.x;
    if (i < N_NODES) g_cnt[i] = 0;
}
__global__ void hist_kernel(const int* __restrict__ dst) {
    int e = blockIdx.x * 256 + threadIdx.x;
    if (e < N_EDGES) atomicAdd(&g_cnt[dst[e]], 1);
}
__global__ void scan1() {
    __shared__ int sh[256];
    int tid = threadIdx.x;
    int n = blockIdx.x * 256 + tid;
    int v = (n < N_NODES) ? g_cnt[n] : 0;
    sh[tid] = v; __syncthreads();
    #pragma unroll
    for (int o = 1; o < 256; o <<= 1) {
        int t = (tid >= o) ? sh[tid - o] : 0;
        __syncthreads();
        sh[tid] += t;
        __syncthreads();
    }
    if (n < N_NODES) g_scan[n] = sh[tid] - v;
    if (tid == 255) g_bsum[blockIdx.x] = sh[tid];
}
__global__ void scan2() {
    __shared__ int sh[256];
    int tid = threadIdx.x;
    int v = (tid < NB_SCAN) ? g_bsum[tid] : 0;
    sh[tid] = v; __syncthreads();
    #pragma unroll
    for (int o = 1; o < 256; o <<= 1) {
        int t = (tid >= o) ? sh[tid - o] : 0;
        __syncthreads();
        sh[tid] += t;
        __syncthreads();
    }
    if (tid < NB_SCAN) g_boff[tid] = sh[tid] - v;
}
__global__ void scan3() {
    int n = blockIdx.x * 256 + threadIdx.x;
    if (n < N_NODES) {
        int o = g_scan[n] + g_boff[blockIdx.x];
        g_off[n] = o;
        g_cur[n] = o;
    }
    if (n == 0) g_off[N_NODES] = N_EDGES;
}
__global__ void scatter_kernel(const int* __restrict__ src, const int* __restrict__ dst,
                               const float* __restrict__ dist) {
    int e = blockIdx.x * 256 + threadIdx.x;
    if (e >= N_EDGES) return;
    int d = __ldg(dst + e);
    int pos = atomicAdd(&g_cur[d], 1);
    float di = __ldg(dist + e);
    float t = di * ((float)(GRID_G - 1) / 10.0f);
    int gg = (int)t;
    gg = gg < GRID_G - 2 ? gg : GRID_G - 2;
    float f = t - (float)gg;
    unsigned int fp = (unsigned int)__half_as_ushort(__float2half_rn(f));
    g_rec[pos] = make_uint2((unsigned)__ldg(src + e), (unsigned)gg | (fp << 16));
}

// ---------------- edge gather: Node[n] = sum_in lerp(tab) * hn[src] ----------------
__global__ __launch_bounds__(256) void edge_gather(
    const unsigned char* __restrict__ tabp,
    const __half* __restrict__ hn,
    float* __restrict__ node)
{
    int wid = threadIdx.x >> 5, lane = threadIdx.x & 31;
    int n = blockIdx.x * 8 + wid;
    if (n >= N_NODES) return;
    int beg = __ldg(&g_off[n]);
    int end = __ldg(&g_off[n + 1]);
    float4 acc = make_float4(0.f, 0.f, 0.f, 0.f);
    uint2 rc;
    if (beg < end) rc = __ldg(&g_rec[beg]);
    for (int i = beg; i < end; i++) {
        uint2 r = rc;
        if (i + 1 < end) rc = __ldg(&g_rec[i + 1]);
        int s = (int)r.x;
        int gg = (int)(r.y & 0xffffu);
        float f = __half2float(__ushort_as_half((unsigned short)(r.y >> 16)));
        uint4 tv = __ldg((const uint4*)(tabp + (long long)gg * TAB_STRIDE) + lane);
        uint2 hv = __ldg((const uint2*)(hn + (long long)s * DIM) + lane);
        float2 p0 = __half22float2(*(__half2*)&tv.x);
        float2 p1 = __half22float2(*(__half2*)&tv.y);
        float2 p2 = __half22float2(*(__half2*)&tv.z);
        float2 p3 = __half22float2(*(__half2*)&tv.w);
        float2 h01 = __half22float2(*(__half2*)&hv.x);
        float2 h23 = __half22float2(*(__half2*)&hv.y);
        acc.x += fmaf(f, p0.y, p0.x) * h01.x;
        acc.y += fmaf(f, p1.y, p1.x) * h01.y;
        acc.z += fmaf(f, p2.y, p2.x) * h23.x;
        acc.w += fmaf(f, p3.y, p3.x) * h23.y;
    }
    *(float4*)(node + (long long)n * DIM + lane * 4) = acc;
}

// ---------------- HMMA GEMM1: Hn2 = fp16(X @ W + b + 1) ----------------
__global__ __launch_bounds__(256) void gemm_m1(
    const float* __restrict__ X, int sx,
    const __nv_bfloat16* __restrict__ Whi, const __nv_bfloat16* __restrict__ Wlo,
    const float* __restrict__ bias, float bextra,
    __half* __restrict__ Hn2, int M)
{
    extern __shared__ uint32_t sm[];
    int tid = threadIdx.x, wid = tid >> 5, lane = tid & 31;
    int mw = wid & 3, nw = wid >> 2;
    int g = lane >> 2, tg = lane & 3;
    int r0 = blockIdx.x * 64;

    load_A(sm, X, sx, 0, r0, M, tid);
    load_B(sm, Whi, Wlo, tid);
    __syncthreads();

    float acc[8][4];
    #pragma unroll
    for (int t = 0; t < 8; t++)
        #pragma unroll
        for (int i = 0; i < 4; i++) acc[t][i] = 0.0f;
    mma_core_t<8>(sm, mw, nw * 64, g, tg, acc, OFF_BHI, OFF_BLO);

    int row0 = r0 + mw * 16 + g, row1 = row0 + 8;
    #pragma unroll
    for (int t = 0; t < 8; t++) {
        int col = nw * 64 + t * 8 + tg * 2;
        float b0 = __ldg(bias + col) + bextra;
        float b1 = __ldg(bias + col + 1) + bextra;
        if (row0 < M)
            *(__half2*)(Hn2 + (long long)row0 * DIM + col) =
                __floats2half2_rn(acc[t][0] + b0, acc[t][1] + b1);
        if (row1 < M)
            *(__half2*)(Hn2 + (long long)row1 * DIM + col) =
                __floats2half2_rn(acc[t][2] + b0, acc[t][3] + b1);
    }
}

// ---------------- fused: H' = H + sp(X@W2+b2)@W3+b3 ; optionally next Hn ----------------
__global__ __launch_bounds__(256) void gemm_m23(
    const float* __restrict__ X, int sx,
    const __nv_bfloat16* __restrict__ W2hi, const __nv_bfloat16* __restrict__ W2lo,
    const float* __restrict__ b2,
    const __nv_bfloat16* __restrict__ W3hi, const __nv_bfloat16* __restrict__ W3lo,
    const float* __restrict__ b3,
    const float* __restrict__ Res, int sr,
    float* __restrict__ Y, int sy,
    const __nv_bfloat16* __restrict__ W1hi, const __nv_bfloat16* __restrict__ W1lo,
    const float* __restrict__ b1n,
    __half* __restrict__ Hn2,
    int has_next, int M)
{
    extern __shared__ uint32_t sm[];
    uint32_t* Ahi = sm + OFF_AHI;
    uint32_t* Alo = sm + OFF_ALO;
    int tid = threadIdx.x, wid = tid >> 5, lane = tid & 31;
    int mw = wid & 3, nw = wid >> 2;
    int g = lane >> 2, tg = lane & 3;
    int r0 = blockIdx.x * 64;
    int rl0 = mw * 16 + g, rl1 = rl0 + 8;
    int row0 = r0 + rl0, row1 = row0 + 8;

    load_A(sm, X, sx, 0, r0, M, tid);
    load_B(sm, W2hi, W2lo, tid);
    __syncthreads();

    float acc[8][4];
    #pragma unroll
    for (int t = 0; t < 8; t++)
        #pragma unroll
        for (int i = 0; i < 4; i++) acc[t][i] = 0.0f;
    mma_core_t<8>(sm, mw, nw * 64, g, tg, acc, OFF_BHI, OFF_BLO);

    #pragma unroll
    for (int t = 0; t < 8; t++) {
        int col = nw * 64 + t * 8 + tg * 2;
        float b0 = __ldg(b2 + col), b1 = __ldg(b2 + col + 1);
        float t0 = sp_half(acc[t][0] + b0), t1 = sp_half(acc[t][1] + b1);
        float t2 = sp_half(acc[t][2] + b0), t3 = sp_half(acc[t][3] + b1);
        uint32_t h, l;
        int w0 = rl0 * ASTR + (col >> 1);
        int w1 = rl1 * ASTR + (col >> 1);
        split2(t0, t1, h, l); Ahi[w0] = h; Alo[w0] = l;
        split2(t2, t3, h, l); Ahi[w1] = h; Alo[w1] = l;
    }
    __syncthreads();
    load_B(sm, W3hi, W3lo, tid);
    __syncthreads();

    #pragma unroll
    for (int t = 0; t < 8; t++)
        #pragma unroll
        for (int i = 0; i < 4; i++) acc[t][i] = 0.0f;
    mma_core_t<8>(sm, mw, nw * 64, g, tg, acc, OFF_BHI, OFF_BLO);

    #pragma unroll
    for (int t = 0; t < 8; t++) {
        int col = nw * 64 + t * 8 + tg * 2;
        float b0 = __ldg(b3 + col), b1 = __ldg(b3 + col + 1);
        float y0 = acc[t][0] + b0, y1 = acc[t][1] + b1;
        float y2 = acc[t][2] + b0, y3 = acc[t][3] + b1;
        if (row0 < M) {
            float2 r = *(const float2*)(Res + (long long)row0 * sr + col);
            y0 += r.x; y1 += r.y;
            *(float2*)(Y + (long long)row0 * sy + col) = make_float2(y0, y1);
        }
        if (row1 < M) {
            float2 r = *(const float2*)(Res + (long long)row1 * sr + col);
            y2 += r.x; y3 += r.y;
            *(float2*)(Y + (long long)row1 * sy + col) = make_float2(y2, y3);
        }
        if (has_next) {
            uint32_t h, l;
            int w0 = rl0 * ASTR + (col >> 1);
            int w1 = rl1 * ASTR + (col >> 1);
            split2(y0, y1, h, l); Ahi[w0] = h; Alo[w0] = l;
            split2(y2, y3, h, l); Ahi[w1] = h; Alo[w1] = l;
        }
    }
    if (!has_next) return;

    __syncthreads();
    load_B(sm, W1hi, W1lo, tid);
    __syncthreads();

    #pragma unroll
    for (int t = 0; t < 8; t++)
        #pragma unroll
        for (int i = 0; i < 4; i++) acc[t][i] = 0.0f;
    mma_core_t<8>(sm, mw, nw * 64, g, tg, acc, OFF_BHI, OFF_BLO);

    #pragma unroll
    for (int t = 0; t < 8; t++) {
        int col = nw * 64 + t * 8 + tg * 2;
        float b0 = __ldg(b1n + col) + 1.0f;
        float b1 = __ldg(b1n + col + 1) + 1.0f;
        if (row0 < M)
            *(__half2*)(Hn2 + (long long)row0 * DIM + col) =
                __floats2half2_rn(acc[t][0] + b0, acc[t][1] + b1);
        if (row1 < M)
            *(__half2*)(Hn2 + (long long)row1 * DIM + col) =
                __floats2half2_rn(acc[t][2] + b0, acc[t][3] + b1);
    }
}

// ---------------- fused readout ----------------
__global__ __launch_bounds__(256) void gemm_r(
    const float* __restrict__ X,
    const __nv_bfloat16* __restrict__ Whi, const __nv_bfloat16* __restrict__ Wlo,
    const float* __restrict__ br1, const float* __restrict__ Wr2,
    const float* __restrict__ br2,
    const int* __restrict__ gid, float* __restrict__ out, int M)
{
    extern __shared__ uint32_t sm[];
    __shared__ float res[64];
    int tid = threadIdx.x, wid = tid >> 5, lane = tid & 31;
    int mw = wid & 3, nw = wid >> 2;
    int g = lane >> 2, tg = lane & 3;
    int r0 = blockIdx.x * 64;
    if (tid < 64) res[tid] = 0.0f;

    float acc[4][4];
    #pragma unroll
    for (int t = 0; t < 4; t++)
        #pragma unroll
        for (int i = 0; i < 4; i++) acc[t][i] = 0.0f;

    for (int ch = 0; ch < 4; ch++) {
        load_A(sm, X, 512, ch * 128, r0, M, tid);
        load_B_r(sm, g_WrHi, g_WrLo, ch, tid);
        __syncthreads();
        mma_core_t<4>(sm, mw, nw * 32, g, tg, acc, OFF_BHI_R, OFF_BLO_R);
        __syncthreads();
    }

    float p0 = 0.0f, p1 = 0.0f;
    #pragma unroll
    for (int t = 0; t < 4; t++) {
        int col = nw * 32 + t * 8 + tg * 2;
        float b0 = __ldg(br1 + col), b1 = __ldg(br1 + col + 1);
        float w0 = __ldg(Wr2 + col), w1 = __ldg(Wr2 + col + 1);
        p0 += sp_one(acc[t][0] + b0) * w0 + sp_one(acc[t][1] + b1) * w1;
        p1 += sp_one(acc[t][2] + b0) * w0 + sp_one(acc[t][3] + b1) * w1;
    }
    p0 += __shfl_down_sync(0xffffffff, p0, 1);
    p0 += __shfl_down_sync(0xffffffff, p0, 2);
    p1 += __shfl_down_sync(0xffffffff, p1, 1);
    p1 += __shfl_down_sync(0xffffffff, p1, 2);
    if (tg == 0) {
        atomicAdd(&res[mw * 16 + g], p0);
        atomicAdd(&res[mw * 16 + g + 8], p1);
    }
    __syncthreads();
    if (tid < 64) {
        int row = r0 + tid;
        if (row < M) atomicAdd(out + __ldg(gid + row), res[tid] + __ldg(br2));
    }
}

// ---------------- launch ----------------
extern "C" void kernel_launch(void* const* d_in, const int* in_sizes, int n_in,
                              void* d_out, int out_size) {
    const int*   atom_type = (const int*)d_in[0];
    const int*   src  = (const int*)d_in[1];
    const int*   dst  = (const int*)d_in[2];
    const int*   gid  = (const int*)d_in[3];
    const float* dist = (const float*)d_in[4];
    const float* emb  = (const float*)d_in[5];
    const float* W_n1 = (const float*)d_in[6];  const float* b_n1 = (const float*)d_in[7];
    const float* W_c1 = (const float*)d_in[8];  const float* b_c1 = (const float*)d_in[9];
    const float* W_c2 = (const float*)d_in[10]; const float* b_c2 = (const float*)d_in[11];
    const float* W_c3 = (const float*)d_in[12]; const float* b_c3 = (const float*)d_in[13];
    const float* W_n2 = (const float*)d_in[14]; const float* b_n2 = (const float*)d_in[15];
    const float* W_n3 = (const float*)d_in[16]; const float* b_n3 = (const float*)d_in[17];
    const float* W_r1 = (const float*)d_in[18]; const float* b_r1 = (const float*)d_in[19];
    const float* W_r2 = (const float*)d_in[20]; const float* b_r2 = (const float*)d_in[21];
    float* out = (float*)d_out;

    float *H, *Node;
    __half* Hn2;
    unsigned char* TabP;
    __nv_bfloat16 *WbHi, *WbLo, *WrHi, *WrLo;
    cudaGetSymbolAddress((void**)&H,    g_H);
    cudaGetSymbolAddress((void**)&Hn2,  g_Hn2);
    cudaGetSymbolAddress((void**)&Node, g_Node);
    cudaGetSymbolAddress((void**)&TabP, g_TabP);
    cudaGetSymbolAddress((void**)&WbHi, g_WbHi);
    cudaGetSymbolAddress((void**)&WbLo, g_WbLo);
    cudaGetSymbolAddress((void**)&WrHi, g_WrHi);
    cudaGetSymbolAddress((void**)&WrLo, g_WrLo);

    cudaFuncSetAttribute(gemm_m1,  cudaFuncAttributeMaxDynamicSharedMemorySize, TSMEM_M);
    cudaFuncSetAttribute(gemm_m23, cudaFuncAttributeMaxDynamicSharedMemorySize, TSMEM_M);
    cudaFuncSetAttribute(gemm_tab, cudaFuncAttributeMaxDynamicSharedMemorySize, TSMEM_M);
    cudaFuncSetAttribute(gemm_r,   cudaFuncAttributeMaxDynamicSharedMemorySize, TSMEM_R);

    const int M = N_NODES;
    const int GB64 = (M + 63) / 64;     // 938
    const int EB = (N_EDGES + 255) / 256;

    // precompute: tables (HMMA path) + weights + embedding + CSR
    fold_kernel<<<dim3(DIM, N_LAYERS), DIM>>>(W_c2, b_c2, W_c3, b_c3);
    spu_kernel<<<dim3(GRID_G / 8, N_LAYERS), 128>>>(W_c1, b_c1);
    gemm_tab<<<dim3(GRID_G / 64, N_LAYERS), 256, TSMEM_M>>>();
    pack_kernel<<<dim3(GRID_G, N_LAYERS), DIM>>>();
    prep_w<<<dim3(9, 16), 128>>>(W_n1, W_n2, W_n3, WbHi, WbLo);
    prep_r<<<32, 128>>>(W_r1, WrHi, WrLo);
    embed_kernel<<<(N_NODES * 32 + 255) / 256, 256>>>(atom_type, emb);

    zero_cnt<<<NB_SCAN, 256>>>();
    hist_kernel<<<EB, 256>>>(dst);
    scan1<<<NB_SCAN, 256>>>();
    scan2<<<1, 256>>>();
    scan3<<<NB_SCAN, 256>>>();
    scatter_kernel<<<EB, 256>>>(src, dst, dist);

    // layer 0 h_new
    gemm_m1<<<GB64, 256, TSMEM_M>>>(H, 512, WbHi, WbLo, b_n1, 1.0f, Hn2, M);

    for (int l = 0; l < N_LAYERS; l++) {
        edge_gather<<<(N_NODES + 7) / 8, 256>>>(
            TabP + (long long)l * GRID_G * TAB_STRIDE, Hn2, Node);
        int nl = l + 1;
        int has_next = (nl < N_LAYERS);
        gemm_m23<<<GB64, 256, TSMEM_M>>>(
            Node, 128,
            WbHi + (long long)(3 + l) * DIM * DIM, WbLo + (long long)(3 + l) * DIM * DIM,
            b_n2 + l * 128,
            WbHi + (long long)(6 + l) * DIM * DIM, WbLo + (long long)(6 + l) * DIM * DIM,
            b_n3 + l * 128,
            H + l * 128, 512, H + nl * 128, 512,
            WbHi + (long long)(has_next ? nl : 0) * DIM * DIM,
            WbLo + (long long)(has_next ? nl : 0) * DIM * DIM,
            b_n1 + (has_next ? nl : 0) * 128,
            Hn2, has_next, M);
    }

    zero_out_kernel<<<1, N_GRAPH>>>(out);
    gemm_r<<<GB64, 256, TSMEM_R>>>(H, WrHi, WrLo, b_r1, W_r2, b_r2, gid, out, M);
}

// round 7
// speedup vs baseline: 2.0064x; 1.0604x over previous
#include <cuda_runtime.h>
#include <cuda_bf16.h>
#include <cuda_fp16.h>
#include <math.h>
#include <stdint.h>

#define N_NODES 60000
#define N_EDGES 600000
#define N_GRAPH 512
#define DIM 128
#define N_LAYERS 3
#define GRID_G 8192
#define NB_SCAN 235      // ceil(60000/256)

// ---------------- device scratch ----------------
__device__ float g_H[(long long)N_NODES * 512];
__device__ __half g_Hn2[(long long)N_NODES * DIM];
__device__ float g_Node[(long long)N_NODES * DIM];
__device__ float g_bf[N_LAYERS * DIM];
__device__ float g_Spu[(long long)N_LAYERS * GRID_G * DIM];
__device__ __align__(256) __half g_TabP[(long long)N_LAYERS * GRID_G * DIM];  // fp16 values
__device__ __align__(256) __nv_bfloat16 g_WbHi[9 * DIM * DIM];
__device__ __align__(256) __nv_bfloat16 g_WbLo[9 * DIM * DIM];
__device__ __align__(256) __nv_bfloat16 g_WfHi[N_LAYERS * DIM * DIM];
__device__ __align__(256) __nv_bfloat16 g_WfLo[N_LAYERS * DIM * DIM];
__device__ __align__(256) __nv_bfloat16 g_WrHi[64 * 512];
__device__ __align__(256) __nv_bfloat16 g_WrLo[64 * 512];
// CSR build
__device__ int g_cnt[N_NODES];
__device__ int g_scan[N_NODES];
__device__ int g_bsum[NB_SCAN];
__device__ int g_boff[NB_SCAN];
__device__ int g_off[N_NODES + 1];
__device__ int g_cur[N_NODES];
__device__ unsigned g_recP[N_EDGES];   // src (16b) | grid idx (13b) << 16

// ---------------- scalar helpers ----------------
__device__ __forceinline__ float sp_half(float x) {
    float bx = 0.5f * x;
    return bx > 14.0f ? x : 2.0f * log1pf(expf(bx));
}
__device__ __forceinline__ float sp_one(float x) {
    return x > 20.0f ? x : log1pf(expf(x));
}

// ---------------- HMMA helpers ----------------
__device__ __forceinline__ void mma16816(float* d, const uint32_t* a,
                                         uint32_t b0, uint32_t b1) {
    asm volatile(
        "mma.sync.aligned.m16n8k16.row.col.f32.bf16.bf16.f32 "
        "{%0,%1,%2,%3}, {%4,%5,%6,%7}, {%8,%9}, {%0,%1,%2,%3};"
        : "+f"(d[0]), "+f"(d[1]), "+f"(d[2]), "+f"(d[3])
        : "r"(a[0]), "r"(a[1]), "r"(a[2]), "r"(a[3]), "r"(b0), "r"(b1));
}

#define ASTR 68
#define A_WORDS (64 * ASTR)
#define B_WORDS (128 * ASTR)
#define OFF_AHI 0
#define OFF_ALO A_WORDS
#define OFF_BHI (2 * A_WORDS)
#define OFF_BLO (2 * A_WORDS + B_WORDS)
#define TSMEM_M ((2 * A_WORDS + 2 * B_WORDS) * 4)   // 104448
#define BR_WORDS (64 * ASTR)
#define OFF_BHI_R (2 * A_WORDS)
#define OFF_BLO_R (2 * A_WORDS + BR_WORDS)
#define TSMEM_R ((2 * A_WORDS + 2 * BR_WORDS) * 4)  // 69632

__device__ __forceinline__ void split2(float x, float y, uint32_t& h, uint32_t& l) {
    __nv_bfloat162 hb = __floats2bfloat162_rn(x, y);
    float2 hf = __bfloat1622float2(hb);
    __nv_bfloat162 lb = __floats2bfloat162_rn(x - hf.x, y - hf.y);
    h = *(uint32_t*)&hb;
    l = *(uint32_t*)&lb;
}

template<int NT>
__device__ __forceinline__ void mma_core_t(const uint32_t* __restrict__ sm,
                                           int mw, int nwbase, int g, int tg,
                                           float acc[NT][4], int offBhi, int offBlo) {
    const uint32_t* Ahi = sm + OFF_AHI;
    const uint32_t* Alo = sm + OFF_ALO;
    const uint32_t* Bhi = sm + offBhi;
    const uint32_t* Blo = sm + offBlo;
    int ra0 = (mw * 16 + g) * ASTR;
    int ra1 = ra0 + 8 * ASTR;
    #pragma unroll
    for (int ks = 0; ks < 8; ks++) {
        int c = ks * 8 + tg;
        uint32_t ah[4], al[4];
        ah[0] = Ahi[ra0 + c];     ah[1] = Ahi[ra1 + c];
        ah[2] = Ahi[ra0 + c + 4]; ah[3] = Ahi[ra1 + c + 4];
        al[0] = Alo[ra0 + c];     al[1] = Alo[ra1 + c];
        al[2] = Alo[ra0 + c + 4]; al[3] = Alo[ra1 + c + 4];
        #pragma unroll
        for (int t = 0; t < NT; t++) {
            int rb = (nwbase + t * 8 + g) * ASTR;
            uint32_t bh0 = Bhi[rb + c], bh1 = Bhi[rb + c + 4];
            uint32_t bl0 = Blo[rb + c], bl1 = Blo[rb + c + 4];
            mma16816(acc[t], ah, bh0, bh1);
            mma16816(acc[t], ah, bl0, bl1);
            mma16816(acc[t], al, bh0, bh1);
        }
    }
}

__device__ __forceinline__ void load_A(uint32_t* sm, const float* __restrict__ X,
                                       int sx, int c0, int r0, int M, int tid) {
    uint32_t* Ahi = sm + OFF_AHI;
    uint32_t* Alo = sm + OFF_ALO;
    #pragma unroll
    for (int j = 0; j < 8; j++) {
        int f = tid + j * 256;
        int row = f >> 5, q = f & 31;
        float4 v = make_float4(0.f, 0.f, 0.f, 0.f);
        int gr = r0 + row;
        if (gr < M) v = *(const float4*)(X + (long long)gr * sx + c0 + q * 4);
        uint32_t h0, l0, h1, l1;
        split2(v.x, v.y, h0, l0);
        split2(v.z, v.w, h1, l1);
        int w = row * ASTR + q * 2;
        *(uint2*)(Ahi + w) = make_uint2(h0, h1);
        *(uint2*)(Alo + w) = make_uint2(l0, l1);
    }
}

__device__ __forceinline__ void load_B(uint32_t* sm, const __nv_bfloat16* __restrict__ Whi,
                                       const __nv_bfloat16* __restrict__ Wlo, int tid) {
    uint32_t* Bhi = sm + OFF_BHI;
    uint32_t* Blo = sm + OFF_BLO;
    const uint4* s1 = (const uint4*)Whi;
    const uint4* s2 = (const uint4*)Wlo;
    #pragma unroll
    for (int j = 0; j < 8; j++) {
        int i = tid + j * 256;
        int row = i >> 4, cq = (i & 15) * 4;
        *(uint4*)(Bhi + row * ASTR + cq) = s1[i];
        *(uint4*)(Blo + row * ASTR + cq) = s2[i];
    }
}

__device__ __forceinline__ void load_B_r(uint32_t* sm, const __nv_bfloat16* __restrict__ Whi,
                                         const __nv_bfloat16* __restrict__ Wlo,
                                         int chunk, int tid) {
    uint32_t* Bhi = sm + OFF_BHI_R;
    uint32_t* Blo = sm + OFF_BLO_R;
    const uint4* s1 = (const uint4*)Whi;
    const uint4* s2 = (const uint4*)Wlo;
    #pragma unroll
    for (int j = 0; j < 4; j++) {
        int i = tid + j * 256;
        int row = i >> 4, q = i & 15;
        int si = row * 64 + chunk * 16 + q;
        *(uint4*)(Bhi + row * ASTR + q * 4) = s1[si];
        *(uint4*)(Blo + row * ASTR + q * 4) = s2[si];
    }
}

// ---------------- weight prep ----------------
__global__ void prep_w(const float* __restrict__ Wn1, const float* __restrict__ Wn2,
                       const float* __restrict__ Wn3,
                       __nv_bfloat16* __restrict__ Hi, __nv_bfloat16* __restrict__ Lo) {
    int m = blockIdx.x;
    const float* src = (m < 3 ? Wn1 : (m < 6 ? Wn2 : Wn3)) + (long long)(m % 3) * DIM * DIM;
    __nv_bfloat16* dh = Hi + (long long)m * DIM * DIM;
    __nv_bfloat16* dl = Lo + (long long)m * DIM * DIM;
    int idx0 = blockIdx.y * 1024;
    for (int i = 0; i < 8; i++) {
        int idx = idx0 + i * 128 + threadIdx.x;
        int k = idx >> 7, n = idx & 127;
        float v = src[idx];
        __nv_bfloat16 h = __float2bfloat16(v);
        __nv_bfloat16 l = __float2bfloat16(v - __bfloat162float(h));
        dh[n * DIM + k] = h;
        dl[n * DIM + k] = l;
    }
}
__global__ void prep_r(const float* __restrict__ Wr1,
                       __nv_bfloat16* __restrict__ Hi, __nv_bfloat16* __restrict__ Lo) {
    int idx = blockIdx.x * 1024 + threadIdx.x;
    for (int i = 0; i < 8; i++) {
        int f = idx + i * 128;
        int k = f >> 6, n = f & 63;
        float v = Wr1[f];
        __nv_bfloat16 h = __float2bfloat16(v);
        __nv_bfloat16 l = __float2bfloat16(v - __bfloat162float(h));
        Hi[n * 512 + k] = h;
        Lo[n * 512 + k] = l;
    }
}

// ---------------- fold W_c2 @ W_c3 -> bf16 hi/lo B-layout ----------------
__global__ void fold_kernel(const float* __restrict__ Wc2, const float* __restrict__ bc2,
                            const float* __restrict__ Wc3, const float* __restrict__ bc3) {
    int k = blockIdx.x, l = blockIdx.y, j = threadIdx.x;
    __shared__ float row[DIM];
    row[j] = Wc2[((long long)l * DIM + k) * DIM + j];
    __syncthreads();
    float acc = 0.0f;
    #pragma unroll 4
    for (int m = 0; m < DIM; m++)
        acc += row[m] * Wc3[((long long)l * DIM + m) * DIM + j];
    __nv_bfloat16 h = __float2bfloat16(acc);
    __nv_bfloat16 lo = __float2bfloat16(acc - __bfloat162float(h));
    g_WfHi[(long long)l * DIM * DIM + j * DIM + k] = h;
    g_WfLo[(long long)l * DIM * DIM + j * DIM + k] = lo;
    if (k == 0) {
        float bacc = bc3[l * DIM + j];
        #pragma unroll 4
        for (int m = 0; m < DIM; m++)
            bacc += bc2[l * DIM + m] * Wc3[((long long)l * DIM + m) * DIM + j];
        g_bf[l * DIM + j] = bacc;
    }
}

// ---------------- spu table: softplus(rbf @ Wc1 + bc1) ----------------
__global__ void spu_kernel(const float* __restrict__ Wc1, const float* __restrict__ bc1) {
    __shared__ float wc[30 * DIM];
    __shared__ float bc[DIM];
    __shared__ float rbf[32];
    int l = blockIdx.y, tid = threadIdx.x;
    const float* W = Wc1 + (long long)l * 30 * DIM;
    for (int i = tid; i < 30 * DIM; i += 128) wc[i] = W[i];
    bc[tid] = bc1[l * DIM + tid];
    __syncthreads();
    for (int gi = 0; gi < 8; gi++) {
        int g = blockIdx.x * 8 + gi;
        if (tid < 30) {
            float dg = (float)g * (10.0f / (float)(GRID_G - 1));
            float c = (float)tid * (10.0f / 29.0f);
            float dd = dg - c;
            rbf[tid] = expf(-dd * dd * 2.9f);
        }
        __syncthreads();
        float u = bc[tid];
        #pragma unroll
        for (int r = 0; r < 30; r++)
            u += rbf[r] * wc[r * DIM + tid];
        g_Spu[((long long)l * GRID_G + g) * DIM + tid] = sp_half(u);
        __syncthreads();
    }
}

// ---------------- table GEMM: TabP(fp16) = Spu @ Wf + bf (HMMA) ----------------
__global__ __launch_bounds__(256) void gemm_tab() {
    extern __shared__ uint32_t sm[];
    int tid = threadIdx.x, wid = tid >> 5, lane = tid & 31;
    int mw = wid & 3, nw = wid >> 2;
    int g = lane >> 2, tg = lane & 3;
    int l = blockIdx.y;
    int r0 = blockIdx.x * 64;
    const float* X = g_Spu + (long long)l * GRID_G * DIM;
    __half* Y = g_TabP + (long long)l * GRID_G * DIM;

    load_A(sm, X, DIM, 0, r0, GRID_G, tid);
    load_B(sm, g_WfHi + (long long)l * DIM * DIM, g_WfLo + (long long)l * DIM * DIM, tid);
    __syncthreads();

    float acc[8][4];
    #pragma unroll
    for (int t = 0; t < 8; t++)
        #pragma unroll
        for (int i = 0; i < 4; i++) acc[t][i] = 0.0f;
    mma_core_t<8>(sm, mw, nw * 64, g, tg, acc, OFF_BHI, OFF_BLO);

    int row0 = r0 + mw * 16 + g, row1 = row0 + 8;
    #pragma unroll
    for (int t = 0; t < 8; t++) {
        int col = nw * 64 + t * 8 + tg * 2;
        float b0 = g_bf[l * DIM + col], b1 = g_bf[l * DIM + col + 1];
        *(__half2*)(Y + (long long)row0 * DIM + col) =
            __floats2half2_rn(acc[t][0] + b0, acc[t][1] + b1);
        *(__half2*)(Y + (long long)row1 * DIM + col) =
            __floats2half2_rn(acc[t][2] + b0, acc[t][3] + b1);
    }
}

// ---------------- embedding ----------------
__global__ void embed_kernel(const int* __restrict__ at, const float* __restrict__ emb) {
    int i = blockIdx.x * blockDim.x + threadIdx.x;
    if (i >= N_NODES * 32) return;
    int n = i >> 5, q = i & 31;
    float4 v = __ldg((const float4*)(emb + (long long)at[n] * DIM) + q);
    *(float4*)(g_H + (long long)n * 512 + q * 4) = v;
}
__global__ void zero_out_kernel(float* out) { out[threadIdx.x] = 0.0f; }

// ---------------- CSR build ----------------
__global__ void zero_cnt() {
    int i = blockIdx.x * 256 + threadIdx.x;
    if (i < N_NODES) g_cnt[i] = 0;
}
__global__ void hist_kernel(const int* __restrict__ dst) {
    int e = blockIdx.x * 256 + threadIdx.x;
    if (e < N_EDGES) atomicAdd(&g_cnt[dst[e]], 1);
}
__global__ void scan1() {
    __shared__ int sh[256];
    int tid = threadIdx.x;
    int n = blockIdx.x * 256 + tid;
    int v = (n < N_NODES) ? g_cnt[n] : 0;
    sh[tid] = v; __syncthreads();
    #pragma unroll
    for (int o = 1; o < 256; o <<= 1) {
        int t = (tid >= o) ? sh[tid - o] : 0;
        __syncthreads();
        sh[tid] += t;
        __syncthreads();
    }
    if (n < N_NODES) g_scan[n] = sh[tid] - v;
    if (tid == 255) g_bsum[blockIdx.x] = sh[tid];
}
__global__ void scan2() {
    __shared__ int sh[256];
    int tid = threadIdx.x;
    int v = (tid < NB_SCAN) ? g_bsum[tid] : 0;
    sh[tid] = v; __syncthreads();
    #pragma unroll
    for (int o = 1; o < 256; o <<= 1) {
        int t = (tid >= o) ? sh[tid - o] : 0;
        __syncthreads();
        sh[tid] += t;
        __syncthreads();
    }
    if (tid < NB_SCAN) g_boff[tid] = sh[tid] - v;
}
__global__ void scan3() {
    int n = blockIdx.x * 256 + threadIdx.x;
    if (n < N_NODES) {
        int o = g_scan[n] + g_boff[blockIdx.x];
        g_off[n] = o;
        g_cur[n] = o;
    }
    if (n == 0) g_off[N_NODES] = N_EDGES;
}
__global__ void scatter_kernel(const int* __restrict__ src, const int* __restrict__ dst,
                               const float* __restrict__ dist) {
    int e = blockIdx.x * 256 + threadIdx.x;
    if (e >= N_EDGES) return;
    int d = __ldg(dst + e);
    int pos = atomicAdd(&g_cur[d], 1);
    float di = __ldg(dist + e);
    float t = di * ((float)(GRID_G - 1) / 10.0f);
    int gg = (int)(t + 0.5f);          // nearest grid point
    gg = gg < GRID_G - 1 ? gg : GRID_G - 1;
    g_recP[pos] = (unsigned)__ldg(src + e) | ((unsigned)gg << 16);
}

// ---------------- edge gather (nearest table, 4-way unrolled) ----------------
__device__ __forceinline__ void eacc(float4& acc, uint2 tv, uint2 hv) {
    float2 t01 = __half22float2(*(__half2*)&tv.x);
    float2 t23 = __half22float2(*(__half2*)&tv.y);
    float2 h01 = __half22float2(*(__half2*)&hv.x);
    float2 h23 = __half22float2(*(__half2*)&hv.y);
    acc.x = fmaf(t01.x, h01.x, acc.x);
    acc.y = fmaf(t01.y, h01.y, acc.y);
    acc.z = fmaf(t23.x, h23.x, acc.z);
    acc.w = fmaf(t23.y, h23.y, acc.w);
}

__global__ __launch_bounds__(256) void edge_gather(
    const __half* __restrict__ tabp,
    const __half* __restrict__ hn,
    float* __restrict__ node)
{
    int wid = threadIdx.x >> 5, lane = threadIdx.x & 31;
    int n = blockIdx.x * 8 + wid;
    if (n >= N_NODES) return;
    int beg = __ldg(&g_off[n]);
    int end = __ldg(&g_off[n + 1]);
    float4 acc = make_float4(0.f, 0.f, 0.f, 0.f);
    int i = beg;
    for (; i + 4 <= end; i += 4) {
        unsigned r0 = __ldg(&g_recP[i]);
        unsigned r1 = __ldg(&g_recP[i + 1]);
        unsigned r2 = __ldg(&g_recP[i + 2]);
        unsigned r3 = __ldg(&g_recP[i + 3]);
        uint2 t0 = __ldg((const uint2*)(tabp + (long long)(r0 >> 16) * DIM) + lane);
        uint2 t1 = __ldg((const uint2*)(tabp + (long long)(r1 >> 16) * DIM) + lane);
        uint2 t2 = __ldg((const uint2*)(tabp + (long long)(r2 >> 16) * DIM) + lane);
        uint2 t3 = __ldg((const uint2*)(tabp + (long long)(r3 >> 16) * DIM) + lane);
        uint2 h0 = __ldg((const uint2*)(hn + (long long)(r0 & 0xFFFFu) * DIM) + lane);
        uint2 h1 = __ldg((const uint2*)(hn + (long long)(r1 & 0xFFFFu) * DIM) + lane);
        uint2 h2 = __ldg((const uint2*)(hn + (long long)(r2 & 0xFFFFu) * DIM) + lane);
        uint2 h3 = __ldg((const uint2*)(hn + (long long)(r3 & 0xFFFFu) * DIM) + lane);
        eacc(acc, t0, h0);
        eacc(acc, t1, h1);
        eacc(acc, t2, h2);
        eacc(acc, t3, h3);
    }
    for (; i < end; i++) {
        unsigned r = __ldg(&g_recP[i]);
        uint2 tv = __ldg((const uint2*)(tabp + (long long)(r >> 16) * DIM) + lane);
        uint2 hv = __ldg((const uint2*)(hn + (long long)(r & 0xFFFFu) * DIM) + lane);
        eacc(acc, tv, hv);
    }
    *(float4*)(node + (long long)n * DIM + lane * 4) = acc;
}

// ---------------- HMMA GEMM1: Hn2 = fp16(X @ W + b + 1) ----------------
__global__ __launch_bounds__(256) void gemm_m1(
    const float* __restrict__ X, int sx,
    const __nv_bfloat16* __restrict__ Whi, const __nv_bfloat16* __restrict__ Wlo,
    const float* __restrict__ bias, float bextra,
    __half* __restrict__ Hn2, int M)
{
    extern __shared__ uint32_t sm[];
    int tid = threadIdx.x, wid = tid >> 5, lane = tid & 31;
    int mw = wid & 3, nw = wid >> 2;
    int g = lane >> 2, tg = lane & 3;
    int r0 = blockIdx.x * 64;

    load_A(sm, X, sx, 0, r0, M, tid);
    load_B(sm, Whi, Wlo, tid);
    __syncthreads();

    float acc[8][4];
    #pragma unroll
    for (int t = 0; t < 8; t++)
        #pragma unroll
        for (int i = 0; i < 4; i++) acc[t][i] = 0.0f;
    mma_core_t<8>(sm, mw, nw * 64, g, tg, acc, OFF_BHI, OFF_BLO);

    int row0 = r0 + mw * 16 + g, row1 = row0 + 8;
    #pragma unroll
    for (int t = 0; t < 8; t++) {
        int col = nw * 64 + t * 8 + tg * 2;
        float b0 = __ldg(bias + col) + bextra;
        float b1 = __ldg(bias + col + 1) + bextra;
        if (row0 < M)
            *(__half2*)(Hn2 + (long long)row0 * DIM + col) =
                __floats2half2_rn(acc[t][0] + b0, acc[t][1] + b1);
        if (row1 < M)
            *(__half2*)(Hn2 + (long long)row1 * DIM + col) =
                __floats2half2_rn(acc[t][2] + b0, acc[t][3] + b1);
    }
}

// ---------------- fused: H' = H + sp(X@W2+b2)@W3+b3 ; optionally next Hn ----------------
__global__ __launch_bounds__(256) void gemm_m23(
    const float* __restrict__ X, int sx,
    const __nv_bfloat16* __restrict__ W2hi, const __nv_bfloat16* __restrict__ W2lo,
    const float* __restrict__ b2,
    const __nv_bfloat16* __restrict__ W3hi, const __nv_bfloat16* __restrict__ W3lo,
    const float* __restrict__ b3,
    const float* __restrict__ Res, int sr,
    float* __restrict__ Y, int sy,
    const __nv_bfloat16* __restrict__ W1hi, const __nv_bfloat16* __restrict__ W1lo,
    const float* __restrict__ b1n,
    __half* __restrict__ Hn2,
    int has_next, int M)
{
    extern __shared__ uint32_t sm[];
    uint32_t* Ahi = sm + OFF_AHI;
    uint32_t* Alo = sm + OFF_ALO;
    int tid = threadIdx.x, wid = tid >> 5, lane = tid & 31;
    int mw = wid & 3, nw = wid >> 2;
    int g = lane >> 2, tg = lane & 3;
    int r0 = blockIdx.x * 64;
    int rl0 = mw * 16 + g, rl1 = rl0 + 8;
    int row0 = r0 + rl0, row1 = row0 + 8;

    load_A(sm, X, sx, 0, r0, M, tid);
    load_B(sm, W2hi, W2lo, tid);
    __syncthreads();

    float acc[8][4];
    #pragma unroll
    for (int t = 0; t < 8; t++)
        #pragma unroll
        for (int i = 0; i < 4; i++) acc[t][i] = 0.0f;
    mma_core_t<8>(sm, mw, nw * 64, g, tg, acc, OFF_BHI, OFF_BLO);

    #pragma unroll
    for (int t = 0; t < 8; t++) {
        int col = nw * 64 + t * 8 + tg * 2;
        float b0 = __ldg(b2 + col), b1 = __ldg(b2 + col + 1);
        float t0 = sp_half(acc[t][0] + b0), t1 = sp_half(acc[t][1] + b1);
        float t2 = sp_half(acc[t][2] + b0), t3 = sp_half(acc[t][3] + b1);
        uint32_t h, l;
        int w0 = rl0 * ASTR + (col >> 1);
        int w1 = rl1 * ASTR + (col >> 1);
        split2(t0, t1, h, l); Ahi[w0] = h; Alo[w0] = l;
        split2(t2, t3, h, l); Ahi[w1] = h; Alo[w1] = l;
    }
    __syncthreads();
    load_B(sm, W3hi, W3lo, tid);
    __syncthreads();

    #pragma unroll
    for (int t = 0; t < 8; t++)
        #pragma unroll
        for (int i = 0; i < 4; i++) acc[t][i] = 0.0f;
    mma_core_t<8>(sm, mw, nw * 64, g, tg, acc, OFF_BHI, OFF_BLO);

    #pragma unroll
    for (int t = 0; t < 8; t++) {
        int col = nw * 64 + t * 8 + tg * 2;
        float b0 = __ldg(b3 + col), b1 = __ldg(b3 + col + 1);
        float y0 = acc[t][0] + b0, y1 = acc[t][1] + b1;
        float y2 = acc[t][2] + b0, y3 = acc[t][3] + b1;
        if (row0 < M) {
            float2 r = *(const float2*)(Res + (long long)row0 * sr + col);
            y0 += r.x; y1 += r.y;
            *(float2*)(Y + (long long)row0 * sy + col) = make_float2(y0, y1);
        }
        if (row1 < M) {
            float2 r = *(const float2*)(Res + (long long)row1 * sr + col);
            y2 += r.x; y3 += r.y;
            *(float2*)(Y + (long long)row1 * sy + col) = make_float2(y2, y3);
        }
        if (has_next) {
            uint32_t h, l;
            int w0 = rl0 * ASTR + (col >> 1);
            int w1 = rl1 * ASTR + (col >> 1);
            split2(y0, y1, h, l); Ahi[w0] = h; Alo[w0] = l;
            split2(y2, y3, h, l); Ahi[w1] = h; Alo[w1] = l;
        }
    }
    if (!has_next) return;

    __syncthreads();
    load_B(sm, W1hi, W1lo, tid);
    __syncthreads();

    #pragma unroll
    for (int t = 0; t < 8; t++)
        #pragma unroll
        for (int i = 0; i < 4; i++) acc[t][i] = 0.0f;
    mma_core_t<8>(sm, mw, nw * 64, g, tg, acc, OFF_BHI, OFF_BLO);

    #pragma unroll
    for (int t = 0; t < 8; t++) {
        int col = nw * 64 + t * 8 + tg * 2;
        float b0 = __ldg(b1n + col) + 1.0f;
        float b1 = __ldg(b1n + col + 1) + 1.0f;
        if (row0 < M)
            *(__half2*)(Hn2 + (long long)row0 * DIM + col) =
                __floats2half2_rn(acc[t][0] + b0, acc[t][1] + b1);
        if (row1 < M)
            *(__half2*)(Hn2 + (long long)row1 * DIM + col) =
                __floats2half2_rn(acc[t][2] + b0, acc[t][3] + b1);
    }
}

// ---------------- fused readout ----------------
__global__ __launch_bounds__(256) void gemm_r(
    const float* __restrict__ X,
    const __nv_bfloat16* __restrict__ Whi, const __nv_bfloat16* __restrict__ Wlo,
    const float* __restrict__ br1, const float* __restrict__ Wr2,
    const float* __restrict__ br2,
    const int* __restrict__ gid, float* __restrict__ out, int M)
{
    extern __shared__ uint32_t sm[];
    __shared__ float res[64];
    int tid = threadIdx.x, wid = tid >> 5, lane = tid & 31;
    int mw = wid & 3, nw = wid >> 2;
    int g = lane >> 2, tg = lane & 3;
    int r0 = blockIdx.x * 64;
    if (tid < 64) res[tid] = 0.0f;

    float acc[4][4];
    #pragma unroll
    for (int t = 0; t < 4; t++)
        #pragma unroll
        for (int i = 0; i < 4; i++) acc[t][i] = 0.0f;

    for (int ch = 0; ch < 4; ch++) {
        load_A(sm, X, 512, ch * 128, r0, M, tid);
        load_B_r(sm, g_WrHi, g_WrLo, ch, tid);
        __syncthreads();
        mma_core_t<4>(sm, mw, nw * 32, g, tg, acc, OFF_BHI_R, OFF_BLO_R);
        __syncthreads();
    }

    float p0 = 0.0f, p1 = 0.0f;
    #pragma unroll
    for (int t = 0; t < 4; t++) {
        int col = nw * 32 + t * 8 + tg * 2;
        float b0 = __ldg(br1 + col), b1 = __ldg(br1 + col + 1);
        float w0 = __ldg(Wr2 + col), w1 = __ldg(Wr2 + col + 1);
        p0 += sp_one(acc[t][0] + b0) * w0 + sp_one(acc[t][1] + b1) * w1;
        p1 += sp_one(acc[t][2] + b0) * w0 + sp_one(acc[t][3] + b1) * w1;
    }
    p0 += __shfl_down_sync(0xffffffff, p0, 1);
    p0 += __shfl_down_sync(0xffffffff, p0, 2);
    p1 += __shfl_down_sync(0xffffffff, p1, 1);
    p1 += __shfl_down_sync(0xffffffff, p1, 2);
    if (tg == 0) {
        atomicAdd(&res[mw * 16 + g], p0);
        atomicAdd(&res[mw * 16 + g + 8], p1);
    }
    __syncthreads();
    if (tid < 64) {
        int row = r0 + tid;
        if (row < M) atomicAdd(out + __ldg(gid + row), res[tid] + __ldg(br2));
    }
}

// ---------------- launch ----------------
extern "C" void kernel_launch(void* const* d_in, const int* in_sizes, int n_in,
                              void* d_out, int out_size) {
    const int*   atom_type = (const int*)d_in[0];
    const int*   src  = (const int*)d_in[1];
    const int*   dst  = (const int*)d_in[2];
    const int*   gid  = (const int*)d_in[3];
    const float* dist = (const float*)d_in[4];
    const float* emb  = (const float*)d_in[5];
    const float* W_n1 = (const float*)d_in[6];  const float* b_n1 = (const float*)d_in[7];
    const float* W_c1 = (const float*)d_in[8];  const float* b_c1 = (const float*)d_in[9];
    const float* W_c2 = (const float*)d_in[10]; const float* b_c2 = (const float*)d_in[11];
    const float* W_c3 = (const float*)d_in[12]; const float* b_c3 = (const float*)d_in[13];
    const float* W_n2 = (const float*)d_in[14]; const float* b_n2 = (const float*)d_in[15];
    const float* W_n3 = (const float*)d_in[16]; const float* b_n3 = (const float*)d_in[17];
    const float* W_r1 = (const float*)d_in[18]; const float* b_r1 = (const float*)d_in[19];
    const float* W_r2 = (const float*)d_in[20]; const float* b_r2 = (const float*)d_in[21];
    float* out = (float*)d_out;

    float *H, *Node;
    __half *Hn2, *TabP;
    __nv_bfloat16 *WbHi, *WbLo, *WrHi, *WrLo;
    cudaGetSymbolAddress((void**)&H,    g_H);
    cudaGetSymbolAddress((void**)&Hn2,  g_Hn2);
    cudaGetSymbolAddress((void**)&Node, g_Node);
    cudaGetSymbolAddress((void**)&TabP, g_TabP);
    cudaGetSymbolAddress((void**)&WbHi, g_WbHi);
    cudaGetSymbolAddress((void**)&WbLo, g_WbLo);
    cudaGetSymbolAddress((void**)&WrHi, g_WrHi);
    cudaGetSymbolAddress((void**)&WrLo, g_WrLo);

    cudaFuncSetAttribute(gemm_m1,  cudaFuncAttributeMaxDynamicSharedMemorySize, TSMEM_M);
    cudaFuncSetAttribute(gemm_m23, cudaFuncAttributeMaxDynamicSharedMemorySize, TSMEM_M);
    cudaFuncSetAttribute(gemm_tab, cudaFuncAttributeMaxDynamicSharedMemorySize, TSMEM_M);
    cudaFuncSetAttribute(gemm_r,   cudaFuncAttributeMaxDynamicSharedMemorySize, TSMEM_R);

    const int M = N_NODES;
    const int GB64 = (M + 63) / 64;     // 938
    const int EB = (N_EDGES + 255) / 256;

    // precompute: tables (HMMA path, fp16 direct) + weights + embedding + CSR
    fold_kernel<<<dim3(DIM, N_LAYERS), DIM>>>(W_c2, b_c2, W_c3, b_c3);
    spu_kernel<<<dim3(GRID_G / 8, N_LAYERS), 128>>>(W_c1, b_c1);
    gemm_tab<<<dim3(GRID_G / 64, N_LAYERS), 256, TSMEM_M>>>();
    prep_w<<<dim3(9, 16), 128>>>(W_n1, W_n2, W_n3, WbHi, WbLo);
    prep_r<<<32, 128>>>(W_r1, WrHi, WrLo);
    embed_kernel<<<(N_NODES * 32 + 255) / 256, 256>>>(atom_type, emb);

    zero_cnt<<<NB_SCAN, 256>>>();
    hist_kernel<<<EB, 256>>>(dst);
    scan1<<<NB_SCAN, 256>>>();
    scan2<<<1, 256>>>();
    scan3<<<NB_SCAN, 256>>>();
    scatter_kernel<<<EB, 256>>>(src, dst, dist);

    // layer 0 h_new
    gemm_m1<<<GB64, 256, TSMEM_M>>>(H, 512, WbHi, WbLo, b_n1, 1.0f, Hn2, M);

    for (int l = 0; l < N_LAYERS; l++) {
        edge_gather<<<(N_NODES + 7) / 8, 256>>>(
            TabP + (long long)l * GRID_G * DIM, Hn2, Node);
        int nl = l + 1;
        int has_next = (nl < N_LAYERS);
        gemm_m23<<<GB64, 256, TSMEM_M>>>(
            Node, 128,
            WbHi + (long long)(3 + l) * DIM * DIM, WbLo + (long long)(3 + l) * DIM * DIM,
            b_n2 + l * 128,
            WbHi + (long long)(6 + l) * DIM * DIM, WbLo + (long long)(6 + l) * DIM * DIM,
            b_n3 + l * 128,
            H + l * 128, 512, H + nl * 128, 512,
            WbHi + (long long)(has_next ? nl : 0) * DIM * DIM,
            WbLo + (long long)(has_next ? nl : 0) * DIM * DIM,
            b_n1 + (has_next ? nl : 0) * 128,
            Hn2, has_next, M);
    }

    zero_out_kernel<<<1, N_GRAPH>>>(out);
    gemm_r<<<GB64, 256, TSMEM_R>>>(H, WrHi, WrLo, b_r1, W_r2, b_r2, gid, out, M);
}

// round 8
// speedup vs baseline: 2.2467x; 1.1198x over previous
#include <cuda_runtime.h>
#include <cuda_fp16.h>
#include <math.h>
#include <stdint.h>

#define N_NODES 60000
#define N_EDGES 600000
#define N_GRAPH 512
#define DIM 128
#define N_LAYERS 3
#define GRID_G 8192
#define NB_SCAN 235      // ceil(60000/256)

// ---------------- device scratch ----------------
__device__ float g_H[(long long)N_NODES * 512];
__device__ __half g_Hn2[(long long)N_NODES * DIM];
__device__ __half g_Node2[(long long)N_NODES * DIM];     // gather output, fp16
__device__ float g_bf[N_LAYERS * DIM];
__device__ float g_Spu[(long long)N_LAYERS * GRID_G * DIM];
__device__ __align__(256) __half g_TabP[(long long)N_LAYERS * GRID_G * DIM];
// fp16 hi/lo weights, B-operand layout [N][K]
__device__ __align__(256) __half g_WbHi[9 * DIM * DIM];
__device__ __align__(256) __half g_WbLo[9 * DIM * DIM];
__device__ __align__(256) __half g_WfHi[N_LAYERS * DIM * DIM];
__device__ __align__(256) __half g_WfLo[N_LAYERS * DIM * DIM];
__device__ __align__(256) __half g_WrHi[64 * 512];
__device__ __align__(256) __half g_WrLo[64 * 512];
// CSR build
__device__ int g_cnt[N_NODES];
__device__ int g_scan[N_NODES];
__device__ int g_bsum[NB_SCAN];
__device__ int g_boff[NB_SCAN];
__device__ int g_off[N_NODES + 1];
__device__ int g_cur[N_NODES];
__device__ unsigned g_recP[N_EDGES];   // src (16b) | grid idx << 16

// ---------------- scalar helpers ----------------
__device__ __forceinline__ float sp_half(float x) {
    float bx = 0.5f * x;
    return bx > 14.0f ? x : 2.0f * log1pf(expf(bx));
}
__device__ __forceinline__ float sp_one(float x) {
    return x > 20.0f ? x : log1pf(expf(x));
}

// ---------------- HMMA fp16 ----------------
__device__ __forceinline__ void mma16816h(float* d, const uint32_t* a,
                                          uint32_t b0, uint32_t b1) {
    asm volatile(
        "mma.sync.aligned.m16n8k16.row.col.f32.f16.f16.f32 "
        "{%0,%1,%2,%3}, {%4,%5,%6,%7}, {%8,%9}, {%0,%1,%2,%3};"
        : "+f"(d[0]), "+f"(d[1]), "+f"(d[2]), "+f"(d[3])
        : "r"(a[0]), "r"(a[1]), "r"(a[2]), "r"(a[3]), "r"(b0), "r"(b1));
}

#define ASTR 68
#define A_WORDS (64 * ASTR)            // 4352
#define B_WORDS (128 * ASTR)           // 8704
#define BR_WORDS (64 * ASTR)
#define OFF_A 0
#define OFF_BHI  A_WORDS
#define OFF_BLO  (A_WORDS + B_WORDS)
#define OFF_BHI_R A_WORDS
#define OFF_BLO_R (A_WORDS + BR_WORDS)
#define TSMEM_M ((A_WORDS + 2 * B_WORDS) * 4)   // 87040
#define TSMEM_R ((A_WORDS + 2 * BR_WORDS) * 4)  // 52224

// 2-product core: acc += A(fp16) @ (Bhi + Blo)
template<int NT>
__device__ __forceinline__ void mma_core2(const uint32_t* __restrict__ sm,
                                          int mw, int nwbase, int g, int tg,
                                          float acc[NT][4], int offBhi, int offBlo) {
    const uint32_t* A   = sm + OFF_A;
    const uint32_t* Bhi = sm + offBhi;
    const uint32_t* Blo = sm + offBlo;
    int ra0 = (mw * 16 + g) * ASTR;
    int ra1 = ra0 + 8 * ASTR;
    #pragma unroll
    for (int ks = 0; ks < 8; ks++) {
        int c = ks * 8 + tg;
        uint32_t ah[4];
        ah[0] = A[ra0 + c];     ah[1] = A[ra1 + c];
        ah[2] = A[ra0 + c + 4]; ah[3] = A[ra1 + c + 4];
        #pragma unroll
        for (int t = 0; t < NT; t++) {
            int rb = (nwbase + t * 8 + g) * ASTR;
            uint32_t bh0 = Bhi[rb + c], bh1 = Bhi[rb + c + 4];
            uint32_t bl0 = Blo[rb + c], bl1 = Blo[rb + c + 4];
            mma16816h(acc[t], ah, bh0, bh1);
            mma16816h(acc[t], ah, bl0, bl1);
        }
    }
}

// fp32 X tile -> fp16 A smem
__device__ __forceinline__ void load_A_f(uint32_t* sm, const float* __restrict__ X,
                                         int sx, int c0, int r0, int M, int tid) {
    uint32_t* A = sm + OFF_A;
    #pragma unroll
    for (int j = 0; j < 8; j++) {
        int f = tid + j * 256;
        int row = f >> 5, q = f & 31;
        float4 v = make_float4(0.f, 0.f, 0.f, 0.f);
        int gr = r0 + row;
        if (gr < M) v = *(const float4*)(X + (long long)gr * sx + c0 + q * 4);
        __half2 h01 = __floats2half2_rn(v.x, v.y);
        __half2 h23 = __floats2half2_rn(v.z, v.w);
        *(uint2*)(A + row * ASTR + q * 2) =
            make_uint2(*(uint32_t*)&h01, *(uint32_t*)&h23);
    }
}

// fp16 X tile [M][128] -> A smem (straight swizzled copy)
__device__ __forceinline__ void load_A_h(uint32_t* sm, const __half* __restrict__ X,
                                         int r0, int M, int tid) {
    uint32_t* A = sm + OFF_A;
    #pragma unroll
    for (int j = 0; j < 4; j++) {
        int idx = tid + j * 256;          // 1024 uint4 = 64 rows x 16
        int row = idx >> 4, q = idx & 15;
        uint4 v = make_uint4(0u, 0u, 0u, 0u);
        int gr = r0 + row;
        if (gr < M) v = *(const uint4*)((const uint4*)(X + (long long)gr * DIM) + q);
        *(uint4*)(A + row * ASTR + q * 4) = v;
    }
}

// W [128 rows][64 words] -> B smem
__device__ __forceinline__ void load_B(uint32_t* sm, int offHi, int offLo,
                                       const __half* __restrict__ Whi,
                                       const __half* __restrict__ Wlo, int tid) {
    uint32_t* Bhi = sm + offHi;
    uint32_t* Blo = sm + offLo;
    const uint4* s1 = (const uint4*)Whi;
    const uint4* s2 = (const uint4*)Wlo;
    #pragma unroll
    for (int j = 0; j < 8; j++) {
        int i = tid + j * 256;
        int row = i >> 4, cq = (i & 15) * 4;
        *(uint4*)(Bhi + row * ASTR + cq) = s1[i];
        *(uint4*)(Blo + row * ASTR + cq) = s2[i];
    }
}

// readout B: 64 rows, K-chunk of 512-row-stride source
__device__ __forceinline__ void load_B_r(uint32_t* sm, const __half* __restrict__ Whi,
                                         const __half* __restrict__ Wlo,
                                         int chunk, int tid) {
    uint32_t* Bhi = sm + OFF_BHI_R;
    uint32_t* Blo = sm + OFF_BLO_R;
    const uint4* s1 = (const uint4*)Whi;
    const uint4* s2 = (const uint4*)Wlo;
    #pragma unroll
    for (int j = 0; j < 4; j++) {
        int i = tid + j * 256;
        int row = i >> 4, q = i & 15;
        int si = row * 64 + chunk * 16 + q;
        *(uint4*)(Bhi + row * ASTR + q * 4) = s1[si];
        *(uint4*)(Blo + row * ASTR + q * 4) = s2[si];
    }
}

// ---------------- weight prep (fp16 hi/lo) ----------------
__global__ void prep_w(const float* __restrict__ Wn1, const float* __restrict__ Wn2,
                       const float* __restrict__ Wn3,
                       __half* __restrict__ Hi, __half* __restrict__ Lo) {
    int m = blockIdx.x;
    const float* src = (m < 3 ? Wn1 : (m < 6 ? Wn2 : Wn3)) + (long long)(m % 3) * DIM * DIM;
    __half* dh = Hi + (long long)m * DIM * DIM;
    __half* dl = Lo + (long long)m * DIM * DIM;
    int idx0 = blockIdx.y * 1024;
    for (int i = 0; i < 8; i++) {
        int idx = idx0 + i * 128 + threadIdx.x;
        int k = idx >> 7, n = idx & 127;
        float v = src[idx];
        __half h = __float2half_rn(v);
        __half l = __float2half_rn(v - __half2float(h));
        dh[n * DIM + k] = h;
        dl[n * DIM + k] = l;
    }
}
__global__ void prep_r(const float* __restrict__ Wr1,
                       __half* __restrict__ Hi, __half* __restrict__ Lo) {
    int idx = blockIdx.x * 1024 + threadIdx.x;
    for (int i = 0; i < 8; i++) {
        int f = idx + i * 128;
        int k = f >> 6, n = f & 63;
        float v = Wr1[f];
        __half h = __float2half_rn(v);
        __half l = __float2half_rn(v - __half2float(h));
        Hi[n * 512 + k] = h;
        Lo[n * 512 + k] = l;
    }
}

// ---------------- fold W_c2 @ W_c3 -> fp16 hi/lo B-layout ----------------
__global__ void fold_kernel(const float* __restrict__ Wc2, const float* __restrict__ bc2,
                            const float* __restrict__ Wc3, const float* __restrict__ bc3) {
    int k = blockIdx.x, l = blockIdx.y, j = threadIdx.x;
    __shared__ float row[DIM];
    row[j] = Wc2[((long long)l * DIM + k) * DIM + j];
    __syncthreads();
    float acc = 0.0f;
    #pragma unroll 4
    for (int m = 0; m < DIM; m++)
        acc += row[m] * Wc3[((long long)l * DIM + m) * DIM + j];
    __half h = __float2half_rn(acc);
    __half lo = __float2half_rn(acc - __half2float(h));
    g_WfHi[(long long)l * DIM * DIM + j * DIM + k] = h;
    g_WfLo[(long long)l * DIM * DIM + j * DIM + k] = lo;
    if (k == 0) {
        float bacc = bc3[l * DIM + j];
        #pragma unroll 4
        for (int m = 0; m < DIM; m++)
            bacc += bc2[l * DIM + m] * Wc3[((long long)l * DIM + m) * DIM + j];
        g_bf[l * DIM + j] = bacc;
    }
}

// ---------------- spu table ----------------
__global__ void spu_kernel(const float* __restrict__ Wc1, const float* __restrict__ bc1) {
    __shared__ float wc[30 * DIM];
    __shared__ float bc[DIM];
    __shared__ float rbf[32];
    int l = blockIdx.y, tid = threadIdx.x;
    const float* W = Wc1 + (long long)l * 30 * DIM;
    for (int i = tid; i < 30 * DIM; i += 128) wc[i] = W[i];
    bc[tid] = bc1[l * DIM + tid];
    __syncthreads();
    for (int gi = 0; gi < 8; gi++) {
        int g = blockIdx.x * 8 + gi;
        if (tid < 30) {
            float dg = (float)g * (10.0f / (float)(GRID_G - 1));
            float c = (float)tid * (10.0f / 29.0f);
            float dd = dg - c;
            rbf[tid] = expf(-dd * dd * 2.9f);
        }
        __syncthreads();
        float u = bc[tid];
        #pragma unroll
        for (int r = 0; r < 30; r++)
            u += rbf[r] * wc[r * DIM + tid];
        g_Spu[((long long)l * GRID_G + g) * DIM + tid] = sp_half(u);
        __syncthreads();
    }
}

// ---------------- table GEMM: TabP(fp16) = Spu @ Wf + bf ----------------
__global__ __launch_bounds__(256) void gemm_tab() {
    extern __shared__ uint32_t sm[];
    int tid = threadIdx.x, wid = tid >> 5, lane = tid & 31;
    int mw = wid & 3, nw = wid >> 2;
    int g = lane >> 2, tg = lane & 3;
    int l = blockIdx.y;
    int r0 = blockIdx.x * 64;
    const float* X = g_Spu + (long long)l * GRID_G * DIM;
    __half* Y = g_TabP + (long long)l * GRID_G * DIM;

    load_A_f(sm, X, DIM, 0, r0, GRID_G, tid);
    load_B(sm, OFF_BHI, OFF_BLO,
           g_WfHi + (long long)l * DIM * DIM, g_WfLo + (long long)l * DIM * DIM, tid);
    __syncthreads();

    float acc[8][4];
    #pragma unroll
    for (int t = 0; t < 8; t++)
        #pragma unroll
        for (int i = 0; i < 4; i++) acc[t][i] = 0.0f;
    mma_core2<8>(sm, mw, nw * 64, g, tg, acc, OFF_BHI, OFF_BLO);

    int row0 = r0 + mw * 16 + g, row1 = row0 + 8;
    #pragma unroll
    for (int t = 0; t < 8; t++) {
        int col = nw * 64 + t * 8 + tg * 2;
        float b0 = g_bf[l * DIM + col], b1 = g_bf[l * DIM + col + 1];
        *(__half2*)(Y + (long long)row0 * DIM + col) =
            __floats2half2_rn(acc[t][0] + b0, acc[t][1] + b1);
        *(__half2*)(Y + (long long)row1 * DIM + col) =
            __floats2half2_rn(acc[t][2] + b0, acc[t][3] + b1);
    }
}

// ---------------- embedding ----------------
__global__ void embed_kernel(const int* __restrict__ at, const float* __restrict__ emb) {
    int i = blockIdx.x * blockDim.x + threadIdx.x;
    if (i >= N_NODES * 32) return;
    int n = i >> 5, q = i & 31;
    float4 v = __ldg((const float4*)(emb + (long long)at[n] * DIM) + q);
    *(float4*)(g_H + (long long)n * 512 + q * 4) = v;
}
__global__ void zero_out_kernel(float* out) { out[threadIdx.x] = 0.0f; }

// ---------------- CSR build ----------------
__global__ void zero_cnt() {
    int i = blockIdx.x * 256 + threadIdx.x;
    if (i < N_NODES) g_cnt[i] = 0;
}
__global__ void hist_kernel(const int* __restrict__ dst) {
    int e = blockIdx.x * 256 + threadIdx.x;
    if (e < N_EDGES) atomicAdd(&g_cnt[dst[e]], 1);
}
__global__ void scan1() {
    __shared__ int sh[256];
    int tid = threadIdx.x;
    int n = blockIdx.x * 256 + tid;
    int v = (n < N_NODES) ? g_cnt[n] : 0;
    sh[tid] = v; __syncthreads();
    #pragma unroll
    for (int o = 1; o < 256; o <<= 1) {
        int t = (tid >= o) ? sh[tid - o] : 0;
        __syncthreads();
        sh[tid] += t;
        __syncthreads();
    }
    if (n < N_NODES) g_scan[n] = sh[tid] - v;
    if (tid == 255) g_bsum[blockIdx.x] = sh[tid];
}
__global__ void scan2() {
    __shared__ int sh[256];
    int tid = threadIdx.x;
    int v = (tid < NB_SCAN) ? g_bsum[tid] : 0;
    sh[tid] = v; __syncthreads();
    #pragma unroll
    for (int o = 1; o < 256; o <<= 1) {
        int t = (tid >= o) ? sh[tid - o] : 0;
        __syncthreads();
        sh[tid] += t;
        __syncthreads();
    }
    if (tid < NB_SCAN) g_boff[tid] = sh[tid] - v;
}
__global__ void scan3() {
    int n = blockIdx.x * 256 + threadIdx.x;
    if (n < N_NODES) {
        int o = g_scan[n] + g_boff[blockIdx.x];
        g_off[n] = o;
        g_cur[n] = o;
    }
    if (n == 0) g_off[N_NODES] = N_EDGES;
}
__global__ void scatter_kernel(const int* __restrict__ src, const int* __restrict__ dst,
                               const float* __restrict__ dist) {
    int e = blockIdx.x * 256 + threadIdx.x;
    if (e >= N_EDGES) return;
    int d = __ldg(dst + e);
    int pos = atomicAdd(&g_cur[d], 1);
    float di = __ldg(dist + e);
    float t = di * ((float)(GRID_G - 1) / 10.0f);
    int gg = (int)(t + 0.5f);
    gg = gg < GRID_G - 1 ? gg : GRID_G - 1;
    g_recP[pos] = (unsigned)__ldg(src + e) | ((unsigned)gg << 16);
}

// ---------------- edge gather -> fp16 Node2 ----------------
__device__ __forceinline__ void eacc(float4& acc, uint2 tv, uint2 hv) {
    float2 t01 = __half22float2(*(__half2*)&tv.x);
    float2 t23 = __half22float2(*(__half2*)&tv.y);
    float2 h01 = __half22float2(*(__half2*)&hv.x);
    float2 h23 = __half22float2(*(__half2*)&hv.y);
    acc.x = fmaf(t01.x, h01.x, acc.x);
    acc.y = fmaf(t01.y, h01.y, acc.y);
    acc.z = fmaf(t23.x, h23.x, acc.z);
    acc.w = fmaf(t23.y, h23.y, acc.w);
}

__global__ __launch_bounds__(256) void edge_gather(
    const __half* __restrict__ tabp,
    const __half* __restrict__ hn,
    __half* __restrict__ node2)
{
    int wid = threadIdx.x >> 5, lane = threadIdx.x & 31;
    int n = blockIdx.x * 8 + wid;
    if (n >= N_NODES) return;
    int beg = __ldg(&g_off[n]);
    int end = __ldg(&g_off[n + 1]);
    float4 acc = make_float4(0.f, 0.f, 0.f, 0.f);
    int i = beg;
    for (; i + 4 <= end; i += 4) {
        unsigned r0 = __ldg(&g_recP[i]);
        unsigned r1 = __ldg(&g_recP[i + 1]);
        unsigned r2 = __ldg(&g_recP[i + 2]);
        unsigned r3 = __ldg(&g_recP[i + 3]);
        uint2 t0 = __ldg((const uint2*)(tabp + (long long)(r0 >> 16) * DIM) + lane);
        uint2 t1 = __ldg((const uint2*)(tabp + (long long)(r1 >> 16) * DIM) + lane);
        uint2 t2 = __ldg((const uint2*)(tabp + (long long)(r2 >> 16) * DIM) + lane);
        uint2 t3 = __ldg((const uint2*)(tabp + (long long)(r3 >> 16) * DIM) + lane);
        uint2 h0 = __ldg((const uint2*)(hn + (long long)(r0 & 0xFFFFu) * DIM) + lane);
        uint2 h1 = __ldg((const uint2*)(hn + (long long)(r1 & 0xFFFFu) * DIM) + lane);
        uint2 h2 = __ldg((const uint2*)(hn + (long long)(r2 & 0xFFFFu) * DIM) + lane);
        uint2 h3 = __ldg((const uint2*)(hn + (long long)(r3 & 0xFFFFu) * DIM) + lane);
        eacc(acc, t0, h0);
        eacc(acc, t1, h1);
        eacc(acc, t2, h2);
        eacc(acc, t3, h3);
    }
    for (; i < end; i++) {
        unsigned r = __ldg(&g_recP[i]);
        uint2 tv = __ldg((const uint2*)(tabp + (long long)(r >> 16) * DIM) + lane);
        uint2 hv = __ldg((const uint2*)(hn + (long long)(r & 0xFFFFu) * DIM) + lane);
        eacc(acc, tv, hv);
    }
    __half2 o01 = __floats2half2_rn(acc.x, acc.y);
    __half2 o23 = __floats2half2_rn(acc.z, acc.w);
    *(uint2*)(node2 + (long long)n * DIM + lane * 4) =
        make_uint2(*(uint32_t*)&o01, *(uint32_t*)&o23);
}

// ---------------- GEMM1: Hn2 = fp16(H_l @ W + b + 1) ----------------
__global__ __launch_bounds__(256) void gemm_m1(
    const float* __restrict__ X, int sx,
    const __half* __restrict__ Whi, const __half* __restrict__ Wlo,
    const float* __restrict__ bias, float bextra,
    __half* __restrict__ Hn2, int M)
{
    extern __shared__ uint32_t sm[];
    int tid = threadIdx.x, wid = tid >> 5, lane = tid & 31;
    int mw = wid & 3, nw = wid >> 2;
    int g = lane >> 2, tg = lane & 3;
    int r0 = blockIdx.x * 64;

    load_A_f(sm, X, sx, 0, r0, M, tid);
    load_B(sm, OFF_BHI, OFF_BLO, Whi, Wlo, tid);
    __syncthreads();

    float acc[8][4];
    #pragma unroll
    for (int t = 0; t < 8; t++)
        #pragma unroll
        for (int i = 0; i < 4; i++) acc[t][i] = 0.0f;
    mma_core2<8>(sm, mw, nw * 64, g, tg, acc, OFF_BHI, OFF_BLO);

    int row0 = r0 + mw * 16 + g, row1 = row0 + 8;
    #pragma unroll
    for (int t = 0; t < 8; t++) {
        int col = nw * 64 + t * 8 + tg * 2;
        float b0 = __ldg(bias + col) + bextra;
        float b1 = __ldg(bias + col + 1) + bextra;
        if (row0 < M)
            *(__half2*)(Hn2 + (long long)row0 * DIM + col) =
                __floats2half2_rn(acc[t][0] + b0, acc[t][1] + b1);
        if (row1 < M)
            *(__half2*)(Hn2 + (long long)row1 * DIM + col) =
                __floats2half2_rn(acc[t][2] + b0, acc[t][3] + b1);
    }
}

// ---------------- fused: H' = H + sp(Node2@W2+b2)@W3+b3 ; optionally next Hn ----------------
__global__ __launch_bounds__(256) void gemm_m23(
    const __half* __restrict__ X,
    const __half* __restrict__ W2hi, const __half* __restrict__ W2lo,
    const float* __restrict__ b2,
    const __half* __restrict__ W3hi, const __half* __restrict__ W3lo,
    const float* __restrict__ b3,
    const float* __restrict__ Res, int sr,
    float* __restrict__ Y, int sy,
    const __half* __restrict__ W1hi, const __half* __restrict__ W1lo,
    const float* __restrict__ b1n,
    __half* __restrict__ Hn2,
    int has_next, int M)
{
    extern __shared__ uint32_t sm[];
    uint32_t* A = sm + OFF_A;
    int tid = threadIdx.x, wid = tid >> 5, lane = tid & 31;
    int mw = wid & 3, nw = wid >> 2;
    int g = lane >> 2, tg = lane & 3;
    int r0 = blockIdx.x * 64;
    int rl0 = mw * 16 + g, rl1 = rl0 + 8;
    int row0 = r0 + rl0, row1 = row0 + 8;

    load_A_h(sm, X, r0, M, tid);
    load_B(sm, OFF_BHI, OFF_BLO, W2hi, W2lo, tid);
    __syncthreads();

    float acc[8][4];
    #pragma unroll
    for (int t = 0; t < 8; t++)
        #pragma unroll
        for (int i = 0; i < 4; i++) acc[t][i] = 0.0f;
    mma_core2<8>(sm, mw, nw * 64, g, tg, acc, OFF_BHI, OFF_BLO);

    // t = sp_half(acc + b2) -> A smem (fp16)
    #pragma unroll
    for (int t = 0; t < 8; t++) {
        int col = nw * 64 + t * 8 + tg * 2;
        float b0 = __ldg(b2 + col), b1 = __ldg(b2 + col + 1);
        __half2 v0 = __floats2half2_rn(sp_half(acc[t][0] + b0), sp_half(acc[t][1] + b1));
        __half2 v1 = __floats2half2_rn(sp_half(acc[t][2] + b0), sp_half(acc[t][3] + b1));
        A[rl0 * ASTR + (col >> 1)] = *(uint32_t*)&v0;
        A[rl1 * ASTR + (col >> 1)] = *(uint32_t*)&v1;
    }
    __syncthreads();
    load_B(sm, OFF_BHI, OFF_BLO, W3hi, W3lo, tid);
    __syncthreads();

    #pragma unroll
    for (int t = 0; t < 8; t++)
        #pragma unroll
        for (int i = 0; i < 4; i++) acc[t][i] = 0.0f;
    mma_core2<8>(sm, mw, nw * 64, g, tg, acc, OFF_BHI, OFF_BLO);

    #pragma unroll
    for (int t = 0; t < 8; t++) {
        int col = nw * 64 + t * 8 + tg * 2;
        float b0 = __ldg(b3 + col), b1 = __ldg(b3 + col + 1);
        float y0 = acc[t][0] + b0, y1 = acc[t][1] + b1;
        float y2 = acc[t][2] + b0, y3 = acc[t][3] + b1;
        if (row0 < M) {
            float2 r = *(const float2*)(Res + (long long)row0 * sr + col);
            y0 += r.x; y1 += r.y;
            *(float2*)(Y + (long long)row0 * sy + col) = make_float2(y0, y1);
        }
        if (row1 < M) {
            float2 r = *(const float2*)(Res + (long long)row1 * sr + col);
            y2 += r.x; y3 += r.y;
            *(float2*)(Y + (long long)row1 * sy + col) = make_float2(y2, y3);
        }
        if (has_next) {
            __half2 v0 = __floats2half2_rn(y0, y1);
            __half2 v1 = __floats2half2_rn(y2, y3);
            A[rl0 * ASTR + (col >> 1)] = *(uint32_t*)&v0;
            A[rl1 * ASTR + (col >> 1)] = *(uint32_t*)&v1;
        }
    }
    if (!has_next) return;

    __syncthreads();
    load_B(sm, OFF_BHI, OFF_BLO, W1hi, W1lo, tid);
    __syncthreads();

    #pragma unroll
    for (int t = 0; t < 8; t++)
        #pragma unroll
        for (int i = 0; i < 4; i++) acc[t][i] = 0.0f;
    mma_core2<8>(sm, mw, nw * 64, g, tg, acc, OFF_BHI, OFF_BLO);

    #pragma unroll
    for (int t = 0; t < 8; t++) {
        int col = nw * 64 + t * 8 + tg * 2;
        float b0 = __ldg(b1n + col) + 1.0f;
        float b1 = __ldg(b1n + col + 1) + 1.0f;
        if (row0 < M)
            *(__half2*)(Hn2 + (long long)row0 * DIM + col) =
                __floats2half2_rn(acc[t][0] + b0, acc[t][1] + b1);
        if (row1 < M)
            *(__half2*)(Hn2 + (long long)row1 * DIM + col) =
                __floats2half2_rn(acc[t][2] + b0, acc[t][3] + b1);
    }
}

// ---------------- fused readout ----------------
__global__ __launch_bounds__(256) void gemm_r(
    const float* __restrict__ X,
    const __half* __restrict__ Whi, const __half* __restrict__ Wlo,
    const float* __restrict__ br1, const float* __restrict__ Wr2,
    const float* __restrict__ br2,
    const int* __restrict__ gid, float* __restrict__ out, int M)
{
    extern __shared__ uint32_t sm[];
    __shared__ float res[64];
    int tid = threadIdx.x, wid = tid >> 5, lane = tid & 31;
    int mw = wid & 3, nw = wid >> 2;
    int g = lane >> 2, tg = lane & 3;
    int r0 = blockIdx.x * 64;
    if (tid < 64) res[tid] = 0.0f;

    float acc[4][4];
    #pragma unroll
    for (int t = 0; t < 4; t++)
        #pragma unroll
        for (int i = 0; i < 4; i++) acc[t][i] = 0.0f;

    for (int ch = 0; ch < 4; ch++) {
        load_A_f(sm, X, 512, ch * 128, r0, M, tid);
        load_B_r(sm, Whi, Wlo, ch, tid);
        __syncthreads();
        mma_core2<4>(sm, mw, nw * 32, g, tg, acc, OFF_BHI_R, OFF_BLO_R);
        __syncthreads();
    }

    float p0 = 0.0f, p1 = 0.0f;
    #pragma unroll
    for (int t = 0; t < 4; t++) {
        int col = nw * 32 + t * 8 + tg * 2;
        float b0 = __ldg(br1 + col), b1 = __ldg(br1 + col + 1);
        float w0 = __ldg(Wr2 + col), w1 = __ldg(Wr2 + col + 1);
        p0 += sp_one(acc[t][0] + b0) * w0 + sp_one(acc[t][1] + b1) * w1;
        p1 += sp_one(acc[t][2] + b0) * w0 + sp_one(acc[t][3] + b1) * w1;
    }
    p0 += __shfl_down_sync(0xffffffff, p0, 1);
    p0 += __shfl_down_sync(0xffffffff, p0, 2);
    p1 += __shfl_down_sync(0xffffffff, p1, 1);
    p1 += __shfl_down_sync(0xffffffff, p1, 2);
    if (tg == 0) {
        atomicAdd(&res[mw * 16 + g], p0);
        atomicAdd(&res[mw * 16 + g + 8], p1);
    }
    __syncthreads();
    if (tid < 64) {
        int row = r0 + tid;
        if (row < M) atomicAdd(out + __ldg(gid + row), res[tid] + __ldg(br2));
    }
}

// ---------------- launch ----------------
extern "C" void kernel_launch(void* const* d_in, const int* in_sizes, int n_in,
                              void* d_out, int out_size) {
    const int*   atom_type = (const int*)d_in[0];
    const int*   src  = (const int*)d_in[1];
    const int*   dst  = (const int*)d_in[2];
    const int*   gid  = (const int*)d_in[3];
    const float* dist = (const float*)d_in[4];
    const float* emb  = (const float*)d_in[5];
    const float* W_n1 = (const float*)d_in[6];  const float* b_n1 = (const float*)d_in[7];
    const float* W_c1 = (const float*)d_in[8];  const float* b_c1 = (const float*)d_in[9];
    const float* W_c2 = (const float*)d_in[10]; const float* b_c2 = (const float*)d_in[11];
    const float* W_c3 = (const float*)d_in[12]; const float* b_c3 = (const float*)d_in[13];
    const float* W_n2 = (const float*)d_in[14]; const float* b_n2 = (const float*)d_in[15];
    const float* W_n3 = (const float*)d_in[16]; const float* b_n3 = (const float*)d_in[17];
    const float* W_r1 = (const float*)d_in[18]; const float* b_r1 = (const float*)d_in[19];
    const float* W_r2 = (const float*)d_in[20]; const float* b_r2 = (const float*)d_in[21];
    float* out = (float*)d_out;

    float* H;
    __half *Hn2, *Node2, *TabP;
    __half *WbHi, *WbLo, *WrHi, *WrLo;
    cudaGetSymbolAddress((void**)&H,     g_H);
    cudaGetSymbolAddress((void**)&Hn2,   g_Hn2);
    cudaGetSymbolAddress((void**)&Node2, g_Node2);
    cudaGetSymbolAddress((void**)&TabP,  g_TabP);
    cudaGetSymbolAddress((void**)&WbHi,  g_WbHi);
    cudaGetSymbolAddress((void**)&WbLo,  g_WbLo);
    cudaGetSymbolAddress((void**)&WrHi,  g_WrHi);
    cudaGetSymbolAddress((void**)&WrLo,  g_WrLo);

    cudaFuncSetAttribute(gemm_m1,  cudaFuncAttributeMaxDynamicSharedMemorySize, TSMEM_M);
    cudaFuncSetAttribute(gemm_m23, cudaFuncAttributeMaxDynamicSharedMemorySize, TSMEM_M);
    cudaFuncSetAttribute(gemm_tab, cudaFuncAttributeMaxDynamicSharedMemorySize, TSMEM_M);
    cudaFuncSetAttribute(gemm_r,   cudaFuncAttributeMaxDynamicSharedMemorySize, TSMEM_R);

    const int M = N_NODES;
    const int GB64 = (M + 63) / 64;     // 938
    const int EB = (N_EDGES + 255) / 256;

    fold_kernel<<<dim3(DIM, N_LAYERS), DIM>>>(W_c2, b_c2, W_c3, b_c3);
    spu_kernel<<<dim3(GRID_G / 8, N_LAYERS), 128>>>(W_c1, b_c1);
    gemm_tab<<<dim3(GRID_G / 64, N_LAYERS), 256, TSMEM_M>>>();
    prep_w<<<dim3(9, 16), 128>>>(W_n1, W_n2, W_n3, WbHi, WbLo);
    prep_r<<<32, 128>>>(W_r1, WrHi, WrLo);
    embed_kernel<<<(N_NODES * 32 + 255) / 256, 256>>>(atom_type, emb);

    zero_cnt<<<NB_SCAN, 256>>>();
    hist_kernel<<<EB, 256>>>(dst);
    scan1<<<NB_SCAN, 256>>>();
    scan2<<<1, 256>>>();
    scan3<<<NB_SCAN, 256>>>();
    scatter_kernel<<<EB, 256>>>(src, dst, dist);

    gemm_m1<<<GB64, 256, TSMEM_M>>>(H, 512, WbHi, WbLo, b_n1, 1.0f, Hn2, M);

    for (int l = 0; l < N_LAYERS; l++) {
        edge_gather<<<(N_NODES + 7) / 8, 256>>>(
            TabP + (long long)l * GRID_G * DIM, Hn2, Node2);
        int nl = l + 1;
        int has_next = (nl < N_LAYERS);
        gemm_m23<<<GB64, 256, TSMEM_M>>>(
            Node2,
            WbHi + (long long)(3 + l) * DIM * DIM, WbLo + (long long)(3 + l) * DIM * DIM,
            b_n2 + l * 128,
            WbHi + (long long)(6 + l) * DIM * DIM, WbLo + (long long)(6 + l) * DIM * DIM,
            b_n3 + l * 128,
            H + l * 128, 512, H + nl * 128, 512,
            WbHi + (long long)(has_next ? nl : 0) * DIM * DIM,
            WbLo + (long long)(has_next ? nl : 0) * DIM * DIM,
            b_n1 + (has_next ? nl : 0) * 128,
            Hn2, has_next, M);
    }

    zero_out_kernel<<<1, N_GRAPH>>>(out);
    gemm_r<<<GB64, 256, TSMEM_R>>>(H, WrHi, WrLo, b_r1, W_r2, b_r2, gid, out, M);
}